// round 7
// baseline (speedup 1.0000x reference)
#include <cuda_runtime.h>
#include <cuda_bf16.h>
#include <math.h>
#include <stdint.h>

// Problem constants
#define BB   8
#define LQ   512
#define LKV  1024
#define DD   1024
#define HH_  16
#define HD   64
#define LN_EPS 1e-5f

// ---------------------------------------------------------------------------
// Scratch (device globals: allocation-free per harness rules)
// ---------------------------------------------------------------------------
__device__ float g_V  [BB * LKV * DD];               // fp32 v proj
__device__ float g_S  [(size_t)BB * HH_ * LQ * LKV]; // fp32 scores
__device__ float g_AO [BB * LQ  * DD];               // fp32 attn_out
__device__ float2 g_stats[(size_t)BB * HH_ * LQ];    // per-row {max, 1/sum}

// bf16 hi/lo buffers
__device__ __align__(16) __nv_bfloat16 g_qh [BB * LQ  * DD], g_ql [BB * LQ  * DD];
__device__ __align__(16) __nv_bfloat16 g_kh [BB * LKV * DD], g_kl [BB * LKV * DD];
__device__ __align__(16) __nv_bfloat16 g_vh [BB * LKV * DD], g_vl [BB * LKV * DD];
__device__ __align__(16) __nv_bfloat16 g_wh [3 * DD * DD],   g_wl [3 * DD * DD];
__device__ __align__(16) __nv_bfloat16 g_woh[DD * DD],       g_wol[DD * DD];
__device__ __align__(16) __nv_bfloat16 g_qh2[BB * LQ  * DD], g_ql2[BB * LQ  * DD];
__device__ __align__(16) __nv_bfloat16 g_kh2[BB * LKV * DD], g_kl2[BB * LKV * DD];
__device__ __align__(16) __nv_bfloat16 g_ch [BB * LQ  * DD], g_cl [BB * LQ  * DD];

// ---------------------------------------------------------------------------
// Baseline-PTX tensor-core helpers (NO tcgen05 — compute_103 target!)
// ---------------------------------------------------------------------------
__device__ __forceinline__ uint32_t smem_u32(const void* p) {
    uint32_t a;
    asm("{ .reg .u64 t; cvta.to.shared.u64 t, %1; cvt.u32.u64 %0, t; }" : "=r"(a) : "l"(p));
    return a;
}
__device__ __forceinline__ void ldsm4(uint32_t& r0, uint32_t& r1, uint32_t& r2,
                                      uint32_t& r3, uint32_t a) {
    asm volatile("ldmatrix.sync.aligned.m8n8.x4.shared.b16 {%0,%1,%2,%3}, [%4];"
                 : "=r"(r0), "=r"(r1), "=r"(r2), "=r"(r3) : "r"(a));
}
__device__ __forceinline__ void mma_bf16(float* d, const uint32_t* a, const uint32_t* b) {
    asm volatile("mma.sync.aligned.m16n8k16.row.col.f32.bf16.bf16.f32 "
                 "{%0,%1,%2,%3},{%4,%5,%6,%7},{%8,%9},{%0,%1,%2,%3};"
                 : "+f"(d[0]), "+f"(d[1]), "+f"(d[2]), "+f"(d[3])
                 : "r"(a[0]), "r"(a[1]), "r"(a[2]), "r"(a[3]), "r"(b[0]), "r"(b[1]));
}
#define CP_ASYNC16(s, g) \
    asm volatile("cp.async.cg.shared.global [%0], [%1], 16;" :: "r"(s), "l"(g))
#define CP_COMMIT() asm volatile("cp.async.commit_group;" ::: "memory")
#define CP_WAIT1()  asm volatile("cp.async.wait_group 1;"  ::: "memory")

// 128B-row XOR swizzle: 16B chunk c (0..7), row r
__device__ __forceinline__ uint32_t sw128(int r, int c) {
    return (uint32_t)(r * 128 + ((c ^ (r & 7)) << 4));
}
__device__ __forceinline__ void bsplit(float v, __nv_bfloat16& h, __nv_bfloat16& l) {
    h = __float2bfloat16(v);
    l = __float2bfloat16(v - __bfloat162float(h));
}

// ---------------------------------------------------------------------------
// fp32 -> bf16 hi/lo split
// ---------------------------------------------------------------------------
__global__ void split_bf16(const float4* __restrict__ x,
                           __nv_bfloat162* __restrict__ hi,
                           __nv_bfloat162* __restrict__ lo, int n4)
{
    int i = blockIdx.x * blockDim.x + threadIdx.x;
    if (i >= n4) return;
    float4 v = x[i];
    __nv_bfloat16 h0, h1, h2, h3, l0, l1, l2, l3;
    bsplit(v.x, h0, l0); bsplit(v.y, h1, l1);
    bsplit(v.z, h2, l2); bsplit(v.w, h3, l3);
    hi[i * 2 + 0] = __halves2bfloat162(h0, h1);
    hi[i * 2 + 1] = __halves2bfloat162(h2, h3);
    lo[i * 2 + 0] = __halves2bfloat162(l0, l1);
    lo[i * 2 + 1] = __halves2bfloat162(l2, l3);
}

// ---------------------------------------------------------------------------
// Transpose + split V
// ---------------------------------------------------------------------------
__global__ void transpose_split_v(const float* __restrict__ V,
                                  __nv_bfloat16* __restrict__ hi,
                                  __nv_bfloat16* __restrict__ lo)
{
    __shared__ float t[32][33];
    const int z = blockIdx.z, b = z >> 4, h = z & 15;
    const int k0 = blockIdx.x * 32, nn0 = blockIdx.y * 32;
    const int tx = threadIdx.x & 31, ty = threadIdx.x >> 5;
#pragma unroll
    for (int i = 0; i < 4; ++i) {
        int k = k0 + ty + i * 8;
        t[ty + i * 8][tx] = V[(((size_t)(b * 1024 + k)) << 10) + h * 64 + nn0 + tx];
    }
    __syncthreads();
#pragma unroll
    for (int i = 0; i < 4; ++i) {
        int n = nn0 + ty + i * 8;
        float v = t[tx][ty + i * 8];
        __nv_bfloat16 hh, ll;
        bsplit(v, hh, ll);
        size_t o = (((size_t)(z * 64 + n)) << 10) + k0 + tx;
        hi[o] = hh;
        lo[o] = ll;
    }
}

// ---------------------------------------------------------------------------
// HMMA bf16x3 GEMM, BK=64, block 128x128 with 4 warps (warp tile 64x64),
// 3-stage cp.async, single sync per iter. Doubled FLOP/smem-byte vs 8-warp
// version (32.8 vs 21.8) -> smem crossbar no longer binds the tensor pipe.
// ---------------------------------------------------------------------------
template<int KCH, bool SPLIT_OUT>
__global__ void __launch_bounds__(128, 2) gemm64(
    const __nv_bfloat16* __restrict__ Ahi, const __nv_bfloat16* __restrict__ Alo,
    const __nv_bfloat16* __restrict__ Bhi, const __nv_bfloat16* __restrict__ Blo,
    const float* __restrict__ bias, float* __restrict__ Cf,
    __nv_bfloat16* __restrict__ Chi, __nv_bfloat16* __restrict__ Clo, float scale,
    long sA0, long sA1, long sB0, long sB1, long sC0, long sC1)
{
    extern __shared__ __align__(16) char dynsm[];
    const uint32_t smBase = smem_u32(dynsm);

    const int tid  = threadIdx.x;
    const int lane = tid & 31;
    const int wid  = tid >> 5;
    const int wr   = wid >> 1;   // 0..1 (64 rows)
    const int wc   = wid & 1;    // 0..1 (64 cols)
    const int z    = blockIdx.z;
    const int m0   = blockIdx.y * 128;
    const int n0   = blockIdx.x * 128;
    const size_t aOff = (size_t)(z >> 4) * sA0 + (size_t)(z & 15) * sA1;
    const size_t bOff = (size_t)(z >> 4) * sB0 + (size_t)(z & 15) * sB1;
    const size_t cOff = (size_t)(z >> 4) * sC0 + (size_t)(z & 15) * sC1;

    const int rA  = lane & 15;
    const int cAh = lane >> 4;
    const int rBl = (lane & 7) + ((lane & 16) >> 1);
    const int cBh = (lane >> 3) & 1;

    float acc[4][8][4];
#pragma unroll
    for (int mt = 0; mt < 4; ++mt)
#pragma unroll
        for (int nt = 0; nt < 8; ++nt)
#pragma unroll
            for (int j = 0; j < 4; ++j) acc[mt][nt][j] = 0.f;

    auto prefetch = [&](int it, int stage) {
        const int part = it / KCH;
        const int ko   = (it % KCH) << 6;
        const __nv_bfloat16* Ap = (part == 2) ? Alo : Ahi;
        const __nv_bfloat16* Bp = (part == 1) ? Blo : Bhi;
        const uint32_t as = smBase + (uint32_t)stage * 32768u;
        const uint32_t bs = as + 16384u;
#pragma unroll
        for (int i = 0; i < 8; ++i) {
            int q = i * 128 + tid;
            int r = q >> 3, c = q & 7;
            CP_ASYNC16(as + sw128(r, c),
                       Ap + aOff + (((size_t)(m0 + r)) << 10) + ko + c * 8);
            CP_ASYNC16(bs + sw128(r, c),
                       Bp + bOff + (((size_t)(n0 + r)) << 10) + ko + c * 8);
        }
        CP_COMMIT();
    };

    const int NIT = 3 * KCH;
    prefetch(0, 0);
    prefetch(1, 1);

    for (int it = 0; it < NIT; ++it) {
        CP_WAIT1();
        __syncthreads();
        if (it + 2 < NIT) prefetch(it + 2, (it + 2) % 3);
        else CP_COMMIT();

        const uint32_t aT = smBase + (uint32_t)(it % 3) * 32768u;
        const uint32_t bT = aT + 16384u;

#pragma unroll
        for (int ks = 0; ks < 4; ++ks) {
            uint32_t af[4][4];
            uint32_t bf[8][2];
#pragma unroll
            for (int mt = 0; mt < 4; ++mt) {
                int r = wr * 64 + mt * 16 + rA;
                ldsm4(af[mt][0], af[mt][1], af[mt][2], af[mt][3],
                      aT + sw128(r, ks * 2 + cAh));
            }
#pragma unroll
            for (int tp = 0; tp < 4; ++tp) {
                int r = wc * 64 + tp * 16 + rBl;
                uint32_t x0, x1, x2, x3;
                ldsm4(x0, x1, x2, x3, bT + sw128(r, ks * 2 + cBh));
                bf[tp * 2][0] = x0;     bf[tp * 2][1] = x1;
                bf[tp * 2 + 1][0] = x2; bf[tp * 2 + 1][1] = x3;
            }
#pragma unroll
            for (int mt = 0; mt < 4; ++mt)
#pragma unroll
                for (int nt = 0; nt < 8; ++nt)
                    mma_bf16(acc[mt][nt], af[mt], bf[nt]);
        }
    }
    __syncthreads();

#pragma unroll
    for (int mt = 0; mt < 4; ++mt) {
        const int row = m0 + wr * 64 + mt * 16 + (lane >> 2);
#pragma unroll
        for (int nt = 0; nt < 8; ++nt) {
            const int col = n0 + wc * 64 + nt * 8 + (lane & 3) * 2;
            const float b0 = bias ? bias[col]     : 0.f;
            const float b1 = bias ? bias[col + 1] : 0.f;
            const float v0 = (acc[mt][nt][0] + b0) * scale;
            const float v1 = (acc[mt][nt][1] + b1) * scale;
            const float v2 = (acc[mt][nt][2] + b0) * scale;
            const float v3 = (acc[mt][nt][3] + b1) * scale;
            const size_t i0 = cOff + ((size_t)row << 10) + col;
            const size_t i1 = i0 + (8 << 10);
            if (SPLIT_OUT) {
                __nv_bfloat16 h0, h1, h2, h3, l0, l1, l2, l3;
                bsplit(v0, h0, l0); bsplit(v1, h1, l1);
                bsplit(v2, h2, l2); bsplit(v3, h3, l3);
                *(__nv_bfloat162*)(Chi + i0) = __halves2bfloat162(h0, h1);
                *(__nv_bfloat162*)(Clo + i0) = __halves2bfloat162(l0, l1);
                *(__nv_bfloat162*)(Chi + i1) = __halves2bfloat162(h2, h3);
                *(__nv_bfloat162*)(Clo + i1) = __halves2bfloat162(l2, l3);
            } else {
                Cf[i0] = v0; Cf[i0 + 1] = v1;
                Cf[i1] = v2; Cf[i1 + 1] = v3;
            }
        }
    }
}

// ---------------------------------------------------------------------------
// Softmax stats + head-mean. One block (512 thr = 16 warps) per (b,q);
// warp h owns head h's 1024-wide row: shfl-only reductions (no block syncs
// in the reduction path). Mean over heads via shared-memory atomics.
// ---------------------------------------------------------------------------
__global__ void __launch_bounds__(512) softmax_stats(const float* __restrict__ S,
                                                     float2* __restrict__ stats,
                                                     float* __restrict__ mean_out)
{
    __shared__ float mean[1024];
    const int bq = blockIdx.x;
    const int b = bq >> 9, q = bq & 511;
    const int tid = threadIdx.x;
    const int lane = tid & 31, w = tid >> 5;   // w = head

    mean[tid] = 0.f;
    mean[tid + 512] = 0.f;
    __syncthreads();

    const size_t rowe = ((size_t)(b * 16 + w) * 512 + q) << 10;
    float4 v[8];
#pragma unroll
    for (int i = 0; i < 8; ++i)
        v[i] = __ldg((const float4*)(S + rowe + (i * 32 + lane) * 4));

    float m = -1e30f;
#pragma unroll
    for (int i = 0; i < 8; ++i)
        m = fmaxf(m, fmaxf(fmaxf(v[i].x, v[i].y), fmaxf(v[i].z, v[i].w)));
#pragma unroll
    for (int o = 16; o; o >>= 1) m = fmaxf(m, __shfl_xor_sync(0xffffffffu, m, o));

    float s = 0.f;
#pragma unroll
    for (int i = 0; i < 8; ++i) {
        v[i].x = __expf(v[i].x - m); v[i].y = __expf(v[i].y - m);
        v[i].z = __expf(v[i].z - m); v[i].w = __expf(v[i].w - m);
        s += (v[i].x + v[i].y) + (v[i].z + v[i].w);
    }
#pragma unroll
    for (int o = 16; o; o >>= 1) s += __shfl_xor_sync(0xffffffffu, s, o);
    const float inv = 1.0f / s;

    if (lane == 0)
        stats[(size_t)(b * 16 + w) * 512 + q] = make_float2(m, inv);

#pragma unroll
    for (int i = 0; i < 8; ++i) {
        int base = (i * 32 + lane) * 4;
        atomicAdd(&mean[base + 0], v[i].x * inv);
        atomicAdd(&mean[base + 1], v[i].y * inv);
        atomicAdd(&mean[base + 2], v[i].z * inv);
        atomicAdd(&mean[base + 3], v[i].w * inv);
    }
    __syncthreads();

    const float inv16 = 1.0f / HH_;
    float* mo = mean_out + (((size_t)bq) << 10);
    mo[tid]       = mean[tid] * inv16;
    mo[tid + 512] = mean[tid + 512] * inv16;
}

// ---------------------------------------------------------------------------
// Fused ctx: per z=(b,h), q-tile 128: reads fp32 S, exp*(inv) in-flight,
// P hi/lo in SMEM, 3-term MMA vs Vt hi/lo. 512 thr (16 warps, 32x16 tiles).
// ---------------------------------------------------------------------------
__global__ void __launch_bounds__(512) ctx_fused(
    const float* __restrict__ S, const float2* __restrict__ stats,
    const __nv_bfloat16* __restrict__ Vhi, const __nv_bfloat16* __restrict__ Vlo,
    __nv_bfloat16* __restrict__ Chi, __nv_bfloat16* __restrict__ Clo)
{
    extern __shared__ __align__(16) char dynsm[];
    const uint32_t smBase = smem_u32(dynsm);   // P: 2*32768; V: +65536, 3*16384

    const int tid  = threadIdx.x;
    const int lane = tid & 31;
    const int wid  = tid >> 5;
    const int wr   = wid >> 2;   // 0..3
    const int wc   = wid & 3;    // 0..3
    const int z    = blockIdx.z, b = z >> 4, h = z & 15;
    const int m0   = blockIdx.y * 128;
    const size_t sOff  = ((size_t)z * 512 + m0) << 10;
    const size_t vOff  = ((size_t)z * 64) << 10;
    const int    stOff = z * 512 + m0;

    const int rA  = lane & 15;
    const int cAh = lane >> 4;
    const int rBl = (lane & 7) + ((lane & 16) >> 1);
    const int cBh = (lane >> 3) & 1;

    float acc[2][2][4];
#pragma unroll
    for (int mt = 0; mt < 2; ++mt)
#pragma unroll
        for (int nt = 0; nt < 2; ++nt)
#pragma unroll
            for (int j = 0; j < 4; ++j) acc[mt][nt][j] = 0.f;

    float4 sreg[4];
    auto ldS = [&](int kc) {
#pragma unroll
        for (int i = 0; i < 4; ++i) {
            int idx = i * 512 + tid;
            int row = idx >> 4, f4 = idx & 15;
            sreg[i] = __ldg((const float4*)(S + sOff + ((size_t)row << 10) +
                                            (kc << 6) + f4 * 4));
        }
    };
    auto cpV = [&](int kc) {
        const uint32_t vs = smBase + 65536u + (uint32_t)(kc % 3) * 16384u;
        int r = tid >> 3, c = tid & 7;
        CP_ASYNC16(vs + sw128(r, c), Vhi + vOff + ((size_t)r << 10) + (kc << 6) + c * 8);
        CP_ASYNC16(vs + 8192u + sw128(r, c),
                   Vlo + vOff + ((size_t)r << 10) + (kc << 6) + c * 8);
        CP_COMMIT();
    };

    ldS(0);
    cpV(0);
    cpV(1);

    for (int kc = 0; kc < 16; ++kc) {
        const uint32_t pB = smBase + (uint32_t)(kc & 1) * 32768u;
#pragma unroll
        for (int i = 0; i < 4; ++i) {
            int idx = i * 512 + tid;
            int row = idx >> 4, f4 = idx & 15;
            float2 st = __ldg((const float2*)&stats[stOff + row]);
            float p0 = __expf(sreg[i].x - st.x) * st.y;
            float p1 = __expf(sreg[i].y - st.x) * st.y;
            float p2 = __expf(sreg[i].z - st.x) * st.y;
            float p3 = __expf(sreg[i].w - st.x) * st.y;
            __nv_bfloat16 h0, h1, h2, h3, l0, l1, l2, l3;
            bsplit(p0, h0, l0); bsplit(p1, h1, l1);
            bsplit(p2, h2, l2); bsplit(p3, h3, l3);
            uint32_t off = sw128(row, f4 >> 1) + (f4 & 1) * 8;
            __nv_bfloat162 ph0 = __halves2bfloat162(h0, h1);
            __nv_bfloat162 ph1 = __halves2bfloat162(h2, h3);
            __nv_bfloat162 pl0 = __halves2bfloat162(l0, l1);
            __nv_bfloat162 pl1 = __halves2bfloat162(l2, l3);
            asm volatile("st.shared.v2.b32 [%0], {%1, %2};" ::
                         "r"(pB + off), "r"(*(uint32_t*)&ph0), "r"(*(uint32_t*)&ph1)
                         : "memory");
            asm volatile("st.shared.v2.b32 [%0], {%1, %2};" ::
                         "r"(pB + 16384u + off), "r"(*(uint32_t*)&pl0), "r"(*(uint32_t*)&pl1)
                         : "memory");
        }
        if (kc + 1 < 16) ldS(kc + 1);

        CP_WAIT1();
        __syncthreads();
        if (kc + 2 < 16) cpV(kc + 2);
        else CP_COMMIT();

        const uint32_t phT = smBase + (uint32_t)(kc & 1) * 32768u;
        const uint32_t plT = phT + 16384u;
        const uint32_t vhT = smBase + 65536u + (uint32_t)(kc % 3) * 16384u;
        const uint32_t vlT = vhT + 8192u;

#pragma unroll
        for (int ks = 0; ks < 4; ++ks) {
            uint32_t ah[2][4], al[2][4];
            uint32_t bh[2][2], bl[2][2];
#pragma unroll
            for (int mt = 0; mt < 2; ++mt) {
                int r = wr * 32 + mt * 16 + rA;
                ldsm4(ah[mt][0], ah[mt][1], ah[mt][2], ah[mt][3],
                      phT + sw128(r, ks * 2 + cAh));
                ldsm4(al[mt][0], al[mt][1], al[mt][2], al[mt][3],
                      plT + sw128(r, ks * 2 + cAh));
            }
            {
                int r = wc * 16 + rBl;
                uint32_t x0, x1, x2, x3;
                ldsm4(x0, x1, x2, x3, vhT + sw128(r, ks * 2 + cBh));
                bh[0][0] = x0; bh[0][1] = x1; bh[1][0] = x2; bh[1][1] = x3;
                ldsm4(x0, x1, x2, x3, vlT + sw128(r, ks * 2 + cBh));
                bl[0][0] = x0; bl[0][1] = x1; bl[1][0] = x2; bl[1][1] = x3;
            }
#pragma unroll
            for (int mt = 0; mt < 2; ++mt)
#pragma unroll
                for (int nt = 0; nt < 2; ++nt) {
                    mma_bf16(acc[mt][nt], ah[mt], bh[nt]);
                    mma_bf16(acc[mt][nt], ah[mt], bl[nt]);
                    mma_bf16(acc[mt][nt], al[mt], bh[nt]);
                }
        }
    }

#pragma unroll
    for (int mt = 0; mt < 2; ++mt) {
        const int row = m0 + wr * 32 + mt * 16 + (lane >> 2);
#pragma unroll
        for (int nt = 0; nt < 2; ++nt) {
            const int col = h * 64 + wc * 16 + nt * 8 + (lane & 3) * 2;
            const size_t i0 = (((size_t)(b * 512 + row)) << 10) + col;
            const size_t i1 = i0 + (8 << 10);
            __nv_bfloat16 h0, h1, h2, h3, l0, l1, l2, l3;
            bsplit(acc[mt][nt][0], h0, l0); bsplit(acc[mt][nt][1], h1, l1);
            bsplit(acc[mt][nt][2], h2, l2); bsplit(acc[mt][nt][3], h3, l3);
            *(__nv_bfloat162*)(Chi + i0) = __halves2bfloat162(h0, h1);
            *(__nv_bfloat162*)(Clo + i0) = __halves2bfloat162(l0, l1);
            *(__nv_bfloat162*)(Chi + i1) = __halves2bfloat162(h2, h3);
            *(__nv_bfloat162*)(Clo + i1) = __halves2bfloat162(l2, l3);
        }
    }
}

// ---------------------------------------------------------------------------
// out = LayerNorm(query + attn_out) * gamma + beta.  One block per row.
// ---------------------------------------------------------------------------
__global__ void residual_ln(const float* __restrict__ q, const float* __restrict__ ao,
                            const float* __restrict__ gamma, const float* __restrict__ beta,
                            float* __restrict__ out)
{
    __shared__ float red[8];
    __shared__ float bcast;
    const long row = blockIdx.x;
    const int tid = threadIdx.x;

    float4 qa = *(const float4*)&q [row * DD + tid * 4];
    float4 aa = *(const float4*)&ao[row * DD + tid * 4];
    float x0 = qa.x + aa.x, x1 = qa.y + aa.y, x2 = qa.z + aa.z, x3 = qa.w + aa.w;

    float s = (x0 + x1) + (x2 + x3);
#pragma unroll
    for (int o = 16; o; o >>= 1) s += __shfl_xor_sync(0xffffffffu, s, o);
    if ((tid & 31) == 0) red[tid >> 5] = s;
    __syncthreads();
    if (tid < 8) {
        s = red[tid];
#pragma unroll
        for (int o = 4; o; o >>= 1) s += __shfl_xor_sync(0xffu, s, o);
        if (tid == 0) bcast = s;
    }
    __syncthreads();
    const float mu = bcast * (1.0f / DD);

    float d0 = x0 - mu, d1 = x1 - mu, d2 = x2 - mu, d3 = x3 - mu;
    float sq = (d0 * d0 + d1 * d1) + (d2 * d2 + d3 * d3);
#pragma unroll
    for (int o = 16; o; o >>= 1) sq += __shfl_xor_sync(0xffffffffu, sq, o);
    __syncthreads();
    if ((tid & 31) == 0) red[tid >> 5] = sq;
    __syncthreads();
    if (tid < 8) {
        sq = red[tid];
#pragma unroll
        for (int o = 4; o; o >>= 1) sq += __shfl_xor_sync(0xffu, sq, o);
        if (tid == 0) bcast = sq;
    }
    __syncthreads();
    const float rstd = rsqrtf(bcast * (1.0f / DD) + LN_EPS);

    float4 g = *(const float4*)&gamma[tid * 4];
    float4 be = *(const float4*)&beta[tid * 4];
    float4 o4;
    o4.x = d0 * rstd * g.x + be.x;
    o4.y = d1 * rstd * g.y + be.y;
    o4.z = d2 * rstd * g.z + be.z;
    o4.w = d3 * rstd * g.w + be.w;
    *(float4*)&out[row * DD + tid * 4] = o4;
}

// ---------------------------------------------------------------------------
extern "C" void kernel_launch(void* const* d_in, const int* in_sizes, int n_in,
                              void* d_out, int out_size)
{
    const float* query = (const float*)d_in[0];
    const float* key_  = (const float*)d_in[1];
    const float* value = (const float*)d_in[2];
    const float* in_w  = (const float*)d_in[3];
    const float* in_b  = (const float*)d_in[4];
    const float* out_w = (const float*)d_in[5];
    const float* out_b = (const float*)d_in[6];
    const float* gamma = (const float*)d_in[7];
    const float* beta  = (const float*)d_in[8];
    float* out = (float*)d_out;

    float *V, *S, *AO;
    float2* ST;
    cudaGetSymbolAddress((void**)&V,  g_V);
    cudaGetSymbolAddress((void**)&S,  g_S);
    cudaGetSymbolAddress((void**)&AO, g_AO);
    cudaGetSymbolAddress((void**)&ST, g_stats);

    __nv_bfloat16 *qh, *ql, *kh, *kl, *vh, *vl, *wh, *wl, *woh, *wol;
    __nv_bfloat16 *qh2, *ql2, *kh2, *kl2, *ch, *cl;
    cudaGetSymbolAddress((void**)&qh,  g_qh);  cudaGetSymbolAddress((void**)&ql,  g_ql);
    cudaGetSymbolAddress((void**)&kh,  g_kh);  cudaGetSymbolAddress((void**)&kl,  g_kl);
    cudaGetSymbolAddress((void**)&vh,  g_vh);  cudaGetSymbolAddress((void**)&vl,  g_vl);
    cudaGetSymbolAddress((void**)&wh,  g_wh);  cudaGetSymbolAddress((void**)&wl,  g_wl);
    cudaGetSymbolAddress((void**)&woh, g_woh); cudaGetSymbolAddress((void**)&wol, g_wol);
    cudaGetSymbolAddress((void**)&qh2, g_qh2); cudaGetSymbolAddress((void**)&ql2, g_ql2);
    cudaGetSymbolAddress((void**)&kh2, g_kh2); cudaGetSymbolAddress((void**)&kl2, g_kl2);
    cudaGetSymbolAddress((void**)&ch,  g_ch);  cudaGetSymbolAddress((void**)&cl,  g_cl);

    const int SM_G = 3 * 32768;
    const int SM_X = 2 * 32768 + 3 * 16384;
    cudaFuncSetAttribute(gemm64<16, true>,  cudaFuncAttributeMaxDynamicSharedMemorySize, SM_G);
    cudaFuncSetAttribute(gemm64<16, false>, cudaFuncAttributeMaxDynamicSharedMemorySize, SM_G);
    cudaFuncSetAttribute(gemm64<1,  false>, cudaFuncAttributeMaxDynamicSharedMemorySize, SM_G);
    cudaFuncSetAttribute(ctx_fused, cudaFuncAttributeMaxDynamicSharedMemorySize, SM_X);

    const float qscale = 0.125f;

    auto launch_split = [](const float* x, __nv_bfloat16* h, __nv_bfloat16* l, long n) {
        int n4 = (int)(n / 4);
        split_bf16<<<(n4 + 255) / 256, 256>>>((const float4*)x, (__nv_bfloat162*)h,
                                              (__nv_bfloat162*)l, n4);
    };

    // 1) split inputs + weights
    launch_split(query, qh, ql, (long)BB * LQ  * DD);
    launch_split(key_,  kh, kl, (long)BB * LKV * DD);
    launch_split(value, vh, vl, (long)BB * LKV * DD);
    launch_split(in_w,  wh, wl, 3L * DD * DD);
    launch_split(out_w, woh, wol, (long)DD * DD);

    // 2) Q/K projections -> bf16 hi/lo directly; V projection -> fp32
    gemm64<16, true><<<dim3(8, 32, 1), 128, SM_G>>>(
        qh, ql, wh, wl, in_b, nullptr, qh2, ql2, qscale, 0,0, 0,0, 0,0);
    gemm64<16, true><<<dim3(8, 64, 1), 128, SM_G>>>(
        kh, kl, wh + (long)DD*DD, wl + (long)DD*DD, in_b + DD,
        nullptr, kh2, kl2, 1.0f, 0,0, 0,0, 0,0);
    gemm64<16, false><<<dim3(8, 64, 1), 128, SM_G>>>(
        vh, vl, wh + 2L*DD*DD, wl + 2L*DD*DD, in_b + 2*DD,
        V, nullptr, nullptr, 1.0f, 0,0, 0,0, 0,0);

    // 3) transpose + split V into head-major Vt
    transpose_split_v<<<dim3(LKV / 32, HD / 32, BB * HH_), 256>>>(V, vh, vl);

    // 4) scores -> fp32 S
    gemm64<1, false><<<dim3(8, 4, BB * HH_), 128, SM_G>>>(
        qh2, ql2, kh2, kl2, nullptr, S, nullptr, nullptr, 1.0f,
        (long)LQ * DD,  (long)HD,
        (long)LKV * DD, (long)HD,
        (long)HH_ * LQ * LKV, (long)LQ * LKV);

    // 5) softmax stats + head-mean
    softmax_stats<<<BB * LQ, 512>>>(S, ST, out + (long)BB * LQ * DD);

    // 6) fused exp/normalize/split + ctx MMA
    ctx_fused<<<dim3(1, 4, BB * HH_), 512, SM_X>>>(S, ST, vh, vl, ch, cl);

    // 7) out projection -> fp32 AO
    gemm64<16, false><<<dim3(8, 32, 1), 128, SM_G>>>(
        ch, cl, woh, wol, out_b, AO, nullptr, nullptr, 1.0f, 0,0, 0,0, 0,0);

    // 8) residual + LayerNorm
    residual_ln<<<BB * LQ, 256>>>(query, AO, gamma, beta, out);
}

// round 8
// speedup vs baseline: 1.2523x; 1.2523x over previous
#include <cuda_runtime.h>
#include <cuda_bf16.h>
#include <math.h>
#include <stdint.h>

// Problem constants
#define BB   8
#define LQ   512
#define LKV  1024
#define DD   1024
#define HH_  16
#define HD   64
#define LN_EPS 1e-5f

// ---------------------------------------------------------------------------
// Scratch (device globals: allocation-free per harness rules)
// ---------------------------------------------------------------------------
__device__ float g_V  [BB * LKV * DD];               // fp32 v proj
__device__ float g_S  [(size_t)BB * HH_ * LQ * LKV]; // fp32 scores
__device__ float g_AO [BB * LQ  * DD];               // fp32 attn_out
__device__ float2 g_stats[(size_t)BB * HH_ * LQ];    // per-row {max, 1/sum}

// bf16 hi/lo buffers
__device__ __align__(16) __nv_bfloat16 g_qh [BB * LQ  * DD], g_ql [BB * LQ  * DD];
__device__ __align__(16) __nv_bfloat16 g_kh [BB * LKV * DD], g_kl [BB * LKV * DD];
__device__ __align__(16) __nv_bfloat16 g_vh [BB * LKV * DD];   // value hi -> later Vt hi
__device__ __align__(16) __nv_bfloat16 g_wh [3 * DD * DD],   g_wl [3 * DD * DD];
__device__ __align__(16) __nv_bfloat16 g_woh[DD * DD];
__device__ __align__(16) __nv_bfloat16 g_qh2[BB * LQ  * DD], g_ql2[BB * LQ  * DD];
__device__ __align__(16) __nv_bfloat16 g_kh2[BB * LKV * DD], g_kl2[BB * LKV * DD];
__device__ __align__(16) __nv_bfloat16 g_ch [BB * LQ  * DD];

// ---------------------------------------------------------------------------
// Baseline-PTX tensor-core helpers (NO tcgen05 — compute_103 target!)
// ---------------------------------------------------------------------------
__device__ __forceinline__ uint32_t smem_u32(const void* p) {
    uint32_t a;
    asm("{ .reg .u64 t; cvta.to.shared.u64 t, %1; cvt.u32.u64 %0, t; }" : "=r"(a) : "l"(p));
    return a;
}
__device__ __forceinline__ void ldsm4(uint32_t& r0, uint32_t& r1, uint32_t& r2,
                                      uint32_t& r3, uint32_t a) {
    asm volatile("ldmatrix.sync.aligned.m8n8.x4.shared.b16 {%0,%1,%2,%3}, [%4];"
                 : "=r"(r0), "=r"(r1), "=r"(r2), "=r"(r3) : "r"(a));
}
__device__ __forceinline__ void mma_bf16(float* d, const uint32_t* a, const uint32_t* b) {
    asm volatile("mma.sync.aligned.m16n8k16.row.col.f32.bf16.bf16.f32 "
                 "{%0,%1,%2,%3},{%4,%5,%6,%7},{%8,%9},{%0,%1,%2,%3};"
                 : "+f"(d[0]), "+f"(d[1]), "+f"(d[2]), "+f"(d[3])
                 : "r"(a[0]), "r"(a[1]), "r"(a[2]), "r"(a[3]), "r"(b[0]), "r"(b[1]));
}
#define CP_ASYNC16(s, g) \
    asm volatile("cp.async.cg.shared.global [%0], [%1], 16;" :: "r"(s), "l"(g))
#define CP_COMMIT() asm volatile("cp.async.commit_group;" ::: "memory")
#define CP_WAIT1()  asm volatile("cp.async.wait_group 1;"  ::: "memory")

// 128B-row XOR swizzle: 16B chunk c (0..7), row r
__device__ __forceinline__ uint32_t sw128(int r, int c) {
    return (uint32_t)(r * 128 + ((c ^ (r & 7)) << 4));
}
__device__ __forceinline__ void bsplit(float v, __nv_bfloat16& h, __nv_bfloat16& l) {
    h = __float2bfloat16(v);
    l = __float2bfloat16(v - __bfloat162float(h));
}

// ---------------------------------------------------------------------------
// fp32 -> bf16 hi/lo split (and hi-only variant)
// ---------------------------------------------------------------------------
__global__ void split_bf16(const float4* __restrict__ x,
                           __nv_bfloat162* __restrict__ hi,
                           __nv_bfloat162* __restrict__ lo, int n4)
{
    int i = blockIdx.x * blockDim.x + threadIdx.x;
    if (i >= n4) return;
    float4 v = x[i];
    __nv_bfloat16 h0, h1, h2, h3, l0, l1, l2, l3;
    bsplit(v.x, h0, l0); bsplit(v.y, h1, l1);
    bsplit(v.z, h2, l2); bsplit(v.w, h3, l3);
    hi[i * 2 + 0] = __halves2bfloat162(h0, h1);
    hi[i * 2 + 1] = __halves2bfloat162(h2, h3);
    lo[i * 2 + 0] = __halves2bfloat162(l0, l1);
    lo[i * 2 + 1] = __halves2bfloat162(l2, l3);
}
__global__ void split1_bf16(const float4* __restrict__ x,
                            __nv_bfloat162* __restrict__ hi, int n4)
{
    int i = blockIdx.x * blockDim.x + threadIdx.x;
    if (i >= n4) return;
    float4 v = x[i];
    hi[i * 2 + 0] = __halves2bfloat162(__float2bfloat16(v.x), __float2bfloat16(v.y));
    hi[i * 2 + 1] = __halves2bfloat162(__float2bfloat16(v.z), __float2bfloat16(v.w));
}

// ---------------------------------------------------------------------------
// Transpose V (hi only): fp32 V[b*Lkv + k][h*64+n] -> Vt hi [(b*16+h)*64+n][k]
// ---------------------------------------------------------------------------
__global__ void transpose_v(const float* __restrict__ V,
                            __nv_bfloat16* __restrict__ hi)
{
    __shared__ float t[32][33];
    const int z = blockIdx.z, b = z >> 4, h = z & 15;
    const int k0 = blockIdx.x * 32, nn0 = blockIdx.y * 32;
    const int tx = threadIdx.x & 31, ty = threadIdx.x >> 5;
#pragma unroll
    for (int i = 0; i < 4; ++i) {
        int k = k0 + ty + i * 8;
        t[ty + i * 8][tx] = V[(((size_t)(b * 1024 + k)) << 10) + h * 64 + nn0 + tx];
    }
    __syncthreads();
#pragma unroll
    for (int i = 0; i < 4; ++i) {
        int n = nn0 + ty + i * 8;
        size_t o = (((size_t)(z * 64 + n)) << 10) + k0 + tx;
        hi[o] = __float2bfloat16(t[tx][ty + i * 8]);
    }
}

// ---------------------------------------------------------------------------
// HMMA GEMM, BK=64, block 128x128, 4 warps (warp tile 64x64), 3-stage
// cp.async, single sync per iter. PARTS=3: bf16x3 split (hi*hi,hi*lo,lo*hi);
// PARTS=1: plain bf16 (lo pointers unused).
// ---------------------------------------------------------------------------
template<int KCH, int PARTS, bool SPLIT_OUT>
__global__ void __launch_bounds__(128, 2) gemm64(
    const __nv_bfloat16* __restrict__ Ahi, const __nv_bfloat16* __restrict__ Alo,
    const __nv_bfloat16* __restrict__ Bhi, const __nv_bfloat16* __restrict__ Blo,
    const float* __restrict__ bias, float* __restrict__ Cf,
    __nv_bfloat16* __restrict__ Chi, __nv_bfloat16* __restrict__ Clo, float scale,
    long sA0, long sA1, long sB0, long sB1, long sC0, long sC1)
{
    extern __shared__ __align__(16) char dynsm[];
    const uint32_t smBase = smem_u32(dynsm);

    const int tid  = threadIdx.x;
    const int lane = tid & 31;
    const int wid  = tid >> 5;
    const int wr   = wid >> 1;   // 0..1 (64 rows)
    const int wc   = wid & 1;    // 0..1 (64 cols)
    const int z    = blockIdx.z;
    const int m0   = blockIdx.y * 128;
    const int n0   = blockIdx.x * 128;
    const size_t aOff = (size_t)(z >> 4) * sA0 + (size_t)(z & 15) * sA1;
    const size_t bOff = (size_t)(z >> 4) * sB0 + (size_t)(z & 15) * sB1;
    const size_t cOff = (size_t)(z >> 4) * sC0 + (size_t)(z & 15) * sC1;

    const int rA  = lane & 15;
    const int cAh = lane >> 4;
    const int rBl = (lane & 7) + ((lane & 16) >> 1);
    const int cBh = (lane >> 3) & 1;

    float acc[4][8][4];
#pragma unroll
    for (int mt = 0; mt < 4; ++mt)
#pragma unroll
        for (int nt = 0; nt < 8; ++nt)
#pragma unroll
            for (int j = 0; j < 4; ++j) acc[mt][nt][j] = 0.f;

    auto prefetch = [&](int it, int stage) {
        const int part = it / KCH;
        const int ko   = (it % KCH) << 6;
        const __nv_bfloat16* Ap = (PARTS == 3 && part == 2) ? Alo : Ahi;
        const __nv_bfloat16* Bp = (PARTS == 3 && part == 1) ? Blo : Bhi;
        const uint32_t as = smBase + (uint32_t)stage * 32768u;
        const uint32_t bs = as + 16384u;
#pragma unroll
        for (int i = 0; i < 8; ++i) {
            int q = i * 128 + tid;
            int r = q >> 3, c = q & 7;
            CP_ASYNC16(as + sw128(r, c),
                       Ap + aOff + (((size_t)(m0 + r)) << 10) + ko + c * 8);
            CP_ASYNC16(bs + sw128(r, c),
                       Bp + bOff + (((size_t)(n0 + r)) << 10) + ko + c * 8);
        }
        CP_COMMIT();
    };

    const int NIT = PARTS * KCH;
    prefetch(0, 0);
    if (NIT > 1) prefetch(1, 1);

    for (int it = 0; it < NIT; ++it) {
        CP_WAIT1();
        __syncthreads();
        if (it + 2 < NIT) prefetch(it + 2, (it + 2) % 3);
        else CP_COMMIT();

        const uint32_t aT = smBase + (uint32_t)(it % 3) * 32768u;
        const uint32_t bT = aT + 16384u;

#pragma unroll
        for (int ks = 0; ks < 4; ++ks) {
            uint32_t af[4][4];
            uint32_t bf[8][2];
#pragma unroll
            for (int mt = 0; mt < 4; ++mt) {
                int r = wr * 64 + mt * 16 + rA;
                ldsm4(af[mt][0], af[mt][1], af[mt][2], af[mt][3],
                      aT + sw128(r, ks * 2 + cAh));
            }
#pragma unroll
            for (int tp = 0; tp < 4; ++tp) {
                int r = wc * 64 + tp * 16 + rBl;
                uint32_t x0, x1, x2, x3;
                ldsm4(x0, x1, x2, x3, bT + sw128(r, ks * 2 + cBh));
                bf[tp * 2][0] = x0;     bf[tp * 2][1] = x1;
                bf[tp * 2 + 1][0] = x2; bf[tp * 2 + 1][1] = x3;
            }
#pragma unroll
            for (int mt = 0; mt < 4; ++mt)
#pragma unroll
                for (int nt = 0; nt < 8; ++nt)
                    mma_bf16(acc[mt][nt], af[mt], bf[nt]);
        }
    }
    __syncthreads();

#pragma unroll
    for (int mt = 0; mt < 4; ++mt) {
        const int row = m0 + wr * 64 + mt * 16 + (lane >> 2);
#pragma unroll
        for (int nt = 0; nt < 8; ++nt) {
            const int col = n0 + wc * 64 + nt * 8 + (lane & 3) * 2;
            const float b0 = bias ? bias[col]     : 0.f;
            const float b1 = bias ? bias[col + 1] : 0.f;
            const float v0 = (acc[mt][nt][0] + b0) * scale;
            const float v1 = (acc[mt][nt][1] + b1) * scale;
            const float v2 = (acc[mt][nt][2] + b0) * scale;
            const float v3 = (acc[mt][nt][3] + b1) * scale;
            const size_t i0 = cOff + ((size_t)row << 10) + col;
            const size_t i1 = i0 + (8 << 10);
            if (SPLIT_OUT) {
                __nv_bfloat16 h0, h1, h2, h3, l0, l1, l2, l3;
                bsplit(v0, h0, l0); bsplit(v1, h1, l1);
                bsplit(v2, h2, l2); bsplit(v3, h3, l3);
                *(__nv_bfloat162*)(Chi + i0) = __halves2bfloat162(h0, h1);
                *(__nv_bfloat162*)(Clo + i0) = __halves2bfloat162(l0, l1);
                *(__nv_bfloat162*)(Chi + i1) = __halves2bfloat162(h2, h3);
                *(__nv_bfloat162*)(Clo + i1) = __halves2bfloat162(l2, l3);
            } else {
                Cf[i0] = v0; Cf[i0 + 1] = v1;
                Cf[i1] = v2; Cf[i1 + 1] = v3;
            }
        }
    }
}

// ---------------------------------------------------------------------------
// Softmax stats + head-mean. One block (512 thr = 16 warps) per (b,q).
// ---------------------------------------------------------------------------
__global__ void __launch_bounds__(512) softmax_stats(const float* __restrict__ S,
                                                     float2* __restrict__ stats,
                                                     float* __restrict__ mean_out)
{
    __shared__ float mean[1024];
    const int bq = blockIdx.x;
    const int b = bq >> 9, q = bq & 511;
    const int tid = threadIdx.x;
    const int lane = tid & 31, w = tid >> 5;

    mean[tid] = 0.f;
    mean[tid + 512] = 0.f;
    __syncthreads();

    const size_t rowe = ((size_t)(b * 16 + w) * 512 + q) << 10;
    float4 v[8];
#pragma unroll
    for (int i = 0; i < 8; ++i)
        v[i] = __ldg((const float4*)(S + rowe + (i * 32 + lane) * 4));

    float m = -1e30f;
#pragma unroll
    for (int i = 0; i < 8; ++i)
        m = fmaxf(m, fmaxf(fmaxf(v[i].x, v[i].y), fmaxf(v[i].z, v[i].w)));
#pragma unroll
    for (int o = 16; o; o >>= 1) m = fmaxf(m, __shfl_xor_sync(0xffffffffu, m, o));

    float s = 0.f;
#pragma unroll
    for (int i = 0; i < 8; ++i) {
        v[i].x = __expf(v[i].x - m); v[i].y = __expf(v[i].y - m);
        v[i].z = __expf(v[i].z - m); v[i].w = __expf(v[i].w - m);
        s += (v[i].x + v[i].y) + (v[i].z + v[i].w);
    }
#pragma unroll
    for (int o = 16; o; o >>= 1) s += __shfl_xor_sync(0xffffffffu, s, o);
    const float inv = 1.0f / s;

    if (lane == 0)
        stats[(size_t)(b * 16 + w) * 512 + q] = make_float2(m, inv);

#pragma unroll
    for (int i = 0; i < 8; ++i) {
        int base = (i * 32 + lane) * 4;
        atomicAdd(&mean[base + 0], v[i].x * inv);
        atomicAdd(&mean[base + 1], v[i].y * inv);
        atomicAdd(&mean[base + 2], v[i].z * inv);
        atomicAdd(&mean[base + 3], v[i].w * inv);
    }
    __syncthreads();

    const float inv16 = 1.0f / HH_;
    float* mo = mean_out + (((size_t)bq) << 10);
    mo[tid]       = mean[tid] * inv16;
    mo[tid + 512] = mean[tid + 512] * inv16;
}

// ---------------------------------------------------------------------------
// Fused ctx (plain bf16): per z=(b,h), q-tile 128: reads fp32 S, exp*inv
// in-flight, P hi in SMEM, single-term MMA vs Vt hi. 512 thr (16 warps,
// 32x16 warp tiles). SMEM: P 2x16KB + V 3x8KB = 56KB.
// ---------------------------------------------------------------------------
__global__ void __launch_bounds__(512) ctx_fused(
    const float* __restrict__ S, const float2* __restrict__ stats,
    const __nv_bfloat16* __restrict__ Vhi,
    __nv_bfloat16* __restrict__ Chi)
{
    extern __shared__ __align__(16) char dynsm[];
    const uint32_t smBase = smem_u32(dynsm);   // P: 2*16384; V: +32768, 3*8192

    const int tid  = threadIdx.x;
    const int lane = tid & 31;
    const int wid  = tid >> 5;
    const int wr   = wid >> 2;
    const int wc   = wid & 3;
    const int z    = blockIdx.z, b = z >> 4, h = z & 15;
    const int m0   = blockIdx.y * 128;
    const size_t sOff  = ((size_t)z * 512 + m0) << 10;
    const size_t vOff  = ((size_t)z * 64) << 10;
    const int    stOff = z * 512 + m0;

    const int rA  = lane & 15;
    const int cAh = lane >> 4;
    const int rBl = (lane & 7) + ((lane & 16) >> 1);
    const int cBh = (lane >> 3) & 1;

    float acc[2][2][4];
#pragma unroll
    for (int mt = 0; mt < 2; ++mt)
#pragma unroll
        for (int nt = 0; nt < 2; ++nt)
#pragma unroll
            for (int j = 0; j < 4; ++j) acc[mt][nt][j] = 0.f;

    float4 sreg[4];
    auto ldS = [&](int kc) {
#pragma unroll
        for (int i = 0; i < 4; ++i) {
            int idx = i * 512 + tid;
            int row = idx >> 4, f4 = idx & 15;
            sreg[i] = __ldg((const float4*)(S + sOff + ((size_t)row << 10) +
                                            (kc << 6) + f4 * 4));
        }
    };
    auto cpV = [&](int kc) {
        const uint32_t vs = smBase + 32768u + (uint32_t)(kc % 3) * 8192u;
        int r = tid >> 3, c = tid & 7;
        CP_ASYNC16(vs + sw128(r, c), Vhi + vOff + ((size_t)r << 10) + (kc << 6) + c * 8);
        CP_COMMIT();
    };

    ldS(0);
    cpV(0);
    cpV(1);

    for (int kc = 0; kc < 16; ++kc) {
        const uint32_t pB = smBase + (uint32_t)(kc & 1) * 16384u;
#pragma unroll
        for (int i = 0; i < 4; ++i) {
            int idx = i * 512 + tid;
            int row = idx >> 4, f4 = idx & 15;
            float2 st = __ldg((const float2*)&stats[stOff + row]);
            float p0 = __expf(sreg[i].x - st.x) * st.y;
            float p1 = __expf(sreg[i].y - st.x) * st.y;
            float p2 = __expf(sreg[i].z - st.x) * st.y;
            float p3 = __expf(sreg[i].w - st.x) * st.y;
            __nv_bfloat162 ph0 = __halves2bfloat162(__float2bfloat16(p0),
                                                    __float2bfloat16(p1));
            __nv_bfloat162 ph1 = __halves2bfloat162(__float2bfloat16(p2),
                                                    __float2bfloat16(p3));
            uint32_t off = sw128(row, f4 >> 1) + (f4 & 1) * 8;
            asm volatile("st.shared.v2.b32 [%0], {%1, %2};" ::
                         "r"(pB + off), "r"(*(uint32_t*)&ph0), "r"(*(uint32_t*)&ph1)
                         : "memory");
        }
        if (kc + 1 < 16) ldS(kc + 1);

        CP_WAIT1();
        __syncthreads();
        if (kc + 2 < 16) cpV(kc + 2);
        else CP_COMMIT();

        const uint32_t phT = smBase + (uint32_t)(kc & 1) * 16384u;
        const uint32_t vhT = smBase + 32768u + (uint32_t)(kc % 3) * 8192u;

#pragma unroll
        for (int ks = 0; ks < 4; ++ks) {
            uint32_t ah[2][4];
            uint32_t bh[2][2];
#pragma unroll
            for (int mt = 0; mt < 2; ++mt) {
                int r = wr * 32 + mt * 16 + rA;
                ldsm4(ah[mt][0], ah[mt][1], ah[mt][2], ah[mt][3],
                      phT + sw128(r, ks * 2 + cAh));
            }
            {
                int r = wc * 16 + rBl;
                uint32_t x0, x1, x2, x3;
                ldsm4(x0, x1, x2, x3, vhT + sw128(r, ks * 2 + cBh));
                bh[0][0] = x0; bh[0][1] = x1; bh[1][0] = x2; bh[1][1] = x3;
            }
#pragma unroll
            for (int mt = 0; mt < 2; ++mt)
#pragma unroll
                for (int nt = 0; nt < 2; ++nt)
                    mma_bf16(acc[mt][nt], ah[mt], bh[nt]);
        }
    }

#pragma unroll
    for (int mt = 0; mt < 2; ++mt) {
        const int row = m0 + wr * 32 + mt * 16 + (lane >> 2);
#pragma unroll
        for (int nt = 0; nt < 2; ++nt) {
            const int col = h * 64 + wc * 16 + nt * 8 + (lane & 3) * 2;
            const size_t i0 = (((size_t)(b * 512 + row)) << 10) + col;
            const size_t i1 = i0 + (8 << 10);
            *(__nv_bfloat162*)(Chi + i0) =
                __halves2bfloat162(__float2bfloat16(acc[mt][nt][0]),
                                   __float2bfloat16(acc[mt][nt][1]));
            *(__nv_bfloat162*)(Chi + i1) =
                __halves2bfloat162(__float2bfloat16(acc[mt][nt][2]),
                                   __float2bfloat16(acc[mt][nt][3]));
        }
    }
}

// ---------------------------------------------------------------------------
// out = LayerNorm(query + attn_out) * gamma + beta.  One block per row.
// ---------------------------------------------------------------------------
__global__ void residual_ln(const float* __restrict__ q, const float* __restrict__ ao,
                            const float* __restrict__ gamma, const float* __restrict__ beta,
                            float* __restrict__ out)
{
    __shared__ float red[8];
    __shared__ float bcast;
    const long row = blockIdx.x;
    const int tid = threadIdx.x;

    float4 qa = *(const float4*)&q [row * DD + tid * 4];
    float4 aa = *(const float4*)&ao[row * DD + tid * 4];
    float x0 = qa.x + aa.x, x1 = qa.y + aa.y, x2 = qa.z + aa.z, x3 = qa.w + aa.w;

    float s = (x0 + x1) + (x2 + x3);
#pragma unroll
    for (int o = 16; o; o >>= 1) s += __shfl_xor_sync(0xffffffffu, s, o);
    if ((tid & 31) == 0) red[tid >> 5] = s;
    __syncthreads();
    if (tid < 8) {
        s = red[tid];
#pragma unroll
        for (int o = 4; o; o >>= 1) s += __shfl_xor_sync(0xffu, s, o);
        if (tid == 0) bcast = s;
    }
    __syncthreads();
    const float mu = bcast * (1.0f / DD);

    float d0 = x0 - mu, d1 = x1 - mu, d2 = x2 - mu, d3 = x3 - mu;
    float sq = (d0 * d0 + d1 * d1) + (d2 * d2 + d3 * d3);
#pragma unroll
    for (int o = 16; o; o >>= 1) sq += __shfl_xor_sync(0xffffffffu, sq, o);
    __syncthreads();
    if ((tid & 31) == 0) red[tid >> 5] = sq;
    __syncthreads();
    if (tid < 8) {
        sq = red[tid];
#pragma unroll
        for (int o = 4; o; o >>= 1) sq += __shfl_xor_sync(0xffu, sq, o);
        if (tid == 0) bcast = sq;
    }
    __syncthreads();
    const float rstd = rsqrtf(bcast * (1.0f / DD) + LN_EPS);

    float4 g = *(const float4*)&gamma[tid * 4];
    float4 be = *(const float4*)&beta[tid * 4];
    float4 o4;
    o4.x = d0 * rstd * g.x + be.x;
    o4.y = d1 * rstd * g.y + be.y;
    o4.z = d2 * rstd * g.z + be.z;
    o4.w = d3 * rstd * g.w + be.w;
    *(float4*)&out[row * DD + tid * 4] = o4;
}

// ---------------------------------------------------------------------------
extern "C" void kernel_launch(void* const* d_in, const int* in_sizes, int n_in,
                              void* d_out, int out_size)
{
    const float* query = (const float*)d_in[0];
    const float* key_  = (const float*)d_in[1];
    const float* value = (const float*)d_in[2];
    const float* in_w  = (const float*)d_in[3];
    const float* in_b  = (const float*)d_in[4];
    const float* out_w = (const float*)d_in[5];
    const float* out_b = (const float*)d_in[6];
    const float* gamma = (const float*)d_in[7];
    const float* beta  = (const float*)d_in[8];
    float* out = (float*)d_out;

    float *V, *S, *AO;
    float2* ST;
    cudaGetSymbolAddress((void**)&V,  g_V);
    cudaGetSymbolAddress((void**)&S,  g_S);
    cudaGetSymbolAddress((void**)&AO, g_AO);
    cudaGetSymbolAddress((void**)&ST, g_stats);

    __nv_bfloat16 *qh, *ql, *kh, *kl, *vh, *wh, *wl, *woh;
    __nv_bfloat16 *qh2, *ql2, *kh2, *kl2, *ch;
    cudaGetSymbolAddress((void**)&qh,  g_qh);  cudaGetSymbolAddress((void**)&ql,  g_ql);
    cudaGetSymbolAddress((void**)&kh,  g_kh);  cudaGetSymbolAddress((void**)&kl,  g_kl);
    cudaGetSymbolAddress((void**)&vh,  g_vh);
    cudaGetSymbolAddress((void**)&wh,  g_wh);  cudaGetSymbolAddress((void**)&wl,  g_wl);
    cudaGetSymbolAddress((void**)&woh, g_woh);
    cudaGetSymbolAddress((void**)&qh2, g_qh2); cudaGetSymbolAddress((void**)&ql2, g_ql2);
    cudaGetSymbolAddress((void**)&kh2, g_kh2); cudaGetSymbolAddress((void**)&kl2, g_kl2);
    cudaGetSymbolAddress((void**)&ch,  g_ch);

    const int SM_G = 3 * 32768;
    const int SM_X = 2 * 16384 + 3 * 8192;   // ctx_fused: 56 KB
    cudaFuncSetAttribute((const void*)gemm64<16, 3, true>,
                         cudaFuncAttributeMaxDynamicSharedMemorySize, SM_G);
    cudaFuncSetAttribute((const void*)gemm64<16, 1, false>,
                         cudaFuncAttributeMaxDynamicSharedMemorySize, SM_G);
    cudaFuncSetAttribute((const void*)gemm64<16, 3, false>,
                         cudaFuncAttributeMaxDynamicSharedMemorySize, SM_G);
    cudaFuncSetAttribute((const void*)gemm64<1, 3, false>,
                         cudaFuncAttributeMaxDynamicSharedMemorySize, SM_G);
    cudaFuncSetAttribute((const void*)ctx_fused,
                         cudaFuncAttributeMaxDynamicSharedMemorySize, SM_X);

    const float qscale = 0.125f;

    auto launch_split = [](const float* x, __nv_bfloat16* h, __nv_bfloat16* l, long n) {
        int n4 = (int)(n / 4);
        split_bf16<<<(n4 + 255) / 256, 256>>>((const float4*)x, (__nv_bfloat162*)h,
                                              (__nv_bfloat162*)l, n4);
    };

    // 1) split inputs + weights (value & out_w hi-only: V path is plain bf16)
    launch_split(query, qh, ql, (long)BB * LQ  * DD);
    launch_split(key_,  kh, kl, (long)BB * LKV * DD);
    {
        int n4 = BB * LKV * DD / 4;
        split1_bf16<<<(n4 + 255) / 256, 256>>>((const float4*)value,
                                               (__nv_bfloat162*)vh, n4);
    }
    launch_split(in_w, wh, wl, 3L * DD * DD);
    {
        int n4 = DD * DD / 4;
        split1_bf16<<<(n4 + 255) / 256, 256>>>((const float4*)out_w,
                                               (__nv_bfloat162*)woh, n4);
    }

    // 2) Q/K projections (bf16x3) -> bf16 hi/lo; V projection (bf16x1) -> fp32
    gemm64<16, 3, true><<<dim3(8, 32, 1), 128, SM_G>>>(
        qh, ql, wh, wl, in_b, nullptr, qh2, ql2, qscale, 0,0, 0,0, 0,0);
    gemm64<16, 3, true><<<dim3(8, 64, 1), 128, SM_G>>>(
        kh, kl, wh + (long)DD*DD, wl + (long)DD*DD, in_b + DD,
        nullptr, kh2, kl2, 1.0f, 0,0, 0,0, 0,0);
    gemm64<16, 1, false><<<dim3(8, 64, 1), 128, SM_G>>>(
        vh, nullptr, wh + 2L*DD*DD, nullptr, in_b + 2*DD,
        V, nullptr, nullptr, 1.0f, 0,0, 0,0, 0,0);

    // 3) transpose V into head-major Vt (hi only; reuses vh)
    transpose_v<<<dim3(LKV / 32, HD / 32, BB * HH_), 256>>>(V, vh);

    // 4) scores (bf16x3) -> fp32 S
    gemm64<1, 3, false><<<dim3(8, 4, BB * HH_), 128, SM_G>>>(
        qh2, ql2, kh2, kl2, nullptr, S, nullptr, nullptr, 1.0f,
        (long)LQ * DD,  (long)HD,
        (long)LKV * DD, (long)HD,
        (long)HH_ * LQ * LKV, (long)LQ * LKV);

    // 5) softmax stats + head-mean
    softmax_stats<<<BB * LQ, 512>>>(S, ST, out + (long)BB * LQ * DD);

    // 6) fused exp/normalize + ctx MMA (plain bf16) -> ch
    ctx_fused<<<dim3(1, 4, BB * HH_), 512, SM_X>>>(S, ST, vh, ch);

    // 7) out projection (bf16x1) -> fp32 AO
    gemm64<16, 1, false><<<dim3(8, 32, 1), 128, SM_G>>>(
        ch, nullptr, woh, nullptr, out_b, AO, nullptr, nullptr, 1.0f,
        0,0, 0,0, 0,0);

    // 8) residual + LayerNorm
    residual_ln<<<BB * LQ, 256>>>(query, AO, gamma, beta, out);
}

// round 9
// speedup vs baseline: 1.3881x; 1.1084x over previous
#include <cuda_runtime.h>
#include <cuda_bf16.h>
#include <math.h>
#include <stdint.h>

// Problem constants
#define BB   8
#define LQ   512
#define LKV  1024
#define DD   1024
#define HH_  16
#define HD   64
#define LN_EPS 1e-5f

// ---------------------------------------------------------------------------
// Scratch (device globals: allocation-free per harness rules)
// ---------------------------------------------------------------------------
__device__ float g_S  [(size_t)BB * HH_ * LQ * LKV]; // fp32 scores
__device__ float g_AO [BB * LQ  * DD];               // fp32 attn_out
__device__ float2 g_stats[(size_t)BB * HH_ * LQ];    // per-row {max, 1/sum}

// bf16 buffers
__device__ __align__(16) __nv_bfloat16 g_qh [BB * LQ  * DD], g_ql [BB * LQ  * DD];
__device__ __align__(16) __nv_bfloat16 g_kh [BB * LKV * DD], g_kl [BB * LKV * DD];
__device__ __align__(16) __nv_bfloat16 g_vh [BB * LKV * DD];   // value input hi
__device__ __align__(16) __nv_bfloat16 g_vt [BB * LKV * DD];   // Vt head-major bf16
__device__ __align__(16) __nv_bfloat16 g_wh [3 * DD * DD],   g_wl [3 * DD * DD];
__device__ __align__(16) __nv_bfloat16 g_woh[DD * DD];
__device__ __align__(16) __nv_bfloat16 g_qh2[BB * LQ  * DD], g_ql2[BB * LQ  * DD];
__device__ __align__(16) __nv_bfloat16 g_kh2[BB * LKV * DD], g_kl2[BB * LKV * DD];
__device__ __align__(16) __nv_bfloat16 g_ch [BB * LQ  * DD];

// ---------------------------------------------------------------------------
// Baseline-PTX tensor-core helpers (NO tcgen05 — compute_103 target!)
// ---------------------------------------------------------------------------
__device__ __forceinline__ uint32_t smem_u32(const void* p) {
    uint32_t a;
    asm("{ .reg .u64 t; cvta.to.shared.u64 t, %1; cvt.u32.u64 %0, t; }" : "=r"(a) : "l"(p));
    return a;
}
__device__ __forceinline__ void ldsm4(uint32_t& r0, uint32_t& r1, uint32_t& r2,
                                      uint32_t& r3, uint32_t a) {
    asm volatile("ldmatrix.sync.aligned.m8n8.x4.shared.b16 {%0,%1,%2,%3}, [%4];"
                 : "=r"(r0), "=r"(r1), "=r"(r2), "=r"(r3) : "r"(a));
}
__device__ __forceinline__ void mma_bf16(float* d, const uint32_t* a, const uint32_t* b) {
    asm volatile("mma.sync.aligned.m16n8k16.row.col.f32.bf16.bf16.f32 "
                 "{%0,%1,%2,%3},{%4,%5,%6,%7},{%8,%9},{%0,%1,%2,%3};"
                 : "+f"(d[0]), "+f"(d[1]), "+f"(d[2]), "+f"(d[3])
                 : "r"(a[0]), "r"(a[1]), "r"(a[2]), "r"(a[3]), "r"(b[0]), "r"(b[1]));
}
#define CP_ASYNC16(s, g) \
    asm volatile("cp.async.cg.shared.global [%0], [%1], 16;" :: "r"(s), "l"(g))
#define CP_COMMIT() asm volatile("cp.async.commit_group;" ::: "memory")
#define CP_WAIT1()  asm volatile("cp.async.wait_group 1;"  ::: "memory")

// 128B-row XOR swizzle: 16B chunk c (0..7), row r
__device__ __forceinline__ uint32_t sw128(int r, int c) {
    return (uint32_t)(r * 128 + ((c ^ (r & 7)) << 4));
}
__device__ __forceinline__ void bsplit(float v, __nv_bfloat16& h, __nv_bfloat16& l) {
    h = __float2bfloat16(v);
    l = __float2bfloat16(v - __bfloat162float(h));
}

// ---------------------------------------------------------------------------
// One launch: split all inputs/weights (hi/lo or hi-only per segment)
// ---------------------------------------------------------------------------
__device__ __forceinline__ void seg_split2(float4 v, __nv_bfloat162* hi,
                                           __nv_bfloat162* lo, long i) {
    __nv_bfloat16 h0, h1, h2, h3, l0, l1, l2, l3;
    bsplit(v.x, h0, l0); bsplit(v.y, h1, l1);
    bsplit(v.z, h2, l2); bsplit(v.w, h3, l3);
    hi[i * 2 + 0] = __halves2bfloat162(h0, h1);
    hi[i * 2 + 1] = __halves2bfloat162(h2, h3);
    lo[i * 2 + 0] = __halves2bfloat162(l0, l1);
    lo[i * 2 + 1] = __halves2bfloat162(l2, l3);
}
__device__ __forceinline__ void seg_split1(float4 v, __nv_bfloat162* hi, long i) {
    hi[i * 2 + 0] = __halves2bfloat162(__float2bfloat16(v.x), __float2bfloat16(v.y));
    hi[i * 2 + 1] = __halves2bfloat162(__float2bfloat16(v.z), __float2bfloat16(v.w));
}

__global__ void split_all(const float4* __restrict__ q, const float4* __restrict__ k,
                          const float4* __restrict__ v, const float4* __restrict__ w,
                          const float4* __restrict__ wo,
                          __nv_bfloat162* qh, __nv_bfloat162* ql,
                          __nv_bfloat162* kh, __nv_bfloat162* kl,
                          __nv_bfloat162* vh,
                          __nv_bfloat162* wh, __nv_bfloat162* wl,
                          __nv_bfloat162* woh)
{
    const long N1 = (long)BB * LQ * DD / 4;            // 1048576
    const long N2 = N1 + (long)BB * LKV * DD / 4;      // +2097152
    const long N3 = N2 + (long)BB * LKV * DD / 4;
    const long N4 = N3 + 3L * DD * DD / 4;
    const long N5 = N4 + (long)DD * DD / 4;
    long i = (long)blockIdx.x * blockDim.x + threadIdx.x;
    if (i < N1)      seg_split2(q[i], qh, ql, i);
    else if (i < N2) { i -= N1; seg_split2(k[i], kh, kl, i); }
    else if (i < N3) { i -= N2; seg_split1(v[i], vh, i); }
    else if (i < N4) { i -= N3; seg_split2(w[i], wh, wl, i); }
    else if (i < N5) { i -= N4; seg_split1(wo[i], woh, i); }
}

// ---------------------------------------------------------------------------
// Merged Q/K/V projection. Grid (8, 160): y<32 Q, y<96 K, else V.
// Q/K: bf16x3 (NIT=48), epilogue -> bf16 hi/lo split.
// V:   bf16x1 (NIT=16), epilogue -> smem transpose -> head-major Vt bf16.
// Block 128x128, 4 warps (64x64 warp tile), BK=64, 3-stage cp.async.
// ---------------------------------------------------------------------------
__global__ void __launch_bounds__(128, 2) qkv_proj(
    const __nv_bfloat16* __restrict__ qhp, const __nv_bfloat16* __restrict__ qlp,
    const __nv_bfloat16* __restrict__ khp, const __nv_bfloat16* __restrict__ klp,
    const __nv_bfloat16* __restrict__ vhp,
    const __nv_bfloat16* __restrict__ whp, const __nv_bfloat16* __restrict__ wlp,
    const float* __restrict__ in_b,
    __nv_bfloat16* __restrict__ qh2, __nv_bfloat16* __restrict__ ql2,
    __nv_bfloat16* __restrict__ kh2, __nv_bfloat16* __restrict__ kl2,
    __nv_bfloat16* __restrict__ vt, float qscale)
{
    extern __shared__ __align__(16) char dynsm[];
    const uint32_t smBase = smem_u32(dynsm);

    const int tid  = threadIdx.x;
    const int lane = tid & 31;
    const int wid  = tid >> 5;
    const int wr   = wid >> 1;
    const int wc   = wid & 1;
    const int y    = blockIdx.y;
    const int n0   = blockIdx.x * 128;

    int region, m0, NIT;
    float scale = 1.0f;
    const __nv_bfloat16 *Ahi, *Alo, *Bhi, *Blo;
    const float* bias;
    if (y < 32) {
        region = 0; m0 = y * 128; NIT = 48; scale = qscale;
        Ahi = qhp; Alo = qlp; Bhi = whp; Blo = wlp; bias = in_b;
    } else if (y < 96) {
        region = 1; m0 = (y - 32) * 128; NIT = 48;
        Ahi = khp; Alo = klp;
        Bhi = whp + (size_t)DD * DD; Blo = wlp + (size_t)DD * DD;
        bias = in_b + DD;
    } else {
        region = 2; m0 = (y - 96) * 128; NIT = 16;
        Ahi = vhp; Alo = vhp;
        Bhi = whp + 2ul * DD * DD; Blo = Bhi;
        bias = in_b + 2 * DD;
    }

    const int rA  = lane & 15;
    const int cAh = lane >> 4;
    const int rBl = (lane & 7) + ((lane & 16) >> 1);
    const int cBh = (lane >> 3) & 1;

    float acc[4][8][4];
#pragma unroll
    for (int mt = 0; mt < 4; ++mt)
#pragma unroll
        for (int nt = 0; nt < 8; ++nt)
#pragma unroll
            for (int j = 0; j < 4; ++j) acc[mt][nt][j] = 0.f;

    auto prefetch = [&](int it, int stage) {
        const int part = it >> 4;            // KCH = 16
        const int ko   = (it & 15) << 6;
        const __nv_bfloat16* Ap = (part == 2) ? Alo : Ahi;
        const __nv_bfloat16* Bp = (part == 1) ? Blo : Bhi;
        const uint32_t as = smBase + (uint32_t)stage * 32768u;
        const uint32_t bs = as + 16384u;
#pragma unroll
        for (int i = 0; i < 8; ++i) {
            int q = i * 128 + tid;
            int r = q >> 3, c = q & 7;
            CP_ASYNC16(as + sw128(r, c),
                       Ap + (((size_t)(m0 + r)) << 10) + ko + c * 8);
            CP_ASYNC16(bs + sw128(r, c),
                       Bp + (((size_t)(n0 + r)) << 10) + ko + c * 8);
        }
        CP_COMMIT();
    };

    prefetch(0, 0);
    prefetch(1, 1);

    for (int it = 0; it < NIT; ++it) {
        CP_WAIT1();
        __syncthreads();
        if (it + 2 < NIT) prefetch(it + 2, (it + 2) % 3);
        else CP_COMMIT();

        const uint32_t aT = smBase + (uint32_t)(it % 3) * 32768u;
        const uint32_t bT = aT + 16384u;

#pragma unroll
        for (int ks = 0; ks < 4; ++ks) {
            uint32_t af[4][4];
            uint32_t bf[8][2];
#pragma unroll
            for (int mt = 0; mt < 4; ++mt) {
                int r = wr * 64 + mt * 16 + rA;
                ldsm4(af[mt][0], af[mt][1], af[mt][2], af[mt][3],
                      aT + sw128(r, ks * 2 + cAh));
            }
#pragma unroll
            for (int tp = 0; tp < 4; ++tp) {
                int r = wc * 64 + tp * 16 + rBl;
                uint32_t x0, x1, x2, x3;
                ldsm4(x0, x1, x2, x3, bT + sw128(r, ks * 2 + cBh));
                bf[tp * 2][0] = x0;     bf[tp * 2][1] = x1;
                bf[tp * 2 + 1][0] = x2; bf[tp * 2 + 1][1] = x3;
            }
#pragma unroll
            for (int mt = 0; mt < 4; ++mt)
#pragma unroll
                for (int nt = 0; nt < 8; ++nt)
                    mma_bf16(acc[mt][nt], af[mt], bf[nt]);
        }
    }
    __syncthreads();

    if (region < 2) {
        __nv_bfloat16* Chi = region ? kh2 : qh2;
        __nv_bfloat16* Clo = region ? kl2 : ql2;
#pragma unroll
        for (int mt = 0; mt < 4; ++mt) {
            const int row = m0 + wr * 64 + mt * 16 + (lane >> 2);
#pragma unroll
            for (int nt = 0; nt < 8; ++nt) {
                const int col = n0 + wc * 64 + nt * 8 + (lane & 3) * 2;
                const float b0 = bias[col], b1 = bias[col + 1];
                const float v0 = (acc[mt][nt][0] + b0) * scale;
                const float v1 = (acc[mt][nt][1] + b1) * scale;
                const float v2 = (acc[mt][nt][2] + b0) * scale;
                const float v3 = (acc[mt][nt][3] + b1) * scale;
                const size_t i0 = ((size_t)row << 10) + col;
                const size_t i1 = i0 + (8 << 10);
                __nv_bfloat16 h0, h1, h2, h3, l0, l1, l2, l3;
                bsplit(v0, h0, l0); bsplit(v1, h1, l1);
                bsplit(v2, h2, l2); bsplit(v3, h3, l3);
                *(__nv_bfloat162*)(Chi + i0) = __halves2bfloat162(h0, h1);
                *(__nv_bfloat162*)(Clo + i0) = __halves2bfloat162(l0, l1);
                *(__nv_bfloat162*)(Chi + i1) = __halves2bfloat162(h2, h3);
                *(__nv_bfloat162*)(Clo + i1) = __halves2bfloat162(l2, l3);
            }
        }
    } else {
        // V region: bias + transpose through smem -> head-major Vt bf16.
        float* ts = (float*)dynsm;   // 128 x 128 fp32, stride 130 (66.6 KB)
#pragma unroll
        for (int mt = 0; mt < 4; ++mt) {
            const int rl = wr * 64 + mt * 16 + (lane >> 2);
#pragma unroll
            for (int nt = 0; nt < 8; ++nt) {
                const int cl = wc * 64 + nt * 8 + (lane & 3) * 2;
                const float b0 = bias[n0 + cl], b1 = bias[n0 + cl + 1];
                ts[rl * 130 + cl]           = acc[mt][nt][0] + b0;
                ts[rl * 130 + cl + 1]       = acc[mt][nt][1] + b1;
                ts[(rl + 8) * 130 + cl]     = acc[mt][nt][2] + b0;
                ts[(rl + 8) * 130 + cl + 1] = acc[mt][nt][3] + b1;
            }
        }
        __syncthreads();
        // m0 = b*1024 + k0 ; output row = b*1024 + (n0 + tid) ; cols k0..k0+127
        const int bb = m0 >> 10;
        const int k0 = m0 & 1023;
        __nv_bfloat16* dst = vt + (((size_t)(bb * 1024 + n0 + tid)) << 10) + k0;
#pragma unroll
        for (int k = 0; k < 128; k += 8) {
            __nv_bfloat162 p0 = __halves2bfloat162(
                __float2bfloat16(ts[(k + 0) * 130 + tid]),
                __float2bfloat16(ts[(k + 1) * 130 + tid]));
            __nv_bfloat162 p1 = __halves2bfloat162(
                __float2bfloat16(ts[(k + 2) * 130 + tid]),
                __float2bfloat16(ts[(k + 3) * 130 + tid]));
            __nv_bfloat162 p2 = __halves2bfloat162(
                __float2bfloat16(ts[(k + 4) * 130 + tid]),
                __float2bfloat16(ts[(k + 5) * 130 + tid]));
            __nv_bfloat162 p3 = __halves2bfloat162(
                __float2bfloat16(ts[(k + 6) * 130 + tid]),
                __float2bfloat16(ts[(k + 7) * 130 + tid]));
            uint4 pk;
            pk.x = *(uint32_t*)&p0; pk.y = *(uint32_t*)&p1;
            pk.z = *(uint32_t*)&p2; pk.w = *(uint32_t*)&p3;
            *(uint4*)(dst + k) = pk;
        }
    }
}

// ---------------------------------------------------------------------------
// HMMA GEMM template (used for scores [KCH=1,PARTS=3] and out-proj
// [KCH=16,PARTS=1]). Same tiling as qkv_proj.
// ---------------------------------------------------------------------------
template<int KCH, int PARTS>
__global__ void __launch_bounds__(128, 2) gemm64(
    const __nv_bfloat16* __restrict__ Ahi, const __nv_bfloat16* __restrict__ Alo,
    const __nv_bfloat16* __restrict__ Bhi, const __nv_bfloat16* __restrict__ Blo,
    const float* __restrict__ bias, float* __restrict__ Cf, float scale,
    long sA0, long sA1, long sB0, long sB1, long sC0, long sC1)
{
    extern __shared__ __align__(16) char dynsm[];
    const uint32_t smBase = smem_u32(dynsm);

    const int tid  = threadIdx.x;
    const int lane = tid & 31;
    const int wid  = tid >> 5;
    const int wr   = wid >> 1;
    const int wc   = wid & 1;
    const int z    = blockIdx.z;
    const int m0   = blockIdx.y * 128;
    const int n0   = blockIdx.x * 128;
    const size_t aOff = (size_t)(z >> 4) * sA0 + (size_t)(z & 15) * sA1;
    const size_t bOff = (size_t)(z >> 4) * sB0 + (size_t)(z & 15) * sB1;
    const size_t cOff = (size_t)(z >> 4) * sC0 + (size_t)(z & 15) * sC1;

    const int rA  = lane & 15;
    const int cAh = lane >> 4;
    const int rBl = (lane & 7) + ((lane & 16) >> 1);
    const int cBh = (lane >> 3) & 1;

    float acc[4][8][4];
#pragma unroll
    for (int mt = 0; mt < 4; ++mt)
#pragma unroll
        for (int nt = 0; nt < 8; ++nt)
#pragma unroll
            for (int j = 0; j < 4; ++j) acc[mt][nt][j] = 0.f;

    auto prefetch = [&](int it, int stage) {
        const int part = it / KCH;
        const int ko   = (it % KCH) << 6;
        const __nv_bfloat16* Ap = (PARTS == 3 && part == 2) ? Alo : Ahi;
        const __nv_bfloat16* Bp = (PARTS == 3 && part == 1) ? Blo : Bhi;
        const uint32_t as = smBase + (uint32_t)stage * 32768u;
        const uint32_t bs = as + 16384u;
#pragma unroll
        for (int i = 0; i < 8; ++i) {
            int q = i * 128 + tid;
            int r = q >> 3, c = q & 7;
            CP_ASYNC16(as + sw128(r, c),
                       Ap + aOff + (((size_t)(m0 + r)) << 10) + ko + c * 8);
            CP_ASYNC16(bs + sw128(r, c),
                       Bp + bOff + (((size_t)(n0 + r)) << 10) + ko + c * 8);
        }
        CP_COMMIT();
    };

    const int NIT = PARTS * KCH;
    prefetch(0, 0);
    if (NIT > 1) prefetch(1, 1);

    for (int it = 0; it < NIT; ++it) {
        CP_WAIT1();
        __syncthreads();
        if (it + 2 < NIT) prefetch(it + 2, (it + 2) % 3);
        else CP_COMMIT();

        const uint32_t aT = smBase + (uint32_t)(it % 3) * 32768u;
        const uint32_t bT = aT + 16384u;

#pragma unroll
        for (int ks = 0; ks < 4; ++ks) {
            uint32_t af[4][4];
            uint32_t bf[8][2];
#pragma unroll
            for (int mt = 0; mt < 4; ++mt) {
                int r = wr * 64 + mt * 16 + rA;
                ldsm4(af[mt][0], af[mt][1], af[mt][2], af[mt][3],
                      aT + sw128(r, ks * 2 + cAh));
            }
#pragma unroll
            for (int tp = 0; tp < 4; ++tp) {
                int r = wc * 64 + tp * 16 + rBl;
                uint32_t x0, x1, x2, x3;
                ldsm4(x0, x1, x2, x3, bT + sw128(r, ks * 2 + cBh));
                bf[tp * 2][0] = x0;     bf[tp * 2][1] = x1;
                bf[tp * 2 + 1][0] = x2; bf[tp * 2 + 1][1] = x3;
            }
#pragma unroll
            for (int mt = 0; mt < 4; ++mt)
#pragma unroll
                for (int nt = 0; nt < 8; ++nt)
                    mma_bf16(acc[mt][nt], af[mt], bf[nt]);
        }
    }
    __syncthreads();

#pragma unroll
    for (int mt = 0; mt < 4; ++mt) {
        const int row = m0 + wr * 64 + mt * 16 + (lane >> 2);
#pragma unroll
        for (int nt = 0; nt < 8; ++nt) {
            const int col = n0 + wc * 64 + nt * 8 + (lane & 3) * 2;
            const float b0 = bias ? bias[col]     : 0.f;
            const float b1 = bias ? bias[col + 1] : 0.f;
            const size_t i0 = cOff + ((size_t)row << 10) + col;
            const size_t i1 = i0 + (8 << 10);
            Cf[i0]     = (acc[mt][nt][0] + b0) * scale;
            Cf[i0 + 1] = (acc[mt][nt][1] + b1) * scale;
            Cf[i1]     = (acc[mt][nt][2] + b0) * scale;
            Cf[i1 + 1] = (acc[mt][nt][3] + b1) * scale;
        }
    }
}

// ---------------------------------------------------------------------------
// Softmax stats + head-mean. One block (512 thr = 16 warps) per (b,q).
// ---------------------------------------------------------------------------
__global__ void __launch_bounds__(512) softmax_stats(const float* __restrict__ S,
                                                     float2* __restrict__ stats,
                                                     float* __restrict__ mean_out)
{
    __shared__ float mean[1024];
    const int bq = blockIdx.x;
    const int b = bq >> 9, q = bq & 511;
    const int tid = threadIdx.x;
    const int lane = tid & 31, w = tid >> 5;

    mean[tid] = 0.f;
    mean[tid + 512] = 0.f;
    __syncthreads();

    const size_t rowe = ((size_t)(b * 16 + w) * 512 + q) << 10;
    float4 v[8];
#pragma unroll
    for (int i = 0; i < 8; ++i)
        v[i] = __ldg((const float4*)(S + rowe + (i * 32 + lane) * 4));

    float m = -1e30f;
#pragma unroll
    for (int i = 0; i < 8; ++i)
        m = fmaxf(m, fmaxf(fmaxf(v[i].x, v[i].y), fmaxf(v[i].z, v[i].w)));
#pragma unroll
    for (int o = 16; o; o >>= 1) m = fmaxf(m, __shfl_xor_sync(0xffffffffu, m, o));

    float s = 0.f;
#pragma unroll
    for (int i = 0; i < 8; ++i) {
        v[i].x = __expf(v[i].x - m); v[i].y = __expf(v[i].y - m);
        v[i].z = __expf(v[i].z - m); v[i].w = __expf(v[i].w - m);
        s += (v[i].x + v[i].y) + (v[i].z + v[i].w);
    }
#pragma unroll
    for (int o = 16; o; o >>= 1) s += __shfl_xor_sync(0xffffffffu, s, o);
    const float inv = 1.0f / s;

    if (lane == 0)
        stats[(size_t)(b * 16 + w) * 512 + q] = make_float2(m, inv);

#pragma unroll
    for (int i = 0; i < 8; ++i) {
        int base = (i * 32 + lane) * 4;
        atomicAdd(&mean[base + 0], v[i].x * inv);
        atomicAdd(&mean[base + 1], v[i].y * inv);
        atomicAdd(&mean[base + 2], v[i].z * inv);
        atomicAdd(&mean[base + 3], v[i].w * inv);
    }
    __syncthreads();

    const float inv16 = 1.0f / HH_;
    float* mo = mean_out + (((size_t)bq) << 10);
    mo[tid]       = mean[tid] * inv16;
    mo[tid + 512] = mean[tid + 512] * inv16;
}

// ---------------------------------------------------------------------------
// Fused ctx (plain bf16): per z=(b,h), q-tile 128: reads fp32 S, exp*inv
// in-flight, P hi in SMEM, MMA vs Vt. 512 thr (16 warps, 32x16 warp tiles).
// SMEM: P 2x16KB + V 3x8KB = 56KB.
// ---------------------------------------------------------------------------
__global__ void __launch_bounds__(512) ctx_fused(
    const float* __restrict__ S, const float2* __restrict__ stats,
    const __nv_bfloat16* __restrict__ Vhi,
    __nv_bfloat16* __restrict__ Chi)
{
    extern __shared__ __align__(16) char dynsm[];
    const uint32_t smBase = smem_u32(dynsm);

    const int tid  = threadIdx.x;
    const int lane = tid & 31;
    const int wid  = tid >> 5;
    const int wr   = wid >> 2;
    const int wc   = wid & 3;
    const int z    = blockIdx.z, b = z >> 4, h = z & 15;
    const int m0   = blockIdx.y * 128;
    const size_t sOff  = ((size_t)z * 512 + m0) << 10;
    const size_t vOff  = ((size_t)z * 64) << 10;
    const int    stOff = z * 512 + m0;

    const int rA  = lane & 15;
    const int cAh = lane >> 4;
    const int rBl = (lane & 7) + ((lane & 16) >> 1);
    const int cBh = (lane >> 3) & 1;

    float acc[2][2][4];
#pragma unroll
    for (int mt = 0; mt < 2; ++mt)
#pragma unroll
        for (int nt = 0; nt < 2; ++nt)
#pragma unroll
            for (int j = 0; j < 4; ++j) acc[mt][nt][j] = 0.f;

    float4 sreg[4];
    auto ldS = [&](int kc) {
#pragma unroll
        for (int i = 0; i < 4; ++i) {
            int idx = i * 512 + tid;
            int row = idx >> 4, f4 = idx & 15;
            sreg[i] = __ldg((const float4*)(S + sOff + ((size_t)row << 10) +
                                            (kc << 6) + f4 * 4));
        }
    };
    auto cpV = [&](int kc) {
        const uint32_t vs = smBase + 32768u + (uint32_t)(kc % 3) * 8192u;
        int r = tid >> 3, c = tid & 7;
        CP_ASYNC16(vs + sw128(r, c), Vhi + vOff + ((size_t)r << 10) + (kc << 6) + c * 8);
        CP_COMMIT();
    };

    ldS(0);
    cpV(0);
    cpV(1);

    for (int kc = 0; kc < 16; ++kc) {
        const uint32_t pB = smBase + (uint32_t)(kc & 1) * 16384u;
#pragma unroll
        for (int i = 0; i < 4; ++i) {
            int idx = i * 512 + tid;
            int row = idx >> 4, f4 = idx & 15;
            float2 st = __ldg((const float2*)&stats[stOff + row]);
            float p0 = __expf(sreg[i].x - st.x) * st.y;
            float p1 = __expf(sreg[i].y - st.x) * st.y;
            float p2 = __expf(sreg[i].z - st.x) * st.y;
            float p3 = __expf(sreg[i].w - st.x) * st.y;
            __nv_bfloat162 ph0 = __halves2bfloat162(__float2bfloat16(p0),
                                                    __float2bfloat16(p1));
            __nv_bfloat162 ph1 = __halves2bfloat162(__float2bfloat16(p2),
                                                    __float2bfloat16(p3));
            uint32_t off = sw128(row, f4 >> 1) + (f4 & 1) * 8;
            asm volatile("st.shared.v2.b32 [%0], {%1, %2};" ::
                         "r"(pB + off), "r"(*(uint32_t*)&ph0), "r"(*(uint32_t*)&ph1)
                         : "memory");
        }
        if (kc + 1 < 16) ldS(kc + 1);

        CP_WAIT1();
        __syncthreads();
        if (kc + 2 < 16) cpV(kc + 2);
        else CP_COMMIT();

        const uint32_t phT = smBase + (uint32_t)(kc & 1) * 16384u;
        const uint32_t vhT = smBase + 32768u + (uint32_t)(kc % 3) * 8192u;

#pragma unroll
        for (int ks = 0; ks < 4; ++ks) {
            uint32_t ah[2][4];
            uint32_t bh[2][2];
#pragma unroll
            for (int mt = 0; mt < 2; ++mt) {
                int r = wr * 32 + mt * 16 + rA;
                ldsm4(ah[mt][0], ah[mt][1], ah[mt][2], ah[mt][3],
                      phT + sw128(r, ks * 2 + cAh));
            }
            {
                int r = wc * 16 + rBl;
                uint32_t x0, x1, x2, x3;
                ldsm4(x0, x1, x2, x3, vhT + sw128(r, ks * 2 + cBh));
                bh[0][0] = x0; bh[0][1] = x1; bh[1][0] = x2; bh[1][1] = x3;
            }
#pragma unroll
            for (int mt = 0; mt < 2; ++mt)
#pragma unroll
                for (int nt = 0; nt < 2; ++nt)
                    mma_bf16(acc[mt][nt], ah[mt], bh[nt]);
        }
    }

#pragma unroll
    for (int mt = 0; mt < 2; ++mt) {
        const int row = m0 + wr * 32 + mt * 16 + (lane >> 2);
#pragma unroll
        for (int nt = 0; nt < 2; ++nt) {
            const int col = h * 64 + wc * 16 + nt * 8 + (lane & 3) * 2;
            const size_t i0 = (((size_t)(b * 512 + row)) << 10) + col;
            const size_t i1 = i0 + (8 << 10);
            *(__nv_bfloat162*)(Chi + i0) =
                __halves2bfloat162(__float2bfloat16(acc[mt][nt][0]),
                                   __float2bfloat16(acc[mt][nt][1]));
            *(__nv_bfloat162*)(Chi + i1) =
                __halves2bfloat162(__float2bfloat16(acc[mt][nt][2]),
                                   __float2bfloat16(acc[mt][nt][3]));
        }
    }
}

// ---------------------------------------------------------------------------
// out = LayerNorm(query + attn_out) * gamma + beta.  One block per row.
// ---------------------------------------------------------------------------
__global__ void residual_ln(const float* __restrict__ q, const float* __restrict__ ao,
                            const float* __restrict__ gamma, const float* __restrict__ beta,
                            float* __restrict__ out)
{
    __shared__ float red[8];
    __shared__ float bcast;
    const long row = blockIdx.x;
    const int tid = threadIdx.x;

    float4 qa = *(const float4*)&q [row * DD + tid * 4];
    float4 aa = *(const float4*)&ao[row * DD + tid * 4];
    float x0 = qa.x + aa.x, x1 = qa.y + aa.y, x2 = qa.z + aa.z, x3 = qa.w + aa.w;

    float s = (x0 + x1) + (x2 + x3);
#pragma unroll
    for (int o = 16; o; o >>= 1) s += __shfl_xor_sync(0xffffffffu, s, o);
    if ((tid & 31) == 0) red[tid >> 5] = s;
    __syncthreads();
    if (tid < 8) {
        s = red[tid];
#pragma unroll
        for (int o = 4; o; o >>= 1) s += __shfl_xor_sync(0xffu, s, o);
        if (tid == 0) bcast = s;
    }
    __syncthreads();
    const float mu = bcast * (1.0f / DD);

    float d0 = x0 - mu, d1 = x1 - mu, d2 = x2 - mu, d3 = x3 - mu;
    float sq = (d0 * d0 + d1 * d1) + (d2 * d2 + d3 * d3);
#pragma unroll
    for (int o = 16; o; o >>= 1) sq += __shfl_xor_sync(0xffffffffu, sq, o);
    __syncthreads();
    if ((tid & 31) == 0) red[tid >> 5] = sq;
    __syncthreads();
    if (tid < 8) {
        sq = red[tid];
#pragma unroll
        for (int o = 4; o; o >>= 1) sq += __shfl_xor_sync(0xffu, sq, o);
        if (tid == 0) bcast = sq;
    }
    __syncthreads();
    const float rstd = rsqrtf(bcast * (1.0f / DD) + LN_EPS);

    float4 g = *(const float4*)&gamma[tid * 4];
    float4 be = *(const float4*)&beta[tid * 4];
    float4 o4;
    o4.x = d0 * rstd * g.x + be.x;
    o4.y = d1 * rstd * g.y + be.y;
    o4.z = d2 * rstd * g.z + be.z;
    o4.w = d3 * rstd * g.w + be.w;
    *(float4*)&out[row * DD + tid * 4] = o4;
}

// ---------------------------------------------------------------------------
extern "C" void kernel_launch(void* const* d_in, const int* in_sizes, int n_in,
                              void* d_out, int out_size)
{
    const float* query = (const float*)d_in[0];
    const float* key_  = (const float*)d_in[1];
    const float* value = (const float*)d_in[2];
    const float* in_w  = (const float*)d_in[3];
    const float* in_b  = (const float*)d_in[4];
    const float* out_w = (const float*)d_in[5];
    const float* out_b = (const float*)d_in[6];
    const float* gamma = (const float*)d_in[7];
    const float* beta  = (const float*)d_in[8];
    float* out = (float*)d_out;

    float *S, *AO;
    float2* ST;
    cudaGetSymbolAddress((void**)&S,  g_S);
    cudaGetSymbolAddress((void**)&AO, g_AO);
    cudaGetSymbolAddress((void**)&ST, g_stats);

    __nv_bfloat16 *qh, *ql, *kh, *kl, *vh, *vt, *wh, *wl, *woh;
    __nv_bfloat16 *qh2, *ql2, *kh2, *kl2, *ch;
    cudaGetSymbolAddress((void**)&qh,  g_qh);  cudaGetSymbolAddress((void**)&ql,  g_ql);
    cudaGetSymbolAddress((void**)&kh,  g_kh);  cudaGetSymbolAddress((void**)&kl,  g_kl);
    cudaGetSymbolAddress((void**)&vh,  g_vh);  cudaGetSymbolAddress((void**)&vt,  g_vt);
    cudaGetSymbolAddress((void**)&wh,  g_wh);  cudaGetSymbolAddress((void**)&wl,  g_wl);
    cudaGetSymbolAddress((void**)&woh, g_woh);
    cudaGetSymbolAddress((void**)&qh2, g_qh2); cudaGetSymbolAddress((void**)&ql2, g_ql2);
    cudaGetSymbolAddress((void**)&kh2, g_kh2); cudaGetSymbolAddress((void**)&kl2, g_kl2);
    cudaGetSymbolAddress((void**)&ch,  g_ch);

    const int SM_G = 3 * 32768;
    const int SM_X = 2 * 16384 + 3 * 8192;
    cudaFuncSetAttribute((const void*)qkv_proj,
                         cudaFuncAttributeMaxDynamicSharedMemorySize, SM_G);
    cudaFuncSetAttribute((const void*)gemm64<1, 3>,
                         cudaFuncAttributeMaxDynamicSharedMemorySize, SM_G);
    cudaFuncSetAttribute((const void*)gemm64<16, 1>,
                         cudaFuncAttributeMaxDynamicSharedMemorySize, SM_G);
    cudaFuncSetAttribute((const void*)ctx_fused,
                         cudaFuncAttributeMaxDynamicSharedMemorySize, SM_X);

    const float qscale = 0.125f;

    // 1) split everything in one launch
    {
        const long total4 = (long)BB*LQ*DD/4 + 2L*BB*LKV*DD/4 + 3L*DD*DD/4 + (long)DD*DD/4;
        split_all<<<(unsigned)((total4 + 255) / 256), 256>>>(
            (const float4*)query, (const float4*)key_, (const float4*)value,
            (const float4*)in_w, (const float4*)out_w,
            (__nv_bfloat162*)qh, (__nv_bfloat162*)ql,
            (__nv_bfloat162*)kh, (__nv_bfloat162*)kl,
            (__nv_bfloat162*)vh,
            (__nv_bfloat162*)wh, (__nv_bfloat162*)wl,
            (__nv_bfloat162*)woh);
    }

    // 2) merged Q/K/V projection (+ fused V transpose -> vt)
    qkv_proj<<<dim3(8, 160), 128, SM_G>>>(
        qh, ql, kh, kl, vh, wh, wl, in_b,
        qh2, ql2, kh2, kl2, vt, qscale);

    // 3) scores (bf16x3) -> fp32 S
    gemm64<1, 3><<<dim3(8, 4, BB * HH_), 128, SM_G>>>(
        qh2, ql2, kh2, kl2, nullptr, S, 1.0f,
        (long)LQ * DD,  (long)HD,
        (long)LKV * DD, (long)HD,
        (long)HH_ * LQ * LKV, (long)LQ * LKV);

    // 4) softmax stats + head-mean
    softmax_stats<<<BB * LQ, 512>>>(S, ST, out + (long)BB * LQ * DD);

    // 5) fused exp/normalize + ctx MMA (plain bf16) -> ch
    ctx_fused<<<dim3(1, 4, BB * HH_), 512, SM_X>>>(S, ST, vt, ch);

    // 6) out projection (bf16x1) -> fp32 AO
    gemm64<16, 1><<<dim3(8, 32, 1), 128, SM_G>>>(
        ch, nullptr, woh, nullptr, out_b, AO, 1.0f, 0,0, 0,0, 0,0);

    // 7) residual + LayerNorm
    residual_ln<<<BB * LQ, 256>>>(query, AO, gamma, beta, out);
}

// round 10
// speedup vs baseline: 1.5775x; 1.1364x over previous
#include <cuda_runtime.h>
#include <cuda_bf16.h>
#include <math.h>
#include <stdint.h>

// Problem constants
#define BB   8
#define LQ   512
#define LKV  1024
#define DD   1024
#define HH_  16
#define HD   64
#define LN_EPS 1e-5f

// ---------------------------------------------------------------------------
// Scratch (device globals: allocation-free per harness rules)
// ---------------------------------------------------------------------------
__device__ float g_S  [(size_t)BB * HH_ * LQ * LKV]; // fp32 scores
__device__ float g_AO [BB * LQ  * DD];               // fp32 attn_out
__device__ float2 g_stats[(size_t)BB * HH_ * LQ];    // per-row {max, 1/sum}

// bf16 buffers
__device__ __align__(16) __nv_bfloat16 g_qh [BB * LQ  * DD], g_ql [BB * LQ  * DD];
__device__ __align__(16) __nv_bfloat16 g_kh [BB * LKV * DD], g_kl [BB * LKV * DD];
__device__ __align__(16) __nv_bfloat16 g_vh [BB * LKV * DD];   // value input hi
__device__ __align__(16) __nv_bfloat16 g_vt [BB * LKV * DD];   // Vt head-major bf16
__device__ __align__(16) __nv_bfloat16 g_wh [3 * DD * DD],   g_wl [3 * DD * DD];
__device__ __align__(16) __nv_bfloat16 g_woh[DD * DD];
__device__ __align__(16) __nv_bfloat16 g_qh2[BB * LQ  * DD], g_ql2[BB * LQ  * DD];
__device__ __align__(16) __nv_bfloat16 g_kh2[BB * LKV * DD], g_kl2[BB * LKV * DD];
__device__ __align__(16) __nv_bfloat16 g_ch [BB * LQ  * DD];

// ---------------------------------------------------------------------------
// Baseline-PTX tensor-core helpers (NO tcgen05 — compute_103 target!)
// ---------------------------------------------------------------------------
__device__ __forceinline__ uint32_t smem_u32(const void* p) {
    uint32_t a;
    asm("{ .reg .u64 t; cvta.to.shared.u64 t, %1; cvt.u32.u64 %0, t; }" : "=r"(a) : "l"(p));
    return a;
}
__device__ __forceinline__ void ldsm4(uint32_t& r0, uint32_t& r1, uint32_t& r2,
                                      uint32_t& r3, uint32_t a) {
    asm volatile("ldmatrix.sync.aligned.m8n8.x4.shared.b16 {%0,%1,%2,%3}, [%4];"
                 : "=r"(r0), "=r"(r1), "=r"(r2), "=r"(r3) : "r"(a));
}
__device__ __forceinline__ void mma_bf16(float* d, const uint32_t* a, const uint32_t* b) {
    asm volatile("mma.sync.aligned.m16n8k16.row.col.f32.bf16.bf16.f32 "
                 "{%0,%1,%2,%3},{%4,%5,%6,%7},{%8,%9},{%0,%1,%2,%3};"
                 : "+f"(d[0]), "+f"(d[1]), "+f"(d[2]), "+f"(d[3])
                 : "r"(a[0]), "r"(a[1]), "r"(a[2]), "r"(a[3]), "r"(b[0]), "r"(b[1]));
}
#define CP_ASYNC16(s, g) \
    asm volatile("cp.async.cg.shared.global [%0], [%1], 16;" :: "r"(s), "l"(g))
#define CP_COMMIT() asm volatile("cp.async.commit_group;" ::: "memory")
#define CP_WAIT1()  asm volatile("cp.async.wait_group 1;"  ::: "memory")

// 128B-row XOR swizzle: 16B chunk c (0..7), row r
__device__ __forceinline__ uint32_t sw128(int r, int c) {
    return (uint32_t)(r * 128 + ((c ^ (r & 7)) << 4));
}
__device__ __forceinline__ void bsplit(float v, __nv_bfloat16& h, __nv_bfloat16& l) {
    h = __float2bfloat16(v);
    l = __float2bfloat16(v - __bfloat162float(h));
}

// ---------------------------------------------------------------------------
// One launch: split all inputs/weights (hi/lo or hi-only per segment)
// ---------------------------------------------------------------------------
__device__ __forceinline__ void seg_split2(float4 v, __nv_bfloat162* hi,
                                           __nv_bfloat162* lo, long i) {
    __nv_bfloat16 h0, h1, h2, h3, l0, l1, l2, l3;
    bsplit(v.x, h0, l0); bsplit(v.y, h1, l1);
    bsplit(v.z, h2, l2); bsplit(v.w, h3, l3);
    hi[i * 2 + 0] = __halves2bfloat162(h0, h1);
    hi[i * 2 + 1] = __halves2bfloat162(h2, h3);
    lo[i * 2 + 0] = __halves2bfloat162(l0, l1);
    lo[i * 2 + 1] = __halves2bfloat162(l2, l3);
}
__device__ __forceinline__ void seg_split1(float4 v, __nv_bfloat162* hi, long i) {
    hi[i * 2 + 0] = __halves2bfloat162(__float2bfloat16(v.x), __float2bfloat16(v.y));
    hi[i * 2 + 1] = __halves2bfloat162(__float2bfloat16(v.z), __float2bfloat16(v.w));
}

__global__ void split_all(const float4* __restrict__ q, const float4* __restrict__ k,
                          const float4* __restrict__ v, const float4* __restrict__ w,
                          const float4* __restrict__ wo,
                          __nv_bfloat162* qh, __nv_bfloat162* ql,
                          __nv_bfloat162* kh, __nv_bfloat162* kl,
                          __nv_bfloat162* vh,
                          __nv_bfloat162* wh, __nv_bfloat162* wl,
                          __nv_bfloat162* woh)
{
    const long N1 = (long)BB * LQ * DD / 4;
    const long N2 = N1 + (long)BB * LKV * DD / 4;
    const long N3 = N2 + (long)BB * LKV * DD / 4;
    const long N4 = N3 + 3L * DD * DD / 4;
    const long N5 = N4 + (long)DD * DD / 4;
    long i = (long)blockIdx.x * blockDim.x + threadIdx.x;
    if (i < N1)      seg_split2(q[i], qh, ql, i);
    else if (i < N2) { i -= N1; seg_split2(k[i], kh, kl, i); }
    else if (i < N3) { i -= N2; seg_split1(v[i], vh, i); }
    else if (i < N4) { i -= N3; seg_split2(w[i], wh, wl, i); }
    else if (i < N5) { i -= N4; seg_split1(wo[i], woh, i); }
}

// ---------------------------------------------------------------------------
// Merged Q/K/V projection. Grid (8, 160): y<32 Q, y<96 K, else V.
// ---------------------------------------------------------------------------
__global__ void __launch_bounds__(128, 2) qkv_proj(
    const __nv_bfloat16* __restrict__ qhp, const __nv_bfloat16* __restrict__ qlp,
    const __nv_bfloat16* __restrict__ khp, const __nv_bfloat16* __restrict__ klp,
    const __nv_bfloat16* __restrict__ vhp,
    const __nv_bfloat16* __restrict__ whp, const __nv_bfloat16* __restrict__ wlp,
    const float* __restrict__ in_b,
    __nv_bfloat16* __restrict__ qh2, __nv_bfloat16* __restrict__ ql2,
    __nv_bfloat16* __restrict__ kh2, __nv_bfloat16* __restrict__ kl2,
    __nv_bfloat16* __restrict__ vt, float qscale)
{
    extern __shared__ __align__(16) char dynsm[];
    const uint32_t smBase = smem_u32(dynsm);

    const int tid  = threadIdx.x;
    const int lane = tid & 31;
    const int wid  = tid >> 5;
    const int wr   = wid >> 1;
    const int wc   = wid & 1;
    const int y    = blockIdx.y;
    const int n0   = blockIdx.x * 128;

    int region, m0, NIT;
    float scale = 1.0f;
    const __nv_bfloat16 *Ahi, *Alo, *Bhi, *Blo;
    const float* bias;
    if (y < 32) {
        region = 0; m0 = y * 128; NIT = 48; scale = qscale;
        Ahi = qhp; Alo = qlp; Bhi = whp; Blo = wlp; bias = in_b;
    } else if (y < 96) {
        region = 1; m0 = (y - 32) * 128; NIT = 48;
        Ahi = khp; Alo = klp;
        Bhi = whp + (size_t)DD * DD; Blo = wlp + (size_t)DD * DD;
        bias = in_b + DD;
    } else {
        region = 2; m0 = (y - 96) * 128; NIT = 16;
        Ahi = vhp; Alo = vhp;
        Bhi = whp + 2ul * DD * DD; Blo = Bhi;
        bias = in_b + 2 * DD;
    }

    const int rA  = lane & 15;
    const int cAh = lane >> 4;
    const int rBl = (lane & 7) + ((lane & 16) >> 1);
    const int cBh = (lane >> 3) & 1;

    float acc[4][8][4];
#pragma unroll
    for (int mt = 0; mt < 4; ++mt)
#pragma unroll
        for (int nt = 0; nt < 8; ++nt)
#pragma unroll
            for (int j = 0; j < 4; ++j) acc[mt][nt][j] = 0.f;

    auto prefetch = [&](int it, int stage) {
        const int part = it >> 4;
        const int ko   = (it & 15) << 6;
        const __nv_bfloat16* Ap = (part == 2) ? Alo : Ahi;
        const __nv_bfloat16* Bp = (part == 1) ? Blo : Bhi;
        const uint32_t as = smBase + (uint32_t)stage * 32768u;
        const uint32_t bs = as + 16384u;
#pragma unroll
        for (int i = 0; i < 8; ++i) {
            int q = i * 128 + tid;
            int r = q >> 3, c = q & 7;
            CP_ASYNC16(as + sw128(r, c),
                       Ap + (((size_t)(m0 + r)) << 10) + ko + c * 8);
            CP_ASYNC16(bs + sw128(r, c),
                       Bp + (((size_t)(n0 + r)) << 10) + ko + c * 8);
        }
        CP_COMMIT();
    };

    prefetch(0, 0);
    prefetch(1, 1);

    for (int it = 0; it < NIT; ++it) {
        CP_WAIT1();
        __syncthreads();
        if (it + 2 < NIT) prefetch(it + 2, (it + 2) % 3);
        else CP_COMMIT();

        const uint32_t aT = smBase + (uint32_t)(it % 3) * 32768u;
        const uint32_t bT = aT + 16384u;

#pragma unroll
        for (int ks = 0; ks < 4; ++ks) {
            uint32_t af[4][4];
            uint32_t bf[8][2];
#pragma unroll
            for (int mt = 0; mt < 4; ++mt) {
                int r = wr * 64 + mt * 16 + rA;
                ldsm4(af[mt][0], af[mt][1], af[mt][2], af[mt][3],
                      aT + sw128(r, ks * 2 + cAh));
            }
#pragma unroll
            for (int tp = 0; tp < 4; ++tp) {
                int r = wc * 64 + tp * 16 + rBl;
                uint32_t x0, x1, x2, x3;
                ldsm4(x0, x1, x2, x3, bT + sw128(r, ks * 2 + cBh));
                bf[tp * 2][0] = x0;     bf[tp * 2][1] = x1;
                bf[tp * 2 + 1][0] = x2; bf[tp * 2 + 1][1] = x3;
            }
#pragma unroll
            for (int mt = 0; mt < 4; ++mt)
#pragma unroll
                for (int nt = 0; nt < 8; ++nt)
                    mma_bf16(acc[mt][nt], af[mt], bf[nt]);
        }
    }
    __syncthreads();

    if (region < 2) {
        __nv_bfloat16* Chi = region ? kh2 : qh2;
        __nv_bfloat16* Clo = region ? kl2 : ql2;
#pragma unroll
        for (int mt = 0; mt < 4; ++mt) {
            const int row = m0 + wr * 64 + mt * 16 + (lane >> 2);
#pragma unroll
            for (int nt = 0; nt < 8; ++nt) {
                const int col = n0 + wc * 64 + nt * 8 + (lane & 3) * 2;
                const float b0 = bias[col], b1 = bias[col + 1];
                const float v0 = (acc[mt][nt][0] + b0) * scale;
                const float v1 = (acc[mt][nt][1] + b1) * scale;
                const float v2 = (acc[mt][nt][2] + b0) * scale;
                const float v3 = (acc[mt][nt][3] + b1) * scale;
                const size_t i0 = ((size_t)row << 10) + col;
                const size_t i1 = i0 + (8 << 10);
                __nv_bfloat16 h0, h1, h2, h3, l0, l1, l2, l3;
                bsplit(v0, h0, l0); bsplit(v1, h1, l1);
                bsplit(v2, h2, l2); bsplit(v3, h3, l3);
                *(__nv_bfloat162*)(Chi + i0) = __halves2bfloat162(h0, h1);
                *(__nv_bfloat162*)(Clo + i0) = __halves2bfloat162(l0, l1);
                *(__nv_bfloat162*)(Chi + i1) = __halves2bfloat162(h2, h3);
                *(__nv_bfloat162*)(Clo + i1) = __halves2bfloat162(l2, l3);
            }
        }
    } else {
        // V region: bias + transpose through smem -> head-major Vt bf16.
        float* ts = (float*)dynsm;   // 128 x 128 fp32, stride 130
#pragma unroll
        for (int mt = 0; mt < 4; ++mt) {
            const int rl = wr * 64 + mt * 16 + (lane >> 2);
#pragma unroll
            for (int nt = 0; nt < 8; ++nt) {
                const int cl = wc * 64 + nt * 8 + (lane & 3) * 2;
                const float b0 = bias[n0 + cl], b1 = bias[n0 + cl + 1];
                ts[rl * 130 + cl]           = acc[mt][nt][0] + b0;
                ts[rl * 130 + cl + 1]       = acc[mt][nt][1] + b1;
                ts[(rl + 8) * 130 + cl]     = acc[mt][nt][2] + b0;
                ts[(rl + 8) * 130 + cl + 1] = acc[mt][nt][3] + b1;
            }
        }
        __syncthreads();
        const int bb = m0 >> 10;
        const int k0 = m0 & 1023;
        __nv_bfloat16* dst = vt + (((size_t)(bb * 1024 + n0 + tid)) << 10) + k0;
#pragma unroll
        for (int k = 0; k < 128; k += 8) {
            __nv_bfloat162 p0 = __halves2bfloat162(
                __float2bfloat16(ts[(k + 0) * 130 + tid]),
                __float2bfloat16(ts[(k + 1) * 130 + tid]));
            __nv_bfloat162 p1 = __halves2bfloat162(
                __float2bfloat16(ts[(k + 2) * 130 + tid]),
                __float2bfloat16(ts[(k + 3) * 130 + tid]));
            __nv_bfloat162 p2 = __halves2bfloat162(
                __float2bfloat16(ts[(k + 4) * 130 + tid]),
                __float2bfloat16(ts[(k + 5) * 130 + tid]));
            __nv_bfloat162 p3 = __halves2bfloat162(
                __float2bfloat16(ts[(k + 6) * 130 + tid]),
                __float2bfloat16(ts[(k + 7) * 130 + tid]));
            uint4 pk;
            pk.x = *(uint32_t*)&p0; pk.y = *(uint32_t*)&p1;
            pk.z = *(uint32_t*)&p2; pk.w = *(uint32_t*)&p3;
            *(uint4*)(dst + k) = pk;
        }
    }
}

// ---------------------------------------------------------------------------
// HMMA GEMM template (scores [KCH=1,PARTS=3], out-proj [KCH=16,PARTS=1]).
// ---------------------------------------------------------------------------
template<int KCH, int PARTS>
__global__ void __launch_bounds__(128, 2) gemm64(
    const __nv_bfloat16* __restrict__ Ahi, const __nv_bfloat16* __restrict__ Alo,
    const __nv_bfloat16* __restrict__ Bhi, const __nv_bfloat16* __restrict__ Blo,
    const float* __restrict__ bias, float* __restrict__ Cf, float scale,
    long sA0, long sA1, long sB0, long sB1, long sC0, long sC1)
{
    extern __shared__ __align__(16) char dynsm[];
    const uint32_t smBase = smem_u32(dynsm);

    const int tid  = threadIdx.x;
    const int lane = tid & 31;
    const int wid  = tid >> 5;
    const int wr   = wid >> 1;
    const int wc   = wid & 1;
    const int z    = blockIdx.z;
    const int m0   = blockIdx.y * 128;
    const int n0   = blockIdx.x * 128;
    const size_t aOff = (size_t)(z >> 4) * sA0 + (size_t)(z & 15) * sA1;
    const size_t bOff = (size_t)(z >> 4) * sB0 + (size_t)(z & 15) * sB1;
    const size_t cOff = (size_t)(z >> 4) * sC0 + (size_t)(z & 15) * sC1;

    const int rA  = lane & 15;
    const int cAh = lane >> 4;
    const int rBl = (lane & 7) + ((lane & 16) >> 1);
    const int cBh = (lane >> 3) & 1;

    float acc[4][8][4];
#pragma unroll
    for (int mt = 0; mt < 4; ++mt)
#pragma unroll
        for (int nt = 0; nt < 8; ++nt)
#pragma unroll
            for (int j = 0; j < 4; ++j) acc[mt][nt][j] = 0.f;

    auto prefetch = [&](int it, int stage) {
        const int part = it / KCH;
        const int ko   = (it % KCH) << 6;
        const __nv_bfloat16* Ap = (PARTS == 3 && part == 2) ? Alo : Ahi;
        const __nv_bfloat16* Bp = (PARTS == 3 && part == 1) ? Blo : Bhi;
        const uint32_t as = smBase + (uint32_t)stage * 32768u;
        const uint32_t bs = as + 16384u;
#pragma unroll
        for (int i = 0; i < 8; ++i) {
            int q = i * 128 + tid;
            int r = q >> 3, c = q & 7;
            CP_ASYNC16(as + sw128(r, c),
                       Ap + aOff + (((size_t)(m0 + r)) << 10) + ko + c * 8);
            CP_ASYNC16(bs + sw128(r, c),
                       Bp + bOff + (((size_t)(n0 + r)) << 10) + ko + c * 8);
        }
        CP_COMMIT();
    };

    const int NIT = PARTS * KCH;
    prefetch(0, 0);
    if (NIT > 1) prefetch(1, 1);

    for (int it = 0; it < NIT; ++it) {
        CP_WAIT1();
        __syncthreads();
        if (it + 2 < NIT) prefetch(it + 2, (it + 2) % 3);
        else CP_COMMIT();

        const uint32_t aT = smBase + (uint32_t)(it % 3) * 32768u;
        const uint32_t bT = aT + 16384u;

#pragma unroll
        for (int ks = 0; ks < 4; ++ks) {
            uint32_t af[4][4];
            uint32_t bf[8][2];
#pragma unroll
            for (int mt = 0; mt < 4; ++mt) {
                int r = wr * 64 + mt * 16 + rA;
                ldsm4(af[mt][0], af[mt][1], af[mt][2], af[mt][3],
                      aT + sw128(r, ks * 2 + cAh));
            }
#pragma unroll
            for (int tp = 0; tp < 4; ++tp) {
                int r = wc * 64 + tp * 16 + rBl;
                uint32_t x0, x1, x2, x3;
                ldsm4(x0, x1, x2, x3, bT + sw128(r, ks * 2 + cBh));
                bf[tp * 2][0] = x0;     bf[tp * 2][1] = x1;
                bf[tp * 2 + 1][0] = x2; bf[tp * 2 + 1][1] = x3;
            }
#pragma unroll
            for (int mt = 0; mt < 4; ++mt)
#pragma unroll
                for (int nt = 0; nt < 8; ++nt)
                    mma_bf16(acc[mt][nt], af[mt], bf[nt]);
        }
    }
    __syncthreads();

#pragma unroll
    for (int mt = 0; mt < 4; ++mt) {
        const int row = m0 + wr * 64 + mt * 16 + (lane >> 2);
#pragma unroll
        for (int nt = 0; nt < 8; ++nt) {
            const int col = n0 + wc * 64 + nt * 8 + (lane & 3) * 2;
            const float b0 = bias ? bias[col]     : 0.f;
            const float b1 = bias ? bias[col + 1] : 0.f;
            const size_t i0 = cOff + ((size_t)row << 10) + col;
            const size_t i1 = i0 + (8 << 10);
            Cf[i0]     = (acc[mt][nt][0] + b0) * scale;
            Cf[i0 + 1] = (acc[mt][nt][1] + b1) * scale;
            Cf[i1]     = (acc[mt][nt][2] + b0) * scale;
            Cf[i1 + 1] = (acc[mt][nt][3] + b1) * scale;
        }
    }
}

// ---------------------------------------------------------------------------
// Softmax stats + head-mean. One block (512 thr = 16 warps) per (b,q);
// warp w owns head w's row (shfl reductions). Head-mean via PRIVATE per-warp
// smem slabs + tree-free column sum (no atomics: the R9 version's 16-way
// same-address shared atomics made L1 the bottleneck at 83%).
// Dynamic smem: 16 warps x 1024 fp32 = 64 KB.
// ---------------------------------------------------------------------------
__global__ void __launch_bounds__(512) softmax_stats(const float* __restrict__ S,
                                                     float2* __restrict__ stats,
                                                     float* __restrict__ mean_out)
{
    extern __shared__ __align__(16) float slab[];   // [16][1024]
    const int bq = blockIdx.x;
    const int b = bq >> 9, q = bq & 511;
    const int tid = threadIdx.x;
    const int lane = tid & 31, w = tid >> 5;

    const size_t rowe = ((size_t)(b * 16 + w) * 512 + q) << 10;
    float4 v[8];
#pragma unroll
    for (int i = 0; i < 8; ++i)
        v[i] = __ldg((const float4*)(S + rowe + (i * 32 + lane) * 4));

    float m = -1e30f;
#pragma unroll
    for (int i = 0; i < 8; ++i)
        m = fmaxf(m, fmaxf(fmaxf(v[i].x, v[i].y), fmaxf(v[i].z, v[i].w)));
#pragma unroll
    for (int o = 16; o; o >>= 1) m = fmaxf(m, __shfl_xor_sync(0xffffffffu, m, o));

    float s = 0.f;
#pragma unroll
    for (int i = 0; i < 8; ++i) {
        v[i].x = __expf(v[i].x - m); v[i].y = __expf(v[i].y - m);
        v[i].z = __expf(v[i].z - m); v[i].w = __expf(v[i].w - m);
        s += (v[i].x + v[i].y) + (v[i].z + v[i].w);
    }
#pragma unroll
    for (int o = 16; o; o >>= 1) s += __shfl_xor_sync(0xffffffffu, s, o);
    const float inv = 1.0f / s;

    if (lane == 0)
        stats[(size_t)(b * 16 + w) * 512 + q] = make_float2(m, inv);

    // store normalized row into this warp's private slab (float4, conflict-free)
    float4* wslab = (float4*)(slab + w * 1024);
#pragma unroll
    for (int i = 0; i < 8; ++i) {
        float4 p;
        p.x = v[i].x * inv; p.y = v[i].y * inv;
        p.z = v[i].z * inv; p.w = v[i].w * inv;
        wslab[i * 32 + lane] = p;
    }
    __syncthreads();

    // column sum over the 16 slabs: thread tid covers positions tid and tid+512
    float s0 = 0.f, s1 = 0.f;
#pragma unroll
    for (int h = 0; h < HH_; ++h) {
        s0 += slab[h * 1024 + tid];
        s1 += slab[h * 1024 + tid + 512];
    }
    const float inv16 = 1.0f / HH_;
    float* mo = mean_out + (((size_t)bq) << 10);
    mo[tid]       = s0 * inv16;
    mo[tid + 512] = s1 * inv16;
}

// ---------------------------------------------------------------------------
// Fused ctx (plain bf16): per z=(b,h), q-tile 128: reads fp32 S, exp*inv
// in-flight, P hi in SMEM, MMA vs Vt. 512 thr (16 warps, 32x16 warp tiles).
// ---------------------------------------------------------------------------
__global__ void __launch_bounds__(512) ctx_fused(
    const float* __restrict__ S, const float2* __restrict__ stats,
    const __nv_bfloat16* __restrict__ Vhi,
    __nv_bfloat16* __restrict__ Chi)
{
    extern __shared__ __align__(16) char dynsm[];
    const uint32_t smBase = smem_u32(dynsm);

    const int tid  = threadIdx.x;
    const int lane = tid & 31;
    const int wid  = tid >> 5;
    const int wr   = wid >> 2;
    const int wc   = wid & 3;
    const int z    = blockIdx.z, b = z >> 4, h = z & 15;
    const int m0   = blockIdx.y * 128;
    const size_t sOff  = ((size_t)z * 512 + m0) << 10;
    const size_t vOff  = ((size_t)z * 64) << 10;
    const int    stOff = z * 512 + m0;

    const int rA  = lane & 15;
    const int cAh = lane >> 4;
    const int rBl = (lane & 7) + ((lane & 16) >> 1);
    const int cBh = (lane >> 3) & 1;

    float acc[2][2][4];
#pragma unroll
    for (int mt = 0; mt < 2; ++mt)
#pragma unroll
        for (int nt = 0; nt < 2; ++nt)
#pragma unroll
            for (int j = 0; j < 4; ++j) acc[mt][nt][j] = 0.f;

    float4 sreg[4];
    auto ldS = [&](int kc) {
#pragma unroll
        for (int i = 0; i < 4; ++i) {
            int idx = i * 512 + tid;
            int row = idx >> 4, f4 = idx & 15;
            sreg[i] = __ldg((const float4*)(S + sOff + ((size_t)row << 10) +
                                            (kc << 6) + f4 * 4));
        }
    };
    auto cpV = [&](int kc) {
        const uint32_t vs = smBase + 32768u + (uint32_t)(kc % 3) * 8192u;
        int r = tid >> 3, c = tid & 7;
        CP_ASYNC16(vs + sw128(r, c), Vhi + vOff + ((size_t)r << 10) + (kc << 6) + c * 8);
        CP_COMMIT();
    };

    ldS(0);
    cpV(0);
    cpV(1);

    for (int kc = 0; kc < 16; ++kc) {
        const uint32_t pB = smBase + (uint32_t)(kc & 1) * 16384u;
#pragma unroll
        for (int i = 0; i < 4; ++i) {
            int idx = i * 512 + tid;
            int row = idx >> 4, f4 = idx & 15;
            float2 st = __ldg((const float2*)&stats[stOff + row]);
            float p0 = __expf(sreg[i].x - st.x) * st.y;
            float p1 = __expf(sreg[i].y - st.x) * st.y;
            float p2 = __expf(sreg[i].z - st.x) * st.y;
            float p3 = __expf(sreg[i].w - st.x) * st.y;
            __nv_bfloat162 ph0 = __halves2bfloat162(__float2bfloat16(p0),
                                                    __float2bfloat16(p1));
            __nv_bfloat162 ph1 = __halves2bfloat162(__float2bfloat16(p2),
                                                    __float2bfloat16(p3));
            uint32_t off = sw128(row, f4 >> 1) + (f4 & 1) * 8;
            asm volatile("st.shared.v2.b32 [%0], {%1, %2};" ::
                         "r"(pB + off), "r"(*(uint32_t*)&ph0), "r"(*(uint32_t*)&ph1)
                         : "memory");
        }
        if (kc + 1 < 16) ldS(kc + 1);

        CP_WAIT1();
        __syncthreads();
        if (kc + 2 < 16) cpV(kc + 2);
        else CP_COMMIT();

        const uint32_t phT = smBase + (uint32_t)(kc & 1) * 16384u;
        const uint32_t vhT = smBase + 32768u + (uint32_t)(kc % 3) * 8192u;

#pragma unroll
        for (int ks = 0; ks < 4; ++ks) {
            uint32_t ah[2][4];
            uint32_t bh[2][2];
#pragma unroll
            for (int mt = 0; mt < 2; ++mt) {
                int r = wr * 32 + mt * 16 + rA;
                ldsm4(ah[mt][0], ah[mt][1], ah[mt][2], ah[mt][3],
                      phT + sw128(r, ks * 2 + cAh));
            }
            {
                int r = wc * 16 + rBl;
                uint32_t x0, x1, x2, x3;
                ldsm4(x0, x1, x2, x3, vhT + sw128(r, ks * 2 + cBh));
                bh[0][0] = x0; bh[0][1] = x1; bh[1][0] = x2; bh[1][1] = x3;
            }
#pragma unroll
            for (int mt = 0; mt < 2; ++mt)
#pragma unroll
                for (int nt = 0; nt < 2; ++nt)
                    mma_bf16(acc[mt][nt], ah[mt], bh[nt]);
        }
    }

#pragma unroll
    for (int mt = 0; mt < 2; ++mt) {
        const int row = m0 + wr * 32 + mt * 16 + (lane >> 2);
#pragma unroll
        for (int nt = 0; nt < 2; ++nt) {
            const int col = h * 64 + wc * 16 + nt * 8 + (lane & 3) * 2;
            const size_t i0 = (((size_t)(b * 512 + row)) << 10) + col;
            const size_t i1 = i0 + (8 << 10);
            *(__nv_bfloat162*)(Chi + i0) =
                __halves2bfloat162(__float2bfloat16(acc[mt][nt][0]),
                                   __float2bfloat16(acc[mt][nt][1]));
            *(__nv_bfloat162*)(Chi + i1) =
                __halves2bfloat162(__float2bfloat16(acc[mt][nt][2]),
                                   __float2bfloat16(acc[mt][nt][3]));
        }
    }
}

// ---------------------------------------------------------------------------
// out = LayerNorm(query + attn_out) * gamma + beta.  One block per row.
// ---------------------------------------------------------------------------
__global__ void residual_ln(const float* __restrict__ q, const float* __restrict__ ao,
                            const float* __restrict__ gamma, const float* __restrict__ beta,
                            float* __restrict__ out)
{
    __shared__ float red[8];
    __shared__ float bcast;
    const long row = blockIdx.x;
    const int tid = threadIdx.x;

    float4 qa = *(const float4*)&q [row * DD + tid * 4];
    float4 aa = *(const float4*)&ao[row * DD + tid * 4];
    float x0 = qa.x + aa.x, x1 = qa.y + aa.y, x2 = qa.z + aa.z, x3 = qa.w + aa.w;

    float s = (x0 + x1) + (x2 + x3);
#pragma unroll
    for (int o = 16; o; o >>= 1) s += __shfl_xor_sync(0xffffffffu, s, o);
    if ((tid & 31) == 0) red[tid >> 5] = s;
    __syncthreads();
    if (tid < 8) {
        s = red[tid];
#pragma unroll
        for (int o = 4; o; o >>= 1) s += __shfl_xor_sync(0xffu, s, o);
        if (tid == 0) bcast = s;
    }
    __syncthreads();
    const float mu = bcast * (1.0f / DD);

    float d0 = x0 - mu, d1 = x1 - mu, d2 = x2 - mu, d3 = x3 - mu;
    float sq = (d0 * d0 + d1 * d1) + (d2 * d2 + d3 * d3);
#pragma unroll
    for (int o = 16; o; o >>= 1) sq += __shfl_xor_sync(0xffffffffu, sq, o);
    __syncthreads();
    if ((tid & 31) == 0) red[tid >> 5] = sq;
    __syncthreads();
    if (tid < 8) {
        sq = red[tid];
#pragma unroll
        for (int o = 4; o; o >>= 1) sq += __shfl_xor_sync(0xffu, sq, o);
        if (tid == 0) bcast = sq;
    }
    __syncthreads();
    const float rstd = rsqrtf(bcast * (1.0f / DD) + LN_EPS);

    float4 g = *(const float4*)&gamma[tid * 4];
    float4 be = *(const float4*)&beta[tid * 4];
    float4 o4;
    o4.x = d0 * rstd * g.x + be.x;
    o4.y = d1 * rstd * g.y + be.y;
    o4.z = d2 * rstd * g.z + be.z;
    o4.w = d3 * rstd * g.w + be.w;
    *(float4*)&out[row * DD + tid * 4] = o4;
}

// ---------------------------------------------------------------------------
extern "C" void kernel_launch(void* const* d_in, const int* in_sizes, int n_in,
                              void* d_out, int out_size)
{
    const float* query = (const float*)d_in[0];
    const float* key_  = (const float*)d_in[1];
    const float* value = (const float*)d_in[2];
    const float* in_w  = (const float*)d_in[3];
    const float* in_b  = (const float*)d_in[4];
    const float* out_w = (const float*)d_in[5];
    const float* out_b = (const float*)d_in[6];
    const float* gamma = (const float*)d_in[7];
    const float* beta  = (const float*)d_in[8];
    float* out = (float*)d_out;

    float *S, *AO;
    float2* ST;
    cudaGetSymbolAddress((void**)&S,  g_S);
    cudaGetSymbolAddress((void**)&AO, g_AO);
    cudaGetSymbolAddress((void**)&ST, g_stats);

    __nv_bfloat16 *qh, *ql, *kh, *kl, *vh, *vt, *wh, *wl, *woh;
    __nv_bfloat16 *qh2, *ql2, *kh2, *kl2, *ch;
    cudaGetSymbolAddress((void**)&qh,  g_qh);  cudaGetSymbolAddress((void**)&ql,  g_ql);
    cudaGetSymbolAddress((void**)&kh,  g_kh);  cudaGetSymbolAddress((void**)&kl,  g_kl);
    cudaGetSymbolAddress((void**)&vh,  g_vh);  cudaGetSymbolAddress((void**)&vt,  g_vt);
    cudaGetSymbolAddress((void**)&wh,  g_wh);  cudaGetSymbolAddress((void**)&wl,  g_wl);
    cudaGetSymbolAddress((void**)&woh, g_woh);
    cudaGetSymbolAddress((void**)&qh2, g_qh2); cudaGetSymbolAddress((void**)&ql2, g_ql2);
    cudaGetSymbolAddress((void**)&kh2, g_kh2); cudaGetSymbolAddress((void**)&kl2, g_kl2);
    cudaGetSymbolAddress((void**)&ch,  g_ch);

    const int SM_G = 3 * 32768;
    const int SM_X = 2 * 16384 + 3 * 8192;
    const int SM_S = 16 * 1024 * 4;   // softmax slabs: 64 KB
    cudaFuncSetAttribute((const void*)qkv_proj,
                         cudaFuncAttributeMaxDynamicSharedMemorySize, SM_G);
    cudaFuncSetAttribute((const void*)gemm64<1, 3>,
                         cudaFuncAttributeMaxDynamicSharedMemorySize, SM_G);
    cudaFuncSetAttribute((const void*)gemm64<16, 1>,
                         cudaFuncAttributeMaxDynamicSharedMemorySize, SM_G);
    cudaFuncSetAttribute((const void*)ctx_fused,
                         cudaFuncAttributeMaxDynamicSharedMemorySize, SM_X);
    cudaFuncSetAttribute((const void*)softmax_stats,
                         cudaFuncAttributeMaxDynamicSharedMemorySize, SM_S);

    const float qscale = 0.125f;

    // 1) split everything in one launch
    {
        const long total4 = (long)BB*LQ*DD/4 + 2L*BB*LKV*DD/4 + 3L*DD*DD/4 + (long)DD*DD/4;
        split_all<<<(unsigned)((total4 + 255) / 256), 256>>>(
            (const float4*)query, (const float4*)key_, (const float4*)value,
            (const float4*)in_w, (const float4*)out_w,
            (__nv_bfloat162*)qh, (__nv_bfloat162*)ql,
            (__nv_bfloat162*)kh, (__nv_bfloat162*)kl,
            (__nv_bfloat162*)vh,
            (__nv_bfloat162*)wh, (__nv_bfloat162*)wl,
            (__nv_bfloat162*)woh);
    }

    // 2) merged Q/K/V projection (+ fused V transpose -> vt)
    qkv_proj<<<dim3(8, 160), 128, SM_G>>>(
        qh, ql, kh, kl, vh, wh, wl, in_b,
        qh2, ql2, kh2, kl2, vt, qscale);

    // 3) scores (bf16x3) -> fp32 S
    gemm64<1, 3><<<dim3(8, 4, BB * HH_), 128, SM_G>>>(
        qh2, ql2, kh2, kl2, nullptr, S, 1.0f,
        (long)LQ * DD,  (long)HD,
        (long)LKV * DD, (long)HD,
        (long)HH_ * LQ * LKV, (long)LQ * LKV);

    // 4) softmax stats + head-mean (atomic-free slab reduction)
    softmax_stats<<<BB * LQ, 512, SM_S>>>(S, ST, out + (long)BB * LQ * DD);

    // 5) fused exp/normalize + ctx MMA (plain bf16) -> ch
    ctx_fused<<<dim3(1, 4, BB * HH_), 512, SM_X>>>(S, ST, vt, ch);

    // 6) out projection (bf16x1) -> fp32 AO
    gemm64<16, 1><<<dim3(8, 32, 1), 128, SM_G>>>(
        ch, nullptr, woh, nullptr, out_b, AO, 1.0f, 0,0, 0,0, 0,0);

    // 7) residual + LayerNorm
    residual_ln<<<BB * LQ, 256>>>(query, AO, gamma, beta, out);
}

// round 11
// speedup vs baseline: 1.7077x; 1.0825x over previous
#include <cuda_runtime.h>
#include <cuda_bf16.h>
#include <math.h>
#include <stdint.h>

// Problem constants
#define BB   8
#define LQ   512
#define LKV  1024
#define DD   1024
#define HH_  16
#define HD   64
#define LN_EPS 1e-5f

#define S_SCALE   4096.0f
#define S_INVSC   (1.0f / 4096.0f)

// ---------------------------------------------------------------------------
// Scratch (device globals: allocation-free per harness rules)
// ---------------------------------------------------------------------------
__device__ __align__(16) short g_S[(size_t)BB * HH_ * LQ * LKV]; // int16 scores (x4096)
__device__ float g_AO [BB * LQ  * DD];               // fp32 attn_out
__device__ float2 g_stats[(size_t)BB * HH_ * LQ];    // per-row {max, 1/sum}

// bf16 buffers
__device__ __align__(16) __nv_bfloat16 g_qh [BB * LQ  * DD], g_ql [BB * LQ  * DD];
__device__ __align__(16) __nv_bfloat16 g_kh [BB * LKV * DD], g_kl [BB * LKV * DD];
__device__ __align__(16) __nv_bfloat16 g_vh [BB * LKV * DD];   // value input hi
__device__ __align__(16) __nv_bfloat16 g_vt [BB * LKV * DD];   // Vt head-major bf16
__device__ __align__(16) __nv_bfloat16 g_wh [3 * DD * DD],   g_wl [3 * DD * DD];
__device__ __align__(16) __nv_bfloat16 g_woh[DD * DD];
__device__ __align__(16) __nv_bfloat16 g_qh2[BB * LQ  * DD], g_ql2[BB * LQ  * DD];
__device__ __align__(16) __nv_bfloat16 g_kh2[BB * LKV * DD], g_kl2[BB * LKV * DD];
__device__ __align__(16) __nv_bfloat16 g_ch [BB * LQ  * DD];

// ---------------------------------------------------------------------------
// Baseline-PTX tensor-core helpers (NO tcgen05 — compute_103 target!)
// ---------------------------------------------------------------------------
__device__ __forceinline__ uint32_t smem_u32(const void* p) {
    uint32_t a;
    asm("{ .reg .u64 t; cvta.to.shared.u64 t, %1; cvt.u32.u64 %0, t; }" : "=r"(a) : "l"(p));
    return a;
}
__device__ __forceinline__ void ldsm4(uint32_t& r0, uint32_t& r1, uint32_t& r2,
                                      uint32_t& r3, uint32_t a) {
    asm volatile("ldmatrix.sync.aligned.m8n8.x4.shared.b16 {%0,%1,%2,%3}, [%4];"
                 : "=r"(r0), "=r"(r1), "=r"(r2), "=r"(r3) : "r"(a));
}
__device__ __forceinline__ void mma_bf16(float* d, const uint32_t* a, const uint32_t* b) {
    asm volatile("mma.sync.aligned.m16n8k16.row.col.f32.bf16.bf16.f32 "
                 "{%0,%1,%2,%3},{%4,%5,%6,%7},{%8,%9},{%0,%1,%2,%3};"
                 : "+f"(d[0]), "+f"(d[1]), "+f"(d[2]), "+f"(d[3])
                 : "r"(a[0]), "r"(a[1]), "r"(a[2]), "r"(a[3]), "r"(b[0]), "r"(b[1]));
}
#define CP_ASYNC16(s, g) \
    asm volatile("cp.async.cg.shared.global [%0], [%1], 16;" :: "r"(s), "l"(g))
#define CP_COMMIT() asm volatile("cp.async.commit_group;" ::: "memory")
#define CP_WAIT1()  asm volatile("cp.async.wait_group 1;"  ::: "memory")

// 128B-row XOR swizzle: 16B chunk c (0..7), row r
__device__ __forceinline__ uint32_t sw128(int r, int c) {
    return (uint32_t)(r * 128 + ((c ^ (r & 7)) << 4));
}
__device__ __forceinline__ void bsplit(float v, __nv_bfloat16& h, __nv_bfloat16& l) {
    h = __float2bfloat16(v);
    l = __float2bfloat16(v - __bfloat162float(h));
}
__device__ __forceinline__ short squant(float v) {
    v = fminf(fmaxf(v, -32700.f), 32700.f);
    return (short)__float2int_rn(v);
}

// ---------------------------------------------------------------------------
// One launch: split all inputs/weights (hi/lo or hi-only per segment)
// ---------------------------------------------------------------------------
__device__ __forceinline__ void seg_split2(float4 v, __nv_bfloat162* hi,
                                           __nv_bfloat162* lo, long i) {
    __nv_bfloat16 h0, h1, h2, h3, l0, l1, l2, l3;
    bsplit(v.x, h0, l0); bsplit(v.y, h1, l1);
    bsplit(v.z, h2, l2); bsplit(v.w, h3, l3);
    hi[i * 2 + 0] = __halves2bfloat162(h0, h1);
    hi[i * 2 + 1] = __halves2bfloat162(h2, h3);
    lo[i * 2 + 0] = __halves2bfloat162(l0, l1);
    lo[i * 2 + 1] = __halves2bfloat162(l2, l3);
}
__device__ __forceinline__ void seg_split1(float4 v, __nv_bfloat162* hi, long i) {
    hi[i * 2 + 0] = __halves2bfloat162(__float2bfloat16(v.x), __float2bfloat16(v.y));
    hi[i * 2 + 1] = __halves2bfloat162(__float2bfloat16(v.z), __float2bfloat16(v.w));
}

__global__ void split_all(const float4* __restrict__ q, const float4* __restrict__ k,
                          const float4* __restrict__ v, const float4* __restrict__ w,
                          const float4* __restrict__ wo,
                          __nv_bfloat162* qh, __nv_bfloat162* ql,
                          __nv_bfloat162* kh, __nv_bfloat162* kl,
                          __nv_bfloat162* vh,
                          __nv_bfloat162* wh, __nv_bfloat162* wl,
                          __nv_bfloat162* woh)
{
    const long N1 = (long)BB * LQ * DD / 4;
    const long N2 = N1 + (long)BB * LKV * DD / 4;
    const long N3 = N2 + (long)BB * LKV * DD / 4;
    const long N4 = N3 + 3L * DD * DD / 4;
    const long N5 = N4 + (long)DD * DD / 4;
    long i = (long)blockIdx.x * blockDim.x + threadIdx.x;
    if (i < N1)      seg_split2(q[i], qh, ql, i);
    else if (i < N2) { i -= N1; seg_split2(k[i], kh, kl, i); }
    else if (i < N3) { i -= N2; seg_split1(v[i], vh, i); }
    else if (i < N4) { i -= N3; seg_split2(w[i], wh, wl, i); }
    else if (i < N5) { i -= N4; seg_split1(wo[i], woh, i); }
}

// ---------------------------------------------------------------------------
// Merged Q/K/V projection. Grid (8, 160): y<32 Q, y<96 K, else V.
// ---------------------------------------------------------------------------
__global__ void __launch_bounds__(128, 2) qkv_proj(
    const __nv_bfloat16* __restrict__ qhp, const __nv_bfloat16* __restrict__ qlp,
    const __nv_bfloat16* __restrict__ khp, const __nv_bfloat16* __restrict__ klp,
    const __nv_bfloat16* __restrict__ vhp,
    const __nv_bfloat16* __restrict__ whp, const __nv_bfloat16* __restrict__ wlp,
    const float* __restrict__ in_b,
    __nv_bfloat16* __restrict__ qh2, __nv_bfloat16* __restrict__ ql2,
    __nv_bfloat16* __restrict__ kh2, __nv_bfloat16* __restrict__ kl2,
    __nv_bfloat16* __restrict__ vt, float qscale)
{
    extern __shared__ __align__(16) char dynsm[];
    const uint32_t smBase = smem_u32(dynsm);

    const int tid  = threadIdx.x;
    const int lane = tid & 31;
    const int wid  = tid >> 5;
    const int wr   = wid >> 1;
    const int wc   = wid & 1;
    const int y    = blockIdx.y;
    const int n0   = blockIdx.x * 128;

    int region, m0, NIT;
    float scale = 1.0f;
    const __nv_bfloat16 *Ahi, *Alo, *Bhi, *Blo;
    const float* bias;
    if (y < 32) {
        region = 0; m0 = y * 128; NIT = 48; scale = qscale;
        Ahi = qhp; Alo = qlp; Bhi = whp; Blo = wlp; bias = in_b;
    } else if (y < 96) {
        region = 1; m0 = (y - 32) * 128; NIT = 48;
        Ahi = khp; Alo = klp;
        Bhi = whp + (size_t)DD * DD; Blo = wlp + (size_t)DD * DD;
        bias = in_b + DD;
    } else {
        region = 2; m0 = (y - 96) * 128; NIT = 16;
        Ahi = vhp; Alo = vhp;
        Bhi = whp + 2ul * DD * DD; Blo = Bhi;
        bias = in_b + 2 * DD;
    }

    const int rA  = lane & 15;
    const int cAh = lane >> 4;
    const int rBl = (lane & 7) + ((lane & 16) >> 1);
    const int cBh = (lane >> 3) & 1;

    float acc[4][8][4];
#pragma unroll
    for (int mt = 0; mt < 4; ++mt)
#pragma unroll
        for (int nt = 0; nt < 8; ++nt)
#pragma unroll
            for (int j = 0; j < 4; ++j) acc[mt][nt][j] = 0.f;

    auto prefetch = [&](int it, int stage) {
        const int part = it >> 4;
        const int ko   = (it & 15) << 6;
        const __nv_bfloat16* Ap = (part == 2) ? Alo : Ahi;
        const __nv_bfloat16* Bp = (part == 1) ? Blo : Bhi;
        const uint32_t as = smBase + (uint32_t)stage * 32768u;
        const uint32_t bs = as + 16384u;
#pragma unroll
        for (int i = 0; i < 8; ++i) {
            int q = i * 128 + tid;
            int r = q >> 3, c = q & 7;
            CP_ASYNC16(as + sw128(r, c),
                       Ap + (((size_t)(m0 + r)) << 10) + ko + c * 8);
            CP_ASYNC16(bs + sw128(r, c),
                       Bp + (((size_t)(n0 + r)) << 10) + ko + c * 8);
        }
        CP_COMMIT();
    };

    prefetch(0, 0);
    prefetch(1, 1);

    for (int it = 0; it < NIT; ++it) {
        CP_WAIT1();
        __syncthreads();
        if (it + 2 < NIT) prefetch(it + 2, (it + 2) % 3);
        else CP_COMMIT();

        const uint32_t aT = smBase + (uint32_t)(it % 3) * 32768u;
        const uint32_t bT = aT + 16384u;

#pragma unroll
        for (int ks = 0; ks < 4; ++ks) {
            uint32_t af[4][4];
            uint32_t bf[8][2];
#pragma unroll
            for (int mt = 0; mt < 4; ++mt) {
                int r = wr * 64 + mt * 16 + rA;
                ldsm4(af[mt][0], af[mt][1], af[mt][2], af[mt][3],
                      aT + sw128(r, ks * 2 + cAh));
            }
#pragma unroll
            for (int tp = 0; tp < 4; ++tp) {
                int r = wc * 64 + tp * 16 + rBl;
                uint32_t x0, x1, x2, x3;
                ldsm4(x0, x1, x2, x3, bT + sw128(r, ks * 2 + cBh));
                bf[tp * 2][0] = x0;     bf[tp * 2][1] = x1;
                bf[tp * 2 + 1][0] = x2; bf[tp * 2 + 1][1] = x3;
            }
#pragma unroll
            for (int mt = 0; mt < 4; ++mt)
#pragma unroll
                for (int nt = 0; nt < 8; ++nt)
                    mma_bf16(acc[mt][nt], af[mt], bf[nt]);
        }
    }
    __syncthreads();

    if (region < 2) {
        __nv_bfloat16* Chi = region ? kh2 : qh2;
        __nv_bfloat16* Clo = region ? kl2 : ql2;
#pragma unroll
        for (int mt = 0; mt < 4; ++mt) {
            const int row = m0 + wr * 64 + mt * 16 + (lane >> 2);
#pragma unroll
            for (int nt = 0; nt < 8; ++nt) {
                const int col = n0 + wc * 64 + nt * 8 + (lane & 3) * 2;
                const float b0 = bias[col], b1 = bias[col + 1];
                const float v0 = (acc[mt][nt][0] + b0) * scale;
                const float v1 = (acc[mt][nt][1] + b1) * scale;
                const float v2 = (acc[mt][nt][2] + b0) * scale;
                const float v3 = (acc[mt][nt][3] + b1) * scale;
                const size_t i0 = ((size_t)row << 10) + col;
                const size_t i1 = i0 + (8 << 10);
                __nv_bfloat16 h0, h1, h2, h3, l0, l1, l2, l3;
                bsplit(v0, h0, l0); bsplit(v1, h1, l1);
                bsplit(v2, h2, l2); bsplit(v3, h3, l3);
                *(__nv_bfloat162*)(Chi + i0) = __halves2bfloat162(h0, h1);
                *(__nv_bfloat162*)(Clo + i0) = __halves2bfloat162(l0, l1);
                *(__nv_bfloat162*)(Chi + i1) = __halves2bfloat162(h2, h3);
                *(__nv_bfloat162*)(Clo + i1) = __halves2bfloat162(l2, l3);
            }
        }
    } else {
        // V region: bias + transpose through smem -> head-major Vt bf16.
        float* ts = (float*)dynsm;   // 128 x 128 fp32, stride 130
#pragma unroll
        for (int mt = 0; mt < 4; ++mt) {
            const int rl = wr * 64 + mt * 16 + (lane >> 2);
#pragma unroll
            for (int nt = 0; nt < 8; ++nt) {
                const int cl = wc * 64 + nt * 8 + (lane & 3) * 2;
                const float b0 = bias[n0 + cl], b1 = bias[n0 + cl + 1];
                ts[rl * 130 + cl]           = acc[mt][nt][0] + b0;
                ts[rl * 130 + cl + 1]       = acc[mt][nt][1] + b1;
                ts[(rl + 8) * 130 + cl]     = acc[mt][nt][2] + b0;
                ts[(rl + 8) * 130 + cl + 1] = acc[mt][nt][3] + b1;
            }
        }
        __syncthreads();
        const int bb = m0 >> 10;
        const int k0 = m0 & 1023;
        __nv_bfloat16* dst = vt + (((size_t)(bb * 1024 + n0 + tid)) << 10) + k0;
#pragma unroll
        for (int k = 0; k < 128; k += 8) {
            __nv_bfloat162 p0 = __halves2bfloat162(
                __float2bfloat16(ts[(k + 0) * 130 + tid]),
                __float2bfloat16(ts[(k + 1) * 130 + tid]));
            __nv_bfloat162 p1 = __halves2bfloat162(
                __float2bfloat16(ts[(k + 2) * 130 + tid]),
                __float2bfloat16(ts[(k + 3) * 130 + tid]));
            __nv_bfloat162 p2 = __halves2bfloat162(
                __float2bfloat16(ts[(k + 4) * 130 + tid]),
                __float2bfloat16(ts[(k + 5) * 130 + tid]));
            __nv_bfloat162 p3 = __halves2bfloat162(
                __float2bfloat16(ts[(k + 6) * 130 + tid]),
                __float2bfloat16(ts[(k + 7) * 130 + tid]));
            uint4 pk;
            pk.x = *(uint32_t*)&p0; pk.y = *(uint32_t*)&p1;
            pk.z = *(uint32_t*)&p2; pk.w = *(uint32_t*)&p3;
            *(uint4*)(dst + k) = pk;
        }
    }
}

// ---------------------------------------------------------------------------
// HMMA GEMM template. I16OUT=true: quantize (acc+bias)*scale to int16 (scores,
// scale = S_SCALE). I16OUT=false: fp32 output (out-proj).
// ---------------------------------------------------------------------------
template<int KCH, int PARTS, bool I16OUT>
__global__ void __launch_bounds__(128, 2) gemm64(
    const __nv_bfloat16* __restrict__ Ahi, const __nv_bfloat16* __restrict__ Alo,
    const __nv_bfloat16* __restrict__ Bhi, const __nv_bfloat16* __restrict__ Blo,
    const float* __restrict__ bias, float* __restrict__ Cf,
    short* __restrict__ Cs, float scale,
    long sA0, long sA1, long sB0, long sB1, long sC0, long sC1)
{
    extern __shared__ __align__(16) char dynsm[];
    const uint32_t smBase = smem_u32(dynsm);

    const int tid  = threadIdx.x;
    const int lane = tid & 31;
    const int wid  = tid >> 5;
    const int wr   = wid >> 1;
    const int wc   = wid & 1;
    const int z    = blockIdx.z;
    const int m0   = blockIdx.y * 128;
    const int n0   = blockIdx.x * 128;
    const size_t aOff = (size_t)(z >> 4) * sA0 + (size_t)(z & 15) * sA1;
    const size_t bOff = (size_t)(z >> 4) * sB0 + (size_t)(z & 15) * sB1;
    const size_t cOff = (size_t)(z >> 4) * sC0 + (size_t)(z & 15) * sC1;

    const int rA  = lane & 15;
    const int cAh = lane >> 4;
    const int rBl = (lane & 7) + ((lane & 16) >> 1);
    const int cBh = (lane >> 3) & 1;

    float acc[4][8][4];
#pragma unroll
    for (int mt = 0; mt < 4; ++mt)
#pragma unroll
        for (int nt = 0; nt < 8; ++nt)
#pragma unroll
            for (int j = 0; j < 4; ++j) acc[mt][nt][j] = 0.f;

    auto prefetch = [&](int it, int stage) {
        const int part = it / KCH;
        const int ko   = (it % KCH) << 6;
        const __nv_bfloat16* Ap = (PARTS == 3 && part == 2) ? Alo : Ahi;
        const __nv_bfloat16* Bp = (PARTS == 3 && part == 1) ? Blo : Bhi;
        const uint32_t as = smBase + (uint32_t)stage * 32768u;
        const uint32_t bs = as + 16384u;
#pragma unroll
        for (int i = 0; i < 8; ++i) {
            int q = i * 128 + tid;
            int r = q >> 3, c = q & 7;
            CP_ASYNC16(as + sw128(r, c),
                       Ap + aOff + (((size_t)(m0 + r)) << 10) + ko + c * 8);
            CP_ASYNC16(bs + sw128(r, c),
                       Bp + bOff + (((size_t)(n0 + r)) << 10) + ko + c * 8);
        }
        CP_COMMIT();
    };

    const int NIT = PARTS * KCH;
    prefetch(0, 0);
    if (NIT > 1) prefetch(1, 1);

    for (int it = 0; it < NIT; ++it) {
        CP_WAIT1();
        __syncthreads();
        if (it + 2 < NIT) prefetch(it + 2, (it + 2) % 3);
        else CP_COMMIT();

        const uint32_t aT = smBase + (uint32_t)(it % 3) * 32768u;
        const uint32_t bT = aT + 16384u;

#pragma unroll
        for (int ks = 0; ks < 4; ++ks) {
            uint32_t af[4][4];
            uint32_t bf[8][2];
#pragma unroll
            for (int mt = 0; mt < 4; ++mt) {
                int r = wr * 64 + mt * 16 + rA;
                ldsm4(af[mt][0], af[mt][1], af[mt][2], af[mt][3],
                      aT + sw128(r, ks * 2 + cAh));
            }
#pragma unroll
            for (int tp = 0; tp < 4; ++tp) {
                int r = wc * 64 + tp * 16 + rBl;
                uint32_t x0, x1, x2, x3;
                ldsm4(x0, x1, x2, x3, bT + sw128(r, ks * 2 + cBh));
                bf[tp * 2][0] = x0;     bf[tp * 2][1] = x1;
                bf[tp * 2 + 1][0] = x2; bf[tp * 2 + 1][1] = x3;
            }
#pragma unroll
            for (int mt = 0; mt < 4; ++mt)
#pragma unroll
                for (int nt = 0; nt < 8; ++nt)
                    mma_bf16(acc[mt][nt], af[mt], bf[nt]);
        }
    }
    __syncthreads();

#pragma unroll
    for (int mt = 0; mt < 4; ++mt) {
        const int row = m0 + wr * 64 + mt * 16 + (lane >> 2);
#pragma unroll
        for (int nt = 0; nt < 8; ++nt) {
            const int col = n0 + wc * 64 + nt * 8 + (lane & 3) * 2;
            const float b0 = bias ? bias[col]     : 0.f;
            const float b1 = bias ? bias[col + 1] : 0.f;
            const float v0 = (acc[mt][nt][0] + b0) * scale;
            const float v1 = (acc[mt][nt][1] + b1) * scale;
            const float v2 = (acc[mt][nt][2] + b0) * scale;
            const float v3 = (acc[mt][nt][3] + b1) * scale;
            const size_t i0 = cOff + ((size_t)row << 10) + col;
            const size_t i1 = i0 + (8 << 10);
            if (I16OUT) {
                *(short2*)(Cs + i0) = make_short2(squant(v0), squant(v1));
                *(short2*)(Cs + i1) = make_short2(squant(v2), squant(v3));
            } else {
                Cf[i0] = v0; Cf[i0 + 1] = v1;
                Cf[i1] = v2; Cf[i1 + 1] = v3;
            }
        }
    }
}

// ---------------------------------------------------------------------------
// Softmax stats + head-mean from int16 S. One block (512 thr = 16 warps) per
// (b,q); warp w owns head w's row. Private per-warp slabs, no atomics.
// Dynamic smem: 64 KB.
// ---------------------------------------------------------------------------
__global__ void __launch_bounds__(512) softmax_stats(const short* __restrict__ S,
                                                     float2* __restrict__ stats,
                                                     float* __restrict__ mean_out)
{
    extern __shared__ __align__(16) float slab[];   // [16][1024]
    const int bq = blockIdx.x;
    const int b = bq >> 9, q = bq & 511;
    const int tid = threadIdx.x;
    const int lane = tid & 31, w = tid >> 5;

    const short* Sp = S + (((size_t)(b * 16 + w) * 512 + q) << 10);
    int4 raw[4];
#pragma unroll
    for (int i = 0; i < 4; ++i)
        raw[i] = __ldg((const int4*)(Sp + (i * 32 + lane) * 8));

    float v[32];
#pragma unroll
    for (int i = 0; i < 4; ++i) {
        const uint32_t* u = (const uint32_t*)&raw[i];
#pragma unroll
        for (int j = 0; j < 4; ++j) {
            v[i * 8 + j * 2 + 0] = (float)((short)(u[j] & 0xFFFF)) * S_INVSC;
            v[i * 8 + j * 2 + 1] = (float)((short)(u[j] >> 16))    * S_INVSC;
        }
    }

    float m = -1e30f;
#pragma unroll
    for (int k = 0; k < 32; ++k) m = fmaxf(m, v[k]);
#pragma unroll
    for (int o = 16; o; o >>= 1) m = fmaxf(m, __shfl_xor_sync(0xffffffffu, m, o));

    float s = 0.f;
#pragma unroll
    for (int k = 0; k < 32; ++k) { v[k] = __expf(v[k] - m); s += v[k]; }
#pragma unroll
    for (int o = 16; o; o >>= 1) s += __shfl_xor_sync(0xffffffffu, s, o);
    const float inv = 1.0f / s;

    if (lane == 0)
        stats[(size_t)(b * 16 + w) * 512 + q] = make_float2(m, inv);

    // store normalized row into this warp's private slab
    float4* wslab = (float4*)(slab + w * 1024);
#pragma unroll
    for (int i = 0; i < 4; ++i)
#pragma unroll
        for (int jj = 0; jj < 2; ++jj) {
            float4 p;
            p.x = v[i * 8 + jj * 4 + 0] * inv;
            p.y = v[i * 8 + jj * 4 + 1] * inv;
            p.z = v[i * 8 + jj * 4 + 2] * inv;
            p.w = v[i * 8 + jj * 4 + 3] * inv;
            wslab[(i * 32 + lane) * 2 + jj] = p;
        }
    __syncthreads();

    float s0 = 0.f, s1 = 0.f;
#pragma unroll
    for (int h = 0; h < HH_; ++h) {
        s0 += slab[h * 1024 + tid];
        s1 += slab[h * 1024 + tid + 512];
    }
    const float inv16 = 1.0f / HH_;
    float* mo = mean_out + (((size_t)bq) << 10);
    mo[tid]       = s0 * inv16;
    mo[tid + 512] = s1 * inv16;
}

// ---------------------------------------------------------------------------
// Fused ctx (plain bf16): per z=(b,h), q-tile 128: reads int16 S, exp*inv
// in-flight, P hi in SMEM, MMA vs Vt. 512 thr (16 warps, 32x16 warp tiles).
// ---------------------------------------------------------------------------
__global__ void __launch_bounds__(512) ctx_fused(
    const short* __restrict__ S, const float2* __restrict__ stats,
    const __nv_bfloat16* __restrict__ Vhi,
    __nv_bfloat16* __restrict__ Chi)
{
    extern __shared__ __align__(16) char dynsm[];
    const uint32_t smBase = smem_u32(dynsm);

    const int tid  = threadIdx.x;
    const int lane = tid & 31;
    const int wid  = tid >> 5;
    const int wr   = wid >> 2;
    const int wc   = wid & 3;
    const int z    = blockIdx.z, b = z >> 4, h = z & 15;
    const int m0   = blockIdx.y * 128;
    const size_t sOff  = ((size_t)z * 512 + m0) << 10;
    const size_t vOff  = ((size_t)z * 64) << 10;
    const int    stOff = z * 512 + m0;

    const int rA  = lane & 15;
    const int cAh = lane >> 4;
    const int rBl = (lane & 7) + ((lane & 16) >> 1);
    const int cBh = (lane >> 3) & 1;

    float acc[2][2][4];
#pragma unroll
    for (int mt = 0; mt < 2; ++mt)
#pragma unroll
        for (int nt = 0; nt < 2; ++nt)
#pragma unroll
            for (int j = 0; j < 4; ++j) acc[mt][nt][j] = 0.f;

    int4 sreg[2];
    auto ldS = [&](int kc) {
#pragma unroll
        for (int i = 0; i < 2; ++i) {
            int idx = i * 512 + tid;
            int row = idx >> 3, c8 = idx & 7;
            sreg[i] = __ldg((const int4*)(S + sOff + ((size_t)row << 10) +
                                          (kc << 6) + c8 * 8));
        }
    };
    auto cpV = [&](int kc) {
        const uint32_t vs = smBase + 32768u + (uint32_t)(kc % 3) * 8192u;
        int r = tid >> 3, c = tid & 7;
        CP_ASYNC16(vs + sw128(r, c), Vhi + vOff + ((size_t)r << 10) + (kc << 6) + c * 8);
        CP_COMMIT();
    };

    ldS(0);
    cpV(0);
    cpV(1);

    for (int kc = 0; kc < 16; ++kc) {
        const uint32_t pB = smBase + (uint32_t)(kc & 1) * 16384u;
#pragma unroll
        for (int i = 0; i < 2; ++i) {
            int idx = i * 512 + tid;
            int row = idx >> 3, c8 = idx & 7;
            float2 st = __ldg((const float2*)&stats[stOff + row]);
            const uint32_t* u = (const uint32_t*)&sreg[i];
            uint32_t packed[4];
#pragma unroll
            for (int j = 0; j < 4; ++j) {
                float a = __expf((float)((short)(u[j] & 0xFFFF)) * S_INVSC - st.x) * st.y;
                float c = __expf((float)((short)(u[j] >> 16))    * S_INVSC - st.x) * st.y;
                __nv_bfloat162 pp = __halves2bfloat162(__float2bfloat16(a),
                                                       __float2bfloat16(c));
                packed[j] = *(uint32_t*)&pp;
            }
            uint32_t off = sw128(row, c8);
            asm volatile("st.shared.v4.b32 [%0], {%1, %2, %3, %4};" ::
                         "r"(pB + off), "r"(packed[0]), "r"(packed[1]),
                         "r"(packed[2]), "r"(packed[3]) : "memory");
        }
        if (kc + 1 < 16) ldS(kc + 1);

        CP_WAIT1();
        __syncthreads();
        if (kc + 2 < 16) cpV(kc + 2);
        else CP_COMMIT();

        const uint32_t phT = smBase + (uint32_t)(kc & 1) * 16384u;
        const uint32_t vhT = smBase + 32768u + (uint32_t)(kc % 3) * 8192u;

#pragma unroll
        for (int ks = 0; ks < 4; ++ks) {
            uint32_t ah[2][4];
            uint32_t bh[2][2];
#pragma unroll
            for (int mt = 0; mt < 2; ++mt) {
                int r = wr * 32 + mt * 16 + rA;
                ldsm4(ah[mt][0], ah[mt][1], ah[mt][2], ah[mt][3],
                      phT + sw128(r, ks * 2 + cAh));
            }
            {
                int r = wc * 16 + rBl;
                uint32_t x0, x1, x2, x3;
                ldsm4(x0, x1, x2, x3, vhT + sw128(r, ks * 2 + cBh));
                bh[0][0] = x0; bh[0][1] = x1; bh[1][0] = x2; bh[1][1] = x3;
            }
#pragma unroll
            for (int mt = 0; mt < 2; ++mt)
#pragma unroll
                for (int nt = 0; nt < 2; ++nt)
                    mma_bf16(acc[mt][nt], ah[mt], bh[nt]);
        }
    }

#pragma unroll
    for (int mt = 0; mt < 2; ++mt) {
        const int row = m0 + wr * 32 + mt * 16 + (lane >> 2);
#pragma unroll
        for (int nt = 0; nt < 2; ++nt) {
            const int col = h * 64 + wc * 16 + nt * 8 + (lane & 3) * 2;
            const size_t i0 = (((size_t)(b * 512 + row)) << 10) + col;
            const size_t i1 = i0 + (8 << 10);
            *(__nv_bfloat162*)(Chi + i0) =
                __halves2bfloat162(__float2bfloat16(acc[mt][nt][0]),
                                   __float2bfloat16(acc[mt][nt][1]));
            *(__nv_bfloat162*)(Chi + i1) =
                __halves2bfloat162(__float2bfloat16(acc[mt][nt][2]),
                                   __float2bfloat16(acc[mt][nt][3]));
        }
    }
}

// ---------------------------------------------------------------------------
// out = LayerNorm(query + attn_out) * gamma + beta.  One block per row.
// ---------------------------------------------------------------------------
__global__ void residual_ln(const float* __restrict__ q, const float* __restrict__ ao,
                            const float* __restrict__ gamma, const float* __restrict__ beta,
                            float* __restrict__ out)
{
    __shared__ float red[8];
    __shared__ float bcast;
    const long row = blockIdx.x;
    const int tid = threadIdx.x;

    float4 qa = *(const float4*)&q [row * DD + tid * 4];
    float4 aa = *(const float4*)&ao[row * DD + tid * 4];
    float x0 = qa.x + aa.x, x1 = qa.y + aa.y, x2 = qa.z + aa.z, x3 = qa.w + aa.w;

    float s = (x0 + x1) + (x2 + x3);
#pragma unroll
    for (int o = 16; o; o >>= 1) s += __shfl_xor_sync(0xffffffffu, s, o);
    if ((tid & 31) == 0) red[tid >> 5] = s;
    __syncthreads();
    if (tid < 8) {
        s = red[tid];
#pragma unroll
        for (int o = 4; o; o >>= 1) s += __shfl_xor_sync(0xffu, s, o);
        if (tid == 0) bcast = s;
    }
    __syncthreads();
    const float mu = bcast * (1.0f / DD);

    float d0 = x0 - mu, d1 = x1 - mu, d2 = x2 - mu, d3 = x3 - mu;
    float sq = (d0 * d0 + d1 * d1) + (d2 * d2 + d3 * d3);
#pragma unroll
    for (int o = 16; o; o >>= 1) sq += __shfl_xor_sync(0xffffffffu, sq, o);
    __syncthreads();
    if ((tid & 31) == 0) red[tid >> 5] = sq;
    __syncthreads();
    if (tid < 8) {
        sq = red[tid];
#pragma unroll
        for (int o = 4; o; o >>= 1) sq += __shfl_xor_sync(0xffu, sq, o);
        if (tid == 0) bcast = sq;
    }
    __syncthreads();
    const float rstd = rsqrtf(bcast * (1.0f / DD) + LN_EPS);

    float4 g = *(const float4*)&gamma[tid * 4];
    float4 be = *(const float4*)&beta[tid * 4];
    float4 o4;
    o4.x = d0 * rstd * g.x + be.x;
    o4.y = d1 * rstd * g.y + be.y;
    o4.z = d2 * rstd * g.z + be.z;
    o4.w = d3 * rstd * g.w + be.w;
    *(float4*)&out[row * DD + tid * 4] = o4;
}

// ---------------------------------------------------------------------------
extern "C" void kernel_launch(void* const* d_in, const int* in_sizes, int n_in,
                              void* d_out, int out_size)
{
    const float* query = (const float*)d_in[0];
    const float* key_  = (const float*)d_in[1];
    const float* value = (const float*)d_in[2];
    const float* in_w  = (const float*)d_in[3];
    const float* in_b  = (const float*)d_in[4];
    const float* out_w = (const float*)d_in[5];
    const float* out_b = (const float*)d_in[6];
    const float* gamma = (const float*)d_in[7];
    const float* beta  = (const float*)d_in[8];
    float* out = (float*)d_out;

    short* Si;
    float* AO;
    float2* ST;
    cudaGetSymbolAddress((void**)&Si, g_S);
    cudaGetSymbolAddress((void**)&AO, g_AO);
    cudaGetSymbolAddress((void**)&ST, g_stats);

    __nv_bfloat16 *qh, *ql, *kh, *kl, *vh, *vt, *wh, *wl, *woh;
    __nv_bfloat16 *qh2, *ql2, *kh2, *kl2, *ch;
    cudaGetSymbolAddress((void**)&qh,  g_qh);  cudaGetSymbolAddress((void**)&ql,  g_ql);
    cudaGetSymbolAddress((void**)&kh,  g_kh);  cudaGetSymbolAddress((void**)&kl,  g_kl);
    cudaGetSymbolAddress((void**)&vh,  g_vh);  cudaGetSymbolAddress((void**)&vt,  g_vt);
    cudaGetSymbolAddress((void**)&wh,  g_wh);  cudaGetSymbolAddress((void**)&wl,  g_wl);
    cudaGetSymbolAddress((void**)&woh, g_woh);
    cudaGetSymbolAddress((void**)&qh2, g_qh2); cudaGetSymbolAddress((void**)&ql2, g_ql2);
    cudaGetSymbolAddress((void**)&kh2, g_kh2); cudaGetSymbolAddress((void**)&kl2, g_kl2);
    cudaGetSymbolAddress((void**)&ch,  g_ch);

    const int SM_G = 3 * 32768;
    const int SM_X = 2 * 16384 + 3 * 8192;
    const int SM_S = 16 * 1024 * 4;   // softmax slabs: 64 KB
    cudaFuncSetAttribute((const void*)qkv_proj,
                         cudaFuncAttributeMaxDynamicSharedMemorySize, SM_G);
    cudaFuncSetAttribute((const void*)gemm64<1, 3, true>,
                         cudaFuncAttributeMaxDynamicSharedMemorySize, SM_G);
    cudaFuncSetAttribute((const void*)gemm64<16, 1, false>,
                         cudaFuncAttributeMaxDynamicSharedMemorySize, SM_G);
    cudaFuncSetAttribute((const void*)ctx_fused,
                         cudaFuncAttributeMaxDynamicSharedMemorySize, SM_X);
    cudaFuncSetAttribute((const void*)softmax_stats,
                         cudaFuncAttributeMaxDynamicSharedMemorySize, SM_S);

    const float qscale = 0.125f;

    // 1) split everything in one launch
    {
        const long total4 = (long)BB*LQ*DD/4 + 2L*BB*LKV*DD/4 + 3L*DD*DD/4 + (long)DD*DD/4;
        split_all<<<(unsigned)((total4 + 255) / 256), 256>>>(
            (const float4*)query, (const float4*)key_, (const float4*)value,
            (const float4*)in_w, (const float4*)out_w,
            (__nv_bfloat162*)qh, (__nv_bfloat162*)ql,
            (__nv_bfloat162*)kh, (__nv_bfloat162*)kl,
            (__nv_bfloat162*)vh,
            (__nv_bfloat162*)wh, (__nv_bfloat162*)wl,
            (__nv_bfloat162*)woh);
    }

    // 2) merged Q/K/V projection (+ fused V transpose -> vt)
    qkv_proj<<<dim3(8, 160), 128, SM_G>>>(
        qh, ql, kh, kl, vh, wh, wl, in_b,
        qh2, ql2, kh2, kl2, vt, qscale);

    // 3) scores (bf16x3) -> int16 S (scaled by 4096)
    gemm64<1, 3, true><<<dim3(8, 4, BB * HH_), 128, SM_G>>>(
        qh2, ql2, kh2, kl2, nullptr, nullptr, Si, S_SCALE,
        (long)LQ * DD,  (long)HD,
        (long)LKV * DD, (long)HD,
        (long)HH_ * LQ * LKV, (long)LQ * LKV);

    // 4) softmax stats + head-mean (int16 S, slab reduction)
    softmax_stats<<<BB * LQ, 512, SM_S>>>(Si, ST, out + (long)BB * LQ * DD);

    // 5) fused exp/normalize + ctx MMA (int16 S in, bf16 ch out)
    ctx_fused<<<dim3(1, 4, BB * HH_), 512, SM_X>>>(Si, ST, vt, ch);

    // 6) out projection (bf16x1) -> fp32 AO
    gemm64<16, 1, false><<<dim3(8, 32, 1), 128, SM_G>>>(
        ch, nullptr, woh, nullptr, out_b, AO, nullptr, 1.0f, 0,0, 0,0, 0,0);

    // 7) residual + LayerNorm
    residual_ln<<<BB * LQ, 256>>>(query, AO, gamma, beta, out);
}

// round 12
// speedup vs baseline: 1.7330x; 1.0148x over previous
#include <cuda_runtime.h>
#include <cuda_bf16.h>
#include <math.h>
#include <stdint.h>

// Problem constants
#define BB   8
#define LQ   512
#define LKV  1024
#define DD   1024
#define HH_  16
#define HD   64
#define LN_EPS 1e-5f

#define S_SCALE   4096.0f
#define S_INVSC   (1.0f / 4096.0f)

// ---------------------------------------------------------------------------
// Scratch (device globals: allocation-free per harness rules)
// ---------------------------------------------------------------------------
__device__ __align__(16) short g_S[(size_t)BB * HH_ * LQ * LKV]; // int16 scores (x4096)
__device__ float g_AO [BB * LQ  * DD];               // fp32 attn_out

// bf16 buffers
__device__ __align__(16) __nv_bfloat16 g_qh [BB * LQ  * DD], g_ql [BB * LQ  * DD];
__device__ __align__(16) __nv_bfloat16 g_kh [BB * LKV * DD], g_kl [BB * LKV * DD];
__device__ __align__(16) __nv_bfloat16 g_vh [BB * LKV * DD];   // value input hi
__device__ __align__(16) __nv_bfloat16 g_vt [BB * LKV * DD];   // Vt head-major bf16
__device__ __align__(16) __nv_bfloat16 g_wh [3 * DD * DD],   g_wl [3 * DD * DD];
__device__ __align__(16) __nv_bfloat16 g_woh[DD * DD];
__device__ __align__(16) __nv_bfloat16 g_qh2[BB * LQ  * DD], g_ql2[BB * LQ  * DD];
__device__ __align__(16) __nv_bfloat16 g_kh2[BB * LKV * DD], g_kl2[BB * LKV * DD];
__device__ __align__(16) __nv_bfloat16 g_ch [BB * LQ  * DD];

// ---------------------------------------------------------------------------
// Baseline-PTX tensor-core helpers (NO tcgen05 — compute_103 target!)
// ---------------------------------------------------------------------------
__device__ __forceinline__ uint32_t smem_u32(const void* p) {
    uint32_t a;
    asm("{ .reg .u64 t; cvta.to.shared.u64 t, %1; cvt.u32.u64 %0, t; }" : "=r"(a) : "l"(p));
    return a;
}
__device__ __forceinline__ void ldsm4(uint32_t& r0, uint32_t& r1, uint32_t& r2,
                                      uint32_t& r3, uint32_t a) {
    asm volatile("ldmatrix.sync.aligned.m8n8.x4.shared.b16 {%0,%1,%2,%3}, [%4];"
                 : "=r"(r0), "=r"(r1), "=r"(r2), "=r"(r3) : "r"(a));
}
__device__ __forceinline__ void mma_bf16(float* d, const uint32_t* a, const uint32_t* b) {
    asm volatile("mma.sync.aligned.m16n8k16.row.col.f32.bf16.bf16.f32 "
                 "{%0,%1,%2,%3},{%4,%5,%6,%7},{%8,%9},{%0,%1,%2,%3};"
                 : "+f"(d[0]), "+f"(d[1]), "+f"(d[2]), "+f"(d[3])
                 : "r"(a[0]), "r"(a[1]), "r"(a[2]), "r"(a[3]), "r"(b[0]), "r"(b[1]));
}
#define CP_ASYNC16(s, g) \
    asm volatile("cp.async.cg.shared.global [%0], [%1], 16;" :: "r"(s), "l"(g))
#define CP_COMMIT() asm volatile("cp.async.commit_group;" ::: "memory")
#define CP_WAIT1()  asm volatile("cp.async.wait_group 1;"  ::: "memory")

// 128B-row XOR swizzle: 16B chunk c (0..7), row r
__device__ __forceinline__ uint32_t sw128(int r, int c) {
    return (uint32_t)(r * 128 + ((c ^ (r & 7)) << 4));
}
__device__ __forceinline__ void bsplit(float v, __nv_bfloat16& h, __nv_bfloat16& l) {
    h = __float2bfloat16(v);
    l = __float2bfloat16(v - __bfloat162float(h));
}
__device__ __forceinline__ short squant(float v) {
    v = fminf(fmaxf(v, -32700.f), 32700.f);
    return (short)__float2int_rn(v);
}

// ---------------------------------------------------------------------------
// One launch: split all inputs/weights (hi/lo or hi-only per segment)
// ---------------------------------------------------------------------------
__device__ __forceinline__ void seg_split2(float4 v, __nv_bfloat162* hi,
                                           __nv_bfloat162* lo, long i) {
    __nv_bfloat16 h0, h1, h2, h3, l0, l1, l2, l3;
    bsplit(v.x, h0, l0); bsplit(v.y, h1, l1);
    bsplit(v.z, h2, l2); bsplit(v.w, h3, l3);
    hi[i * 2 + 0] = __halves2bfloat162(h0, h1);
    hi[i * 2 + 1] = __halves2bfloat162(h2, h3);
    lo[i * 2 + 0] = __halves2bfloat162(l0, l1);
    lo[i * 2 + 1] = __halves2bfloat162(l2, l3);
}
__device__ __forceinline__ void seg_split1(float4 v, __nv_bfloat162* hi, long i) {
    hi[i * 2 + 0] = __halves2bfloat162(__float2bfloat16(v.x), __float2bfloat16(v.y));
    hi[i * 2 + 1] = __halves2bfloat162(__float2bfloat16(v.z), __float2bfloat16(v.w));
}

__global__ void split_all(const float4* __restrict__ q, const float4* __restrict__ k,
                          const float4* __restrict__ v, const float4* __restrict__ w,
                          const float4* __restrict__ wo,
                          __nv_bfloat162* qh, __nv_bfloat162* ql,
                          __nv_bfloat162* kh, __nv_bfloat162* kl,
                          __nv_bfloat162* vh,
                          __nv_bfloat162* wh, __nv_bfloat162* wl,
                          __nv_bfloat162* woh)
{
    const long N1 = (long)BB * LQ * DD / 4;
    const long N2 = N1 + (long)BB * LKV * DD / 4;
    const long N3 = N2 + (long)BB * LKV * DD / 4;
    const long N4 = N3 + 3L * DD * DD / 4;
    const long N5 = N4 + (long)DD * DD / 4;
    long i = (long)blockIdx.x * blockDim.x + threadIdx.x;
    if (i < N1)      seg_split2(q[i], qh, ql, i);
    else if (i < N2) { i -= N1; seg_split2(k[i], kh, kl, i); }
    else if (i < N3) { i -= N2; seg_split1(v[i], vh, i); }
    else if (i < N4) { i -= N3; seg_split2(w[i], wh, wl, i); }
    else if (i < N5) { i -= N4; seg_split1(wo[i], woh, i); }
}

// ---------------------------------------------------------------------------
// Merged Q/K/V projection. Grid (8, 160): y<32 Q, y<96 K, else V.
// ---------------------------------------------------------------------------
__global__ void __launch_bounds__(128, 2) qkv_proj(
    const __nv_bfloat16* __restrict__ qhp, const __nv_bfloat16* __restrict__ qlp,
    const __nv_bfloat16* __restrict__ khp, const __nv_bfloat16* __restrict__ klp,
    const __nv_bfloat16* __restrict__ vhp,
    const __nv_bfloat16* __restrict__ whp, const __nv_bfloat16* __restrict__ wlp,
    const float* __restrict__ in_b,
    __nv_bfloat16* __restrict__ qh2, __nv_bfloat16* __restrict__ ql2,
    __nv_bfloat16* __restrict__ kh2, __nv_bfloat16* __restrict__ kl2,
    __nv_bfloat16* __restrict__ vt, float qscale)
{
    extern __shared__ __align__(16) char dynsm[];
    const uint32_t smBase = smem_u32(dynsm);

    const int tid  = threadIdx.x;
    const int lane = tid & 31;
    const int wid  = tid >> 5;
    const int wr   = wid >> 1;
    const int wc   = wid & 1;
    const int y    = blockIdx.y;
    const int n0   = blockIdx.x * 128;

    int region, m0, NIT;
    float scale = 1.0f;
    const __nv_bfloat16 *Ahi, *Alo, *Bhi, *Blo;
    const float* bias;
    if (y < 32) {
        region = 0; m0 = y * 128; NIT = 48; scale = qscale;
        Ahi = qhp; Alo = qlp; Bhi = whp; Blo = wlp; bias = in_b;
    } else if (y < 96) {
        region = 1; m0 = (y - 32) * 128; NIT = 48;
        Ahi = khp; Alo = klp;
        Bhi = whp + (size_t)DD * DD; Blo = wlp + (size_t)DD * DD;
        bias = in_b + DD;
    } else {
        region = 2; m0 = (y - 96) * 128; NIT = 16;
        Ahi = vhp; Alo = vhp;
        Bhi = whp + 2ul * DD * DD; Blo = Bhi;
        bias = in_b + 2 * DD;
    }

    const int rA  = lane & 15;
    const int cAh = lane >> 4;
    const int rBl = (lane & 7) + ((lane & 16) >> 1);
    const int cBh = (lane >> 3) & 1;

    float acc[4][8][4];
#pragma unroll
    for (int mt = 0; mt < 4; ++mt)
#pragma unroll
        for (int nt = 0; nt < 8; ++nt)
#pragma unroll
            for (int j = 0; j < 4; ++j) acc[mt][nt][j] = 0.f;

    auto prefetch = [&](int it, int stage) {
        const int part = it >> 4;
        const int ko   = (it & 15) << 6;
        const __nv_bfloat16* Ap = (part == 2) ? Alo : Ahi;
        const __nv_bfloat16* Bp = (part == 1) ? Blo : Bhi;
        const uint32_t as = smBase + (uint32_t)stage * 32768u;
        const uint32_t bs = as + 16384u;
#pragma unroll
        for (int i = 0; i < 8; ++i) {
            int q = i * 128 + tid;
            int r = q >> 3, c = q & 7;
            CP_ASYNC16(as + sw128(r, c),
                       Ap + (((size_t)(m0 + r)) << 10) + ko + c * 8);
            CP_ASYNC16(bs + sw128(r, c),
                       Bp + (((size_t)(n0 + r)) << 10) + ko + c * 8);
        }
        CP_COMMIT();
    };

    prefetch(0, 0);
    prefetch(1, 1);

    for (int it = 0; it < NIT; ++it) {
        CP_WAIT1();
        __syncthreads();
        if (it + 2 < NIT) prefetch(it + 2, (it + 2) % 3);
        else CP_COMMIT();

        const uint32_t aT = smBase + (uint32_t)(it % 3) * 32768u;
        const uint32_t bT = aT + 16384u;

#pragma unroll
        for (int ks = 0; ks < 4; ++ks) {
            uint32_t af[4][4];
            uint32_t bf[8][2];
#pragma unroll
            for (int mt = 0; mt < 4; ++mt) {
                int r = wr * 64 + mt * 16 + rA;
                ldsm4(af[mt][0], af[mt][1], af[mt][2], af[mt][3],
                      aT + sw128(r, ks * 2 + cAh));
            }
#pragma unroll
            for (int tp = 0; tp < 4; ++tp) {
                int r = wc * 64 + tp * 16 + rBl;
                uint32_t x0, x1, x2, x3;
                ldsm4(x0, x1, x2, x3, bT + sw128(r, ks * 2 + cBh));
                bf[tp * 2][0] = x0;     bf[tp * 2][1] = x1;
                bf[tp * 2 + 1][0] = x2; bf[tp * 2 + 1][1] = x3;
            }
#pragma unroll
            for (int mt = 0; mt < 4; ++mt)
#pragma unroll
                for (int nt = 0; nt < 8; ++nt)
                    mma_bf16(acc[mt][nt], af[mt], bf[nt]);
        }
    }
    __syncthreads();

    if (region < 2) {
        __nv_bfloat16* Chi = region ? kh2 : qh2;
        __nv_bfloat16* Clo = region ? kl2 : ql2;
#pragma unroll
        for (int mt = 0; mt < 4; ++mt) {
            const int row = m0 + wr * 64 + mt * 16 + (lane >> 2);
#pragma unroll
            for (int nt = 0; nt < 8; ++nt) {
                const int col = n0 + wc * 64 + nt * 8 + (lane & 3) * 2;
                const float b0 = bias[col], b1 = bias[col + 1];
                const float v0 = (acc[mt][nt][0] + b0) * scale;
                const float v1 = (acc[mt][nt][1] + b1) * scale;
                const float v2 = (acc[mt][nt][2] + b0) * scale;
                const float v3 = (acc[mt][nt][3] + b1) * scale;
                const size_t i0 = ((size_t)row << 10) + col;
                const size_t i1 = i0 + (8 << 10);
                __nv_bfloat16 h0, h1, h2, h3, l0, l1, l2, l3;
                bsplit(v0, h0, l0); bsplit(v1, h1, l1);
                bsplit(v2, h2, l2); bsplit(v3, h3, l3);
                *(__nv_bfloat162*)(Chi + i0) = __halves2bfloat162(h0, h1);
                *(__nv_bfloat162*)(Clo + i0) = __halves2bfloat162(l0, l1);
                *(__nv_bfloat162*)(Chi + i1) = __halves2bfloat162(h2, h3);
                *(__nv_bfloat162*)(Clo + i1) = __halves2bfloat162(l2, l3);
            }
        }
    } else {
        // V region: bias + transpose through smem -> head-major Vt bf16.
        float* ts = (float*)dynsm;   // 128 x 128 fp32, stride 130
#pragma unroll
        for (int mt = 0; mt < 4; ++mt) {
            const int rl = wr * 64 + mt * 16 + (lane >> 2);
#pragma unroll
            for (int nt = 0; nt < 8; ++nt) {
                const int cl = wc * 64 + nt * 8 + (lane & 3) * 2;
                const float b0 = bias[n0 + cl], b1 = bias[n0 + cl + 1];
                ts[rl * 130 + cl]           = acc[mt][nt][0] + b0;
                ts[rl * 130 + cl + 1]       = acc[mt][nt][1] + b1;
                ts[(rl + 8) * 130 + cl]     = acc[mt][nt][2] + b0;
                ts[(rl + 8) * 130 + cl + 1] = acc[mt][nt][3] + b1;
            }
        }
        __syncthreads();
        const int bb = m0 >> 10;
        const int k0 = m0 & 1023;
        __nv_bfloat16* dst = vt + (((size_t)(bb * 1024 + n0 + tid)) << 10) + k0;
#pragma unroll
        for (int k = 0; k < 128; k += 8) {
            __nv_bfloat162 p0 = __halves2bfloat162(
                __float2bfloat16(ts[(k + 0) * 130 + tid]),
                __float2bfloat16(ts[(k + 1) * 130 + tid]));
            __nv_bfloat162 p1 = __halves2bfloat162(
                __float2bfloat16(ts[(k + 2) * 130 + tid]),
                __float2bfloat16(ts[(k + 3) * 130 + tid]));
            __nv_bfloat162 p2 = __halves2bfloat162(
                __float2bfloat16(ts[(k + 4) * 130 + tid]),
                __float2bfloat16(ts[(k + 5) * 130 + tid]));
            __nv_bfloat162 p3 = __halves2bfloat162(
                __float2bfloat16(ts[(k + 6) * 130 + tid]),
                __float2bfloat16(ts[(k + 7) * 130 + tid]));
            uint4 pk;
            pk.x = *(uint32_t*)&p0; pk.y = *(uint32_t*)&p1;
            pk.z = *(uint32_t*)&p2; pk.w = *(uint32_t*)&p3;
            *(uint4*)(dst + k) = pk;
        }
    }
}

// ---------------------------------------------------------------------------
// HMMA GEMM template. I16OUT=true: quantize (acc+bias)*scale to int16 (scores).
// I16OUT=false: fp32 output (out-proj).
// ---------------------------------------------------------------------------
template<int KCH, int PARTS, bool I16OUT>
__global__ void __launch_bounds__(128, 2) gemm64(
    const __nv_bfloat16* __restrict__ Ahi, const __nv_bfloat16* __restrict__ Alo,
    const __nv_bfloat16* __restrict__ Bhi, const __nv_bfloat16* __restrict__ Blo,
    const float* __restrict__ bias, float* __restrict__ Cf,
    short* __restrict__ Cs, float scale,
    long sA0, long sA1, long sB0, long sB1, long sC0, long sC1)
{
    extern __shared__ __align__(16) char dynsm[];
    const uint32_t smBase = smem_u32(dynsm);

    const int tid  = threadIdx.x;
    const int lane = tid & 31;
    const int wid  = tid >> 5;
    const int wr   = wid >> 1;
    const int wc   = wid & 1;
    const int z    = blockIdx.z;
    const int m0   = blockIdx.y * 128;
    const int n0   = blockIdx.x * 128;
    const size_t aOff = (size_t)(z >> 4) * sA0 + (size_t)(z & 15) * sA1;
    const size_t bOff = (size_t)(z >> 4) * sB0 + (size_t)(z & 15) * sB1;
    const size_t cOff = (size_t)(z >> 4) * sC0 + (size_t)(z & 15) * sC1;

    const int rA  = lane & 15;
    const int cAh = lane >> 4;
    const int rBl = (lane & 7) + ((lane & 16) >> 1);
    const int cBh = (lane >> 3) & 1;

    float acc[4][8][4];
#pragma unroll
    for (int mt = 0; mt < 4; ++mt)
#pragma unroll
        for (int nt = 0; nt < 8; ++nt)
#pragma unroll
            for (int j = 0; j < 4; ++j) acc[mt][nt][j] = 0.f;

    auto prefetch = [&](int it, int stage) {
        const int part = it / KCH;
        const int ko   = (it % KCH) << 6;
        const __nv_bfloat16* Ap = (PARTS == 3 && part == 2) ? Alo : Ahi;
        const __nv_bfloat16* Bp = (PARTS == 3 && part == 1) ? Blo : Bhi;
        const uint32_t as = smBase + (uint32_t)stage * 32768u;
        const uint32_t bs = as + 16384u;
#pragma unroll
        for (int i = 0; i < 8; ++i) {
            int q = i * 128 + tid;
            int r = q >> 3, c = q & 7;
            CP_ASYNC16(as + sw128(r, c),
                       Ap + aOff + (((size_t)(m0 + r)) << 10) + ko + c * 8);
            CP_ASYNC16(bs + sw128(r, c),
                       Bp + bOff + (((size_t)(n0 + r)) << 10) + ko + c * 8);
        }
        CP_COMMIT();
    };

    const int NIT = PARTS * KCH;
    prefetch(0, 0);
    if (NIT > 1) prefetch(1, 1);

    for (int it = 0; it < NIT; ++it) {
        CP_WAIT1();
        __syncthreads();
        if (it + 2 < NIT) prefetch(it + 2, (it + 2) % 3);
        else CP_COMMIT();

        const uint32_t aT = smBase + (uint32_t)(it % 3) * 32768u;
        const uint32_t bT = aT + 16384u;

#pragma unroll
        for (int ks = 0; ks < 4; ++ks) {
            uint32_t af[4][4];
            uint32_t bf[8][2];
#pragma unroll
            for (int mt = 0; mt < 4; ++mt) {
                int r = wr * 64 + mt * 16 + rA;
                ldsm4(af[mt][0], af[mt][1], af[mt][2], af[mt][3],
                      aT + sw128(r, ks * 2 + cAh));
            }
#pragma unroll
            for (int tp = 0; tp < 4; ++tp) {
                int r = wc * 64 + tp * 16 + rBl;
                uint32_t x0, x1, x2, x3;
                ldsm4(x0, x1, x2, x3, bT + sw128(r, ks * 2 + cBh));
                bf[tp * 2][0] = x0;     bf[tp * 2][1] = x1;
                bf[tp * 2 + 1][0] = x2; bf[tp * 2 + 1][1] = x3;
            }
#pragma unroll
            for (int mt = 0; mt < 4; ++mt)
#pragma unroll
                for (int nt = 0; nt < 8; ++nt)
                    mma_bf16(acc[mt][nt], af[mt], bf[nt]);
        }
    }
    __syncthreads();

#pragma unroll
    for (int mt = 0; mt < 4; ++mt) {
        const int row = m0 + wr * 64 + mt * 16 + (lane >> 2);
#pragma unroll
        for (int nt = 0; nt < 8; ++nt) {
            const int col = n0 + wc * 64 + nt * 8 + (lane & 3) * 2;
            const float b0 = bias ? bias[col]     : 0.f;
            const float b1 = bias ? bias[col + 1] : 0.f;
            const float v0 = (acc[mt][nt][0] + b0) * scale;
            const float v1 = (acc[mt][nt][1] + b1) * scale;
            const float v2 = (acc[mt][nt][2] + b0) * scale;
            const float v3 = (acc[mt][nt][3] + b1) * scale;
            const size_t i0 = cOff + ((size_t)row << 10) + col;
            const size_t i1 = i0 + (8 << 10);
            if (I16OUT) {
                *(short2*)(Cs + i0) = make_short2(squant(v0), squant(v1));
                *(short2*)(Cs + i1) = make_short2(squant(v2), squant(v3));
            } else {
                Cf[i0] = v0; Cf[i0 + 1] = v1;
                Cf[i1] = v2; Cf[i1 + 1] = v3;
            }
        }
    }
}

// ---------------------------------------------------------------------------
// Head-mean of softmax(S). One block (512 thr = 16 warps) per (b,q); warp w
// owns head w's row. NO max pass: S is clamped to |s|<=7.98, exp is safe
// (max row sum ~3e6, fp32 fine). Private per-warp slabs, no atomics.
// ---------------------------------------------------------------------------
__global__ void __launch_bounds__(512) mean_heads(const short* __restrict__ S,
                                                  float* __restrict__ mean_out)
{
    extern __shared__ __align__(16) float slab[];   // [16][1024]
    const int bq = blockIdx.x;
    const int b = bq >> 9, q = bq & 511;
    const int tid = threadIdx.x;
    const int lane = tid & 31, w = tid >> 5;

    const short* Sp = S + (((size_t)(b * 16 + w) * 512 + q) << 10);
    int4 raw[4];
#pragma unroll
    for (int i = 0; i < 4; ++i)
        raw[i] = __ldg((const int4*)(Sp + (i * 32 + lane) * 8));

    float v[32];
    float s = 0.f;
#pragma unroll
    for (int i = 0; i < 4; ++i) {
        const uint32_t* u = (const uint32_t*)&raw[i];
#pragma unroll
        for (int j = 0; j < 4; ++j) {
            float a = __expf((float)((short)(u[j] & 0xFFFF)) * S_INVSC);
            float c = __expf((float)((short)(u[j] >> 16))    * S_INVSC);
            v[i * 8 + j * 2 + 0] = a;
            v[i * 8 + j * 2 + 1] = c;
            s += a + c;
        }
    }
#pragma unroll
    for (int o = 16; o; o >>= 1) s += __shfl_xor_sync(0xffffffffu, s, o);
    const float inv = 1.0f / s;

    float4* wslab = (float4*)(slab + w * 1024);
#pragma unroll
    for (int i = 0; i < 4; ++i)
#pragma unroll
        for (int jj = 0; jj < 2; ++jj) {
            float4 p;
            p.x = v[i * 8 + jj * 4 + 0] * inv;
            p.y = v[i * 8 + jj * 4 + 1] * inv;
            p.z = v[i * 8 + jj * 4 + 2] * inv;
            p.w = v[i * 8 + jj * 4 + 3] * inv;
            wslab[(i * 32 + lane) * 2 + jj] = p;
        }
    __syncthreads();

    float s0 = 0.f, s1 = 0.f;
#pragma unroll
    for (int h = 0; h < HH_; ++h) {
        s0 += slab[h * 1024 + tid];
        s1 += slab[h * 1024 + tid + 512];
    }
    const float inv16 = 1.0f / HH_;
    float* mo = mean_out + (((size_t)bq) << 10);
    mo[tid]       = s0 * inv16;
    mo[tid + 512] = s1 * inv16;
}

// ---------------------------------------------------------------------------
// Fused ctx (plain bf16), SELF-NORMALIZING: per z=(b,h), q-tile 128.
// Reads int16 S, computes UNNORMALIZED e=exp(s) into P smem, MMA accumulates
// sum(e*v); each thread register-accumulates its 2 fixed rows' e-sums across
// all kv chunks; octet-shuffle + smem combine at end; epilogue multiplies by
// 1/rowsum. No stats dependency. 512 thr (16 warps, 32x16 warp tiles).
// SMEM: P 2x16KB + V 3x8KB + rowsum 512B.
// ---------------------------------------------------------------------------
__global__ void __launch_bounds__(512) ctx_fused(
    const short* __restrict__ S,
    const __nv_bfloat16* __restrict__ Vhi,
    __nv_bfloat16* __restrict__ Chi)
{
    extern __shared__ __align__(16) char dynsm[];
    const uint32_t smBase = smem_u32(dynsm);
    float* rs = (float*)(dynsm + 32768 + 3 * 8192);   // [128] row sums

    const int tid  = threadIdx.x;
    const int lane = tid & 31;
    const int wid  = tid >> 5;
    const int wr   = wid >> 2;
    const int wc   = wid & 3;
    const int z    = blockIdx.z, b = z >> 4, h = z & 15;
    const int m0   = blockIdx.y * 128;
    const size_t sOff  = ((size_t)z * 512 + m0) << 10;
    const size_t vOff  = ((size_t)z * 64) << 10;

    const int rA  = lane & 15;
    const int cAh = lane >> 4;
    const int rBl = (lane & 7) + ((lane & 16) >> 1);
    const int cBh = (lane >> 3) & 1;

    float acc[2][2][4];
#pragma unroll
    for (int mt = 0; mt < 2; ++mt)
#pragma unroll
        for (int nt = 0; nt < 2; ++nt)
#pragma unroll
            for (int j = 0; j < 4; ++j) acc[mt][nt][j] = 0.f;

    float rsum0 = 0.f, rsum1 = 0.f;   // rows tid>>3 and (tid>>3)+64

    int4 sreg[2];
    auto ldS = [&](int kc) {
#pragma unroll
        for (int i = 0; i < 2; ++i) {
            int idx = i * 512 + tid;
            int row = idx >> 3, c8 = idx & 7;
            sreg[i] = __ldg((const int4*)(S + sOff + ((size_t)row << 10) +
                                          (kc << 6) + c8 * 8));
        }
    };
    auto cpV = [&](int kc) {
        const uint32_t vs = smBase + 32768u + (uint32_t)(kc % 3) * 8192u;
        int r = tid >> 3, c = tid & 7;
        CP_ASYNC16(vs + sw128(r, c), Vhi + vOff + ((size_t)r << 10) + (kc << 6) + c * 8);
        CP_COMMIT();
    };

    ldS(0);
    cpV(0);
    cpV(1);

    for (int kc = 0; kc < 16; ++kc) {
        const uint32_t pB = smBase + (uint32_t)(kc & 1) * 16384u;
#pragma unroll
        for (int i = 0; i < 2; ++i) {
            int idx = i * 512 + tid;
            int row = idx >> 3, c8 = idx & 7;
            const uint32_t* u = (const uint32_t*)&sreg[i];
            uint32_t packed[4];
            float esum = 0.f;
#pragma unroll
            for (int j = 0; j < 4; ++j) {
                float a = __expf((float)((short)(u[j] & 0xFFFF)) * S_INVSC);
                float c = __expf((float)((short)(u[j] >> 16))    * S_INVSC);
                esum += a + c;
                __nv_bfloat162 pp = __halves2bfloat162(__float2bfloat16(a),
                                                       __float2bfloat16(c));
                packed[j] = *(uint32_t*)&pp;
            }
            if (i == 0) rsum0 += esum; else rsum1 += esum;
            uint32_t off = sw128(row, c8);
            asm volatile("st.shared.v4.b32 [%0], {%1, %2, %3, %4};" ::
                         "r"(pB + off), "r"(packed[0]), "r"(packed[1]),
                         "r"(packed[2]), "r"(packed[3]) : "memory");
        }
        if (kc + 1 < 16) ldS(kc + 1);

        CP_WAIT1();
        __syncthreads();
        if (kc + 2 < 16) cpV(kc + 2);
        else CP_COMMIT();

        const uint32_t phT = smBase + (uint32_t)(kc & 1) * 16384u;
        const uint32_t vhT = smBase + 32768u + (uint32_t)(kc % 3) * 8192u;

#pragma unroll
        for (int ks = 0; ks < 4; ++ks) {
            uint32_t ah[2][4];
            uint32_t bh[2][2];
#pragma unroll
            for (int mt = 0; mt < 2; ++mt) {
                int r = wr * 32 + mt * 16 + rA;
                ldsm4(ah[mt][0], ah[mt][1], ah[mt][2], ah[mt][3],
                      phT + sw128(r, ks * 2 + cAh));
            }
            {
                int r = wc * 16 + rBl;
                uint32_t x0, x1, x2, x3;
                ldsm4(x0, x1, x2, x3, vhT + sw128(r, ks * 2 + cBh));
                bh[0][0] = x0; bh[0][1] = x1; bh[1][0] = x2; bh[1][1] = x3;
            }
#pragma unroll
            for (int mt = 0; mt < 2; ++mt)
#pragma unroll
                for (int nt = 0; nt < 2; ++nt)
                    mma_bf16(acc[mt][nt], ah[mt], bh[nt]);
        }
    }

    // combine row sums: octet shuffle (threads tid&7 share a row), then smem
#pragma unroll
    for (int o = 1; o < 8; o <<= 1) {
        rsum0 += __shfl_xor_sync(0xffffffffu, rsum0, o);
        rsum1 += __shfl_xor_sync(0xffffffffu, rsum1, o);
    }
    if ((tid & 7) == 0) {
        rs[tid >> 3]        = rsum0;   // rows 0..63
        rs[(tid >> 3) + 64] = rsum1;   // rows 64..127
    }
    __syncthreads();

#pragma unroll
    for (int mt = 0; mt < 2; ++mt) {
        const int rl = wr * 32 + mt * 16 + (lane >> 2);
        const float inv0 = 1.0f / rs[rl];
        const float inv1 = 1.0f / rs[rl + 8];
        const int row = m0 + rl;
#pragma unroll
        for (int nt = 0; nt < 2; ++nt) {
            const int col = h * 64 + wc * 16 + nt * 8 + (lane & 3) * 2;
            const size_t i0 = (((size_t)(b * 512 + row)) << 10) + col;
            const size_t i1 = i0 + (8 << 10);
            *(__nv_bfloat162*)(Chi + i0) =
                __halves2bfloat162(__float2bfloat16(acc[mt][nt][0] * inv0),
                                   __float2bfloat16(acc[mt][nt][1] * inv0));
            *(__nv_bfloat162*)(Chi + i1) =
                __halves2bfloat162(__float2bfloat16(acc[mt][nt][2] * inv1),
                                   __float2bfloat16(acc[mt][nt][3] * inv1));
        }
    }
}

// ---------------------------------------------------------------------------
// out = LayerNorm(query + attn_out) * gamma + beta.  One block per row.
// ---------------------------------------------------------------------------
__global__ void residual_ln(const float* __restrict__ q, const float* __restrict__ ao,
                            const float* __restrict__ gamma, const float* __restrict__ beta,
                            float* __restrict__ out)
{
    __shared__ float red[8];
    __shared__ float bcast;
    const long row = blockIdx.x;
    const int tid = threadIdx.x;

    float4 qa = *(const float4*)&q [row * DD + tid * 4];
    float4 aa = *(const float4*)&ao[row * DD + tid * 4];
    float x0 = qa.x + aa.x, x1 = qa.y + aa.y, x2 = qa.z + aa.z, x3 = qa.w + aa.w;

    float s = (x0 + x1) + (x2 + x3);
#pragma unroll
    for (int o = 16; o; o >>= 1) s += __shfl_xor_sync(0xffffffffu, s, o);
    if ((tid & 31) == 0) red[tid >> 5] = s;
    __syncthreads();
    if (tid < 8) {
        s = red[tid];
#pragma unroll
        for (int o = 4; o; o >>= 1) s += __shfl_xor_sync(0xffu, s, o);
        if (tid == 0) bcast = s;
    }
    __syncthreads();
    const float mu = bcast * (1.0f / DD);

    float d0 = x0 - mu, d1 = x1 - mu, d2 = x2 - mu, d3 = x3 - mu;
    float sq = (d0 * d0 + d1 * d1) + (d2 * d2 + d3 * d3);
#pragma unroll
    for (int o = 16; o; o >>= 1) sq += __shfl_xor_sync(0xffffffffu, sq, o);
    __syncthreads();
    if ((tid & 31) == 0) red[tid >> 5] = sq;
    __syncthreads();
    if (tid < 8) {
        sq = red[tid];
#pragma unroll
        for (int o = 4; o; o >>= 1) sq += __shfl_xor_sync(0xffu, sq, o);
        if (tid == 0) bcast = sq;
    }
    __syncthreads();
    const float rstd = rsqrtf(bcast * (1.0f / DD) + LN_EPS);

    float4 g = *(const float4*)&gamma[tid * 4];
    float4 be = *(const float4*)&beta[tid * 4];
    float4 o4;
    o4.x = d0 * rstd * g.x + be.x;
    o4.y = d1 * rstd * g.y + be.y;
    o4.z = d2 * rstd * g.z + be.z;
    o4.w = d3 * rstd * g.w + be.w;
    *(float4*)&out[row * DD + tid * 4] = o4;
}

// ---------------------------------------------------------------------------
extern "C" void kernel_launch(void* const* d_in, const int* in_sizes, int n_in,
                              void* d_out, int out_size)
{
    const float* query = (const float*)d_in[0];
    const float* key_  = (const float*)d_in[1];
    const float* value = (const float*)d_in[2];
    const float* in_w  = (const float*)d_in[3];
    const float* in_b  = (const float*)d_in[4];
    const float* out_w = (const float*)d_in[5];
    const float* out_b = (const float*)d_in[6];
    const float* gamma = (const float*)d_in[7];
    const float* beta  = (const float*)d_in[8];
    float* out = (float*)d_out;

    short* Si;
    float* AO;
    cudaGetSymbolAddress((void**)&Si, g_S);
    cudaGetSymbolAddress((void**)&AO, g_AO);

    __nv_bfloat16 *qh, *ql, *kh, *kl, *vh, *vt, *wh, *wl, *woh;
    __nv_bfloat16 *qh2, *ql2, *kh2, *kl2, *ch;
    cudaGetSymbolAddress((void**)&qh,  g_qh);  cudaGetSymbolAddress((void**)&ql,  g_ql);
    cudaGetSymbolAddress((void**)&kh,  g_kh);  cudaGetSymbolAddress((void**)&kl,  g_kl);
    cudaGetSymbolAddress((void**)&vh,  g_vh);  cudaGetSymbolAddress((void**)&vt,  g_vt);
    cudaGetSymbolAddress((void**)&wh,  g_wh);  cudaGetSymbolAddress((void**)&wl,  g_wl);
    cudaGetSymbolAddress((void**)&woh, g_woh);
    cudaGetSymbolAddress((void**)&qh2, g_qh2); cudaGetSymbolAddress((void**)&ql2, g_ql2);
    cudaGetSymbolAddress((void**)&kh2, g_kh2); cudaGetSymbolAddress((void**)&kl2, g_kl2);
    cudaGetSymbolAddress((void**)&ch,  g_ch);

    const int SM_G = 3 * 32768;
    const int SM_X = 2 * 16384 + 3 * 8192 + 512;   // + rowsum array
    const int SM_S = 16 * 1024 * 4;                // mean slabs: 64 KB
    cudaFuncSetAttribute((const void*)qkv_proj,
                         cudaFuncAttributeMaxDynamicSharedMemorySize, SM_G);
    cudaFuncSetAttribute((const void*)gemm64<1, 3, true>,
                         cudaFuncAttributeMaxDynamicSharedMemorySize, SM_G);
    cudaFuncSetAttribute((const void*)gemm64<16, 1, false>,
                         cudaFuncAttributeMaxDynamicSharedMemorySize, SM_G);
    cudaFuncSetAttribute((const void*)ctx_fused,
                         cudaFuncAttributeMaxDynamicSharedMemorySize, SM_X);
    cudaFuncSetAttribute((const void*)mean_heads,
                         cudaFuncAttributeMaxDynamicSharedMemorySize, SM_S);

    const float qscale = 0.125f;

    // 1) split everything in one launch
    {
        const long total4 = (long)BB*LQ*DD/4 + 2L*BB*LKV*DD/4 + 3L*DD*DD/4 + (long)DD*DD/4;
        split_all<<<(unsigned)((total4 + 255) / 256), 256>>>(
            (const float4*)query, (const float4*)key_, (const float4*)value,
            (const float4*)in_w, (const float4*)out_w,
            (__nv_bfloat162*)qh, (__nv_bfloat162*)ql,
            (__nv_bfloat162*)kh, (__nv_bfloat162*)kl,
            (__nv_bfloat162*)vh,
            (__nv_bfloat162*)wh, (__nv_bfloat162*)wl,
            (__nv_bfloat162*)woh);
    }

    // 2) merged Q/K/V projection (+ fused V transpose -> vt)
    qkv_proj<<<dim3(8, 160), 128, SM_G>>>(
        qh, ql, kh, kl, vh, wh, wl, in_b,
        qh2, ql2, kh2, kl2, vt, qscale);

    // 3) scores (bf16x3) -> int16 S (scaled by 4096)
    gemm64<1, 3, true><<<dim3(8, 4, BB * HH_), 128, SM_G>>>(
        qh2, ql2, kh2, kl2, nullptr, nullptr, Si, S_SCALE,
        (long)LQ * DD,  (long)HD,
        (long)LKV * DD, (long)HD,
        (long)HH_ * LQ * LKV, (long)LQ * LKV);

    // 4) head-mean of softmax (no-max, slab reduction)
    mean_heads<<<BB * LQ, 512, SM_S>>>(Si, out + (long)BB * LQ * DD);

    // 5) fused self-normalizing ctx MMA (int16 S in, bf16 ch out)
    ctx_fused<<<dim3(1, 4, BB * HH_), 512, SM_X>>>(Si, vt, ch);

    // 6) out projection (bf16x1) -> fp32 AO
    gemm64<16, 1, false><<<dim3(8, 32, 1), 128, SM_G>>>(
        ch, nullptr, woh, nullptr, out_b, AO, nullptr, 1.0f, 0,0, 0,0, 0,0);

    // 7) residual + LayerNorm
    residual_ln<<<BB * LQ, 256>>>(query, AO, gamma, beta, out);
}

// round 13
// speedup vs baseline: 1.7835x; 1.0291x over previous
#include <cuda_runtime.h>
#include <cuda_bf16.h>
#include <math.h>
#include <stdint.h>

// Problem constants
#define BB   8
#define LQ   512
#define LKV  1024
#define DD   1024
#define HH_  16
#define HD   64
#define LN_EPS 1e-5f

#define S_SCALE   4096.0f
#define S_INVSC   (1.0f / 4096.0f)

// ---------------------------------------------------------------------------
// Scratch (device globals: allocation-free per harness rules)
// ---------------------------------------------------------------------------
__device__ __align__(16) short g_S[(size_t)BB * HH_ * LQ * LKV]; // int16 scores (x4096)
__device__ float g_AO  [BB * LQ  * DD];              // fp32 attn_out
__device__ float g_rsum[BB * HH_ * LQ];              // 1/rowsum (from ctx_fused)

// bf16 buffers
__device__ __align__(16) __nv_bfloat16 g_qh [BB * LQ  * DD], g_ql [BB * LQ  * DD];
__device__ __align__(16) __nv_bfloat16 g_kh [BB * LKV * DD], g_kl [BB * LKV * DD];
__device__ __align__(16) __nv_bfloat16 g_vh [BB * LKV * DD];   // value input hi
__device__ __align__(16) __nv_bfloat16 g_vt [BB * LKV * DD];   // Vt head-major bf16
__device__ __align__(16) __nv_bfloat16 g_wh [3 * DD * DD],   g_wl [3 * DD * DD];
__device__ __align__(16) __nv_bfloat16 g_woh[DD * DD];
__device__ __align__(16) __nv_bfloat16 g_qh2[BB * LQ  * DD], g_ql2[BB * LQ  * DD];
__device__ __align__(16) __nv_bfloat16 g_kh2[BB * LKV * DD], g_kl2[BB * LKV * DD];
__device__ __align__(16) __nv_bfloat16 g_ch [BB * LQ  * DD];

// ---------------------------------------------------------------------------
// Baseline-PTX tensor-core helpers (NO tcgen05 — compute_103 target!)
// ---------------------------------------------------------------------------
__device__ __forceinline__ uint32_t smem_u32(const void* p) {
    uint32_t a;
    asm("{ .reg .u64 t; cvta.to.shared.u64 t, %1; cvt.u32.u64 %0, t; }" : "=r"(a) : "l"(p));
    return a;
}
__device__ __forceinline__ void ldsm4(uint32_t& r0, uint32_t& r1, uint32_t& r2,
                                      uint32_t& r3, uint32_t a) {
    asm volatile("ldmatrix.sync.aligned.m8n8.x4.shared.b16 {%0,%1,%2,%3}, [%4];"
                 : "=r"(r0), "=r"(r1), "=r"(r2), "=r"(r3) : "r"(a));
}
__device__ __forceinline__ void mma_bf16(float* d, const uint32_t* a, const uint32_t* b) {
    asm volatile("mma.sync.aligned.m16n8k16.row.col.f32.bf16.bf16.f32 "
                 "{%0,%1,%2,%3},{%4,%5,%6,%7},{%8,%9},{%0,%1,%2,%3};"
                 : "+f"(d[0]), "+f"(d[1]), "+f"(d[2]), "+f"(d[3])
                 : "r"(a[0]), "r"(a[1]), "r"(a[2]), "r"(a[3]), "r"(b[0]), "r"(b[1]));
}
#define CP_ASYNC16(s, g) \
    asm volatile("cp.async.cg.shared.global [%0], [%1], 16;" :: "r"(s), "l"(g))
#define CP_COMMIT() asm volatile("cp.async.commit_group;" ::: "memory")
#define CP_WAIT1()  asm volatile("cp.async.wait_group 1;"  ::: "memory")

// 128B-row XOR swizzle: 16B chunk c (0..7), row r
__device__ __forceinline__ uint32_t sw128(int r, int c) {
    return (uint32_t)(r * 128 + ((c ^ (r & 7)) << 4));
}
__device__ __forceinline__ void bsplit(float v, __nv_bfloat16& h, __nv_bfloat16& l) {
    h = __float2bfloat16(v);
    l = __float2bfloat16(v - __bfloat162float(h));
}
__device__ __forceinline__ short squant(float v) {
    v = fminf(fmaxf(v, -32700.f), 32700.f);
    return (short)__float2int_rn(v);
}

// ---------------------------------------------------------------------------
// One launch: split all inputs/weights (hi/lo or hi-only per segment)
// ---------------------------------------------------------------------------
__device__ __forceinline__ void seg_split2(float4 v, __nv_bfloat162* hi,
                                           __nv_bfloat162* lo, long i) {
    __nv_bfloat16 h0, h1, h2, h3, l0, l1, l2, l3;
    bsplit(v.x, h0, l0); bsplit(v.y, h1, l1);
    bsplit(v.z, h2, l2); bsplit(v.w, h3, l3);
    hi[i * 2 + 0] = __halves2bfloat162(h0, h1);
    hi[i * 2 + 1] = __halves2bfloat162(h2, h3);
    lo[i * 2 + 0] = __halves2bfloat162(l0, l1);
    lo[i * 2 + 1] = __halves2bfloat162(l2, l3);
}
__device__ __forceinline__ void seg_split1(float4 v, __nv_bfloat162* hi, long i) {
    hi[i * 2 + 0] = __halves2bfloat162(__float2bfloat16(v.x), __float2bfloat16(v.y));
    hi[i * 2 + 1] = __halves2bfloat162(__float2bfloat16(v.z), __float2bfloat16(v.w));
}

__global__ void split_all(const float4* __restrict__ q, const float4* __restrict__ k,
                          const float4* __restrict__ v, const float4* __restrict__ w,
                          const float4* __restrict__ wo,
                          __nv_bfloat162* qh, __nv_bfloat162* ql,
                          __nv_bfloat162* kh, __nv_bfloat162* kl,
                          __nv_bfloat162* vh,
                          __nv_bfloat162* wh, __nv_bfloat162* wl,
                          __nv_bfloat162* woh)
{
    const long N1 = (long)BB * LQ * DD / 4;
    const long N2 = N1 + (long)BB * LKV * DD / 4;
    const long N3 = N2 + (long)BB * LKV * DD / 4;
    const long N4 = N3 + 3L * DD * DD / 4;
    const long N5 = N4 + (long)DD * DD / 4;
    long i = (long)blockIdx.x * blockDim.x + threadIdx.x;
    if (i < N1)      seg_split2(q[i], qh, ql, i);
    else if (i < N2) { i -= N1; seg_split2(k[i], kh, kl, i); }
    else if (i < N3) { i -= N2; seg_split1(v[i], vh, i); }
    else if (i < N4) { i -= N3; seg_split2(w[i], wh, wl, i); }
    else if (i < N5) { i -= N4; seg_split1(wo[i], woh, i); }
}

// ---------------------------------------------------------------------------
// Merged Q/K/V projection. Grid (8, 160): y<32 Q, y<96 K, else V.
// ---------------------------------------------------------------------------
__global__ void __launch_bounds__(128, 2) qkv_proj(
    const __nv_bfloat16* __restrict__ qhp, const __nv_bfloat16* __restrict__ qlp,
    const __nv_bfloat16* __restrict__ khp, const __nv_bfloat16* __restrict__ klp,
    const __nv_bfloat16* __restrict__ vhp,
    const __nv_bfloat16* __restrict__ whp, const __nv_bfloat16* __restrict__ wlp,
    const float* __restrict__ in_b,
    __nv_bfloat16* __restrict__ qh2, __nv_bfloat16* __restrict__ ql2,
    __nv_bfloat16* __restrict__ kh2, __nv_bfloat16* __restrict__ kl2,
    __nv_bfloat16* __restrict__ vt, float qscale)
{
    extern __shared__ __align__(16) char dynsm[];
    const uint32_t smBase = smem_u32(dynsm);

    const int tid  = threadIdx.x;
    const int lane = tid & 31;
    const int wid  = tid >> 5;
    const int wr   = wid >> 1;
    const int wc   = wid & 1;
    const int y    = blockIdx.y;
    const int n0   = blockIdx.x * 128;

    int region, m0, NIT;
    float scale = 1.0f;
    const __nv_bfloat16 *Ahi, *Alo, *Bhi, *Blo;
    const float* bias;
    if (y < 32) {
        region = 0; m0 = y * 128; NIT = 48; scale = qscale;
        Ahi = qhp; Alo = qlp; Bhi = whp; Blo = wlp; bias = in_b;
    } else if (y < 96) {
        region = 1; m0 = (y - 32) * 128; NIT = 48;
        Ahi = khp; Alo = klp;
        Bhi = whp + (size_t)DD * DD; Blo = wlp + (size_t)DD * DD;
        bias = in_b + DD;
    } else {
        region = 2; m0 = (y - 96) * 128; NIT = 16;
        Ahi = vhp; Alo = vhp;
        Bhi = whp + 2ul * DD * DD; Blo = Bhi;
        bias = in_b + 2 * DD;
    }

    const int rA  = lane & 15;
    const int cAh = lane >> 4;
    const int rBl = (lane & 7) + ((lane & 16) >> 1);
    const int cBh = (lane >> 3) & 1;

    float acc[4][8][4];
#pragma unroll
    for (int mt = 0; mt < 4; ++mt)
#pragma unroll
        for (int nt = 0; nt < 8; ++nt)
#pragma unroll
            for (int j = 0; j < 4; ++j) acc[mt][nt][j] = 0.f;

    auto prefetch = [&](int it, int stage) {
        const int part = it >> 4;
        const int ko   = (it & 15) << 6;
        const __nv_bfloat16* Ap = (part == 2) ? Alo : Ahi;
        const __nv_bfloat16* Bp = (part == 1) ? Blo : Bhi;
        const uint32_t as = smBase + (uint32_t)stage * 32768u;
        const uint32_t bs = as + 16384u;
#pragma unroll
        for (int i = 0; i < 8; ++i) {
            int q = i * 128 + tid;
            int r = q >> 3, c = q & 7;
            CP_ASYNC16(as + sw128(r, c),
                       Ap + (((size_t)(m0 + r)) << 10) + ko + c * 8);
            CP_ASYNC16(bs + sw128(r, c),
                       Bp + (((size_t)(n0 + r)) << 10) + ko + c * 8);
        }
        CP_COMMIT();
    };

    prefetch(0, 0);
    prefetch(1, 1);

    for (int it = 0; it < NIT; ++it) {
        CP_WAIT1();
        __syncthreads();
        if (it + 2 < NIT) prefetch(it + 2, (it + 2) % 3);
        else CP_COMMIT();

        const uint32_t aT = smBase + (uint32_t)(it % 3) * 32768u;
        const uint32_t bT = aT + 16384u;

#pragma unroll
        for (int ks = 0; ks < 4; ++ks) {
            uint32_t af[4][4];
            uint32_t bf[8][2];
#pragma unroll
            for (int mt = 0; mt < 4; ++mt) {
                int r = wr * 64 + mt * 16 + rA;
                ldsm4(af[mt][0], af[mt][1], af[mt][2], af[mt][3],
                      aT + sw128(r, ks * 2 + cAh));
            }
#pragma unroll
            for (int tp = 0; tp < 4; ++tp) {
                int r = wc * 64 + tp * 16 + rBl;
                uint32_t x0, x1, x2, x3;
                ldsm4(x0, x1, x2, x3, bT + sw128(r, ks * 2 + cBh));
                bf[tp * 2][0] = x0;     bf[tp * 2][1] = x1;
                bf[tp * 2 + 1][0] = x2; bf[tp * 2 + 1][1] = x3;
            }
#pragma unroll
            for (int mt = 0; mt < 4; ++mt)
#pragma unroll
                for (int nt = 0; nt < 8; ++nt)
                    mma_bf16(acc[mt][nt], af[mt], bf[nt]);
        }
    }
    __syncthreads();

    if (region < 2) {
        __nv_bfloat16* Chi = region ? kh2 : qh2;
        __nv_bfloat16* Clo = region ? kl2 : ql2;
#pragma unroll
        for (int mt = 0; mt < 4; ++mt) {
            const int row = m0 + wr * 64 + mt * 16 + (lane >> 2);
#pragma unroll
            for (int nt = 0; nt < 8; ++nt) {
                const int col = n0 + wc * 64 + nt * 8 + (lane & 3) * 2;
                const float b0 = bias[col], b1 = bias[col + 1];
                const float v0 = (acc[mt][nt][0] + b0) * scale;
                const float v1 = (acc[mt][nt][1] + b1) * scale;
                const float v2 = (acc[mt][nt][2] + b0) * scale;
                const float v3 = (acc[mt][nt][3] + b1) * scale;
                const size_t i0 = ((size_t)row << 10) + col;
                const size_t i1 = i0 + (8 << 10);
                __nv_bfloat16 h0, h1, h2, h3, l0, l1, l2, l3;
                bsplit(v0, h0, l0); bsplit(v1, h1, l1);
                bsplit(v2, h2, l2); bsplit(v3, h3, l3);
                *(__nv_bfloat162*)(Chi + i0) = __halves2bfloat162(h0, h1);
                *(__nv_bfloat162*)(Clo + i0) = __halves2bfloat162(l0, l1);
                *(__nv_bfloat162*)(Chi + i1) = __halves2bfloat162(h2, h3);
                *(__nv_bfloat162*)(Clo + i1) = __halves2bfloat162(l2, l3);
            }
        }
    } else {
        // V region: bias + transpose through smem -> head-major Vt bf16.
        float* ts = (float*)dynsm;   // 128 x 128 fp32, stride 130
#pragma unroll
        for (int mt = 0; mt < 4; ++mt) {
            const int rl = wr * 64 + mt * 16 + (lane >> 2);
#pragma unroll
            for (int nt = 0; nt < 8; ++nt) {
                const int cl = wc * 64 + nt * 8 + (lane & 3) * 2;
                const float b0 = bias[n0 + cl], b1 = bias[n0 + cl + 1];
                ts[rl * 130 + cl]           = acc[mt][nt][0] + b0;
                ts[rl * 130 + cl + 1]       = acc[mt][nt][1] + b1;
                ts[(rl + 8) * 130 + cl]     = acc[mt][nt][2] + b0;
                ts[(rl + 8) * 130 + cl + 1] = acc[mt][nt][3] + b1;
            }
        }
        __syncthreads();
        const int bb = m0 >> 10;
        const int k0 = m0 & 1023;
        __nv_bfloat16* dst = vt + (((size_t)(bb * 1024 + n0 + tid)) << 10) + k0;
#pragma unroll
        for (int k = 0; k < 128; k += 8) {
            __nv_bfloat162 p0 = __halves2bfloat162(
                __float2bfloat16(ts[(k + 0) * 130 + tid]),
                __float2bfloat16(ts[(k + 1) * 130 + tid]));
            __nv_bfloat162 p1 = __halves2bfloat162(
                __float2bfloat16(ts[(k + 2) * 130 + tid]),
                __float2bfloat16(ts[(k + 3) * 130 + tid]));
            __nv_bfloat162 p2 = __halves2bfloat162(
                __float2bfloat16(ts[(k + 4) * 130 + tid]),
                __float2bfloat16(ts[(k + 5) * 130 + tid]));
            __nv_bfloat162 p3 = __halves2bfloat162(
                __float2bfloat16(ts[(k + 6) * 130 + tid]),
                __float2bfloat16(ts[(k + 7) * 130 + tid]));
            uint4 pk;
            pk.x = *(uint32_t*)&p0; pk.y = *(uint32_t*)&p1;
            pk.z = *(uint32_t*)&p2; pk.w = *(uint32_t*)&p3;
            *(uint4*)(dst + k) = pk;
        }
    }
}

// ---------------------------------------------------------------------------
// HMMA GEMM template. I16OUT=true: quantize (acc+bias)*scale to int16 (scores).
// I16OUT=false: fp32 output (out-proj).
// ---------------------------------------------------------------------------
template<int KCH, int PARTS, bool I16OUT>
__global__ void __launch_bounds__(128, 2) gemm64(
    const __nv_bfloat16* __restrict__ Ahi, const __nv_bfloat16* __restrict__ Alo,
    const __nv_bfloat16* __restrict__ Bhi, const __nv_bfloat16* __restrict__ Blo,
    const float* __restrict__ bias, float* __restrict__ Cf,
    short* __restrict__ Cs, float scale,
    long sA0, long sA1, long sB0, long sB1, long sC0, long sC1)
{
    extern __shared__ __align__(16) char dynsm[];
    const uint32_t smBase = smem_u32(dynsm);

    const int tid  = threadIdx.x;
    const int lane = tid & 31;
    const int wid  = tid >> 5;
    const int wr   = wid >> 1;
    const int wc   = wid & 1;
    const int z    = blockIdx.z;
    const int m0   = blockIdx.y * 128;
    const int n0   = blockIdx.x * 128;
    const size_t aOff = (size_t)(z >> 4) * sA0 + (size_t)(z & 15) * sA1;
    const size_t bOff = (size_t)(z >> 4) * sB0 + (size_t)(z & 15) * sB1;
    const size_t cOff = (size_t)(z >> 4) * sC0 + (size_t)(z & 15) * sC1;

    const int rA  = lane & 15;
    const int cAh = lane >> 4;
    const int rBl = (lane & 7) + ((lane & 16) >> 1);
    const int cBh = (lane >> 3) & 1;

    float acc[4][8][4];
#pragma unroll
    for (int mt = 0; mt < 4; ++mt)
#pragma unroll
        for (int nt = 0; nt < 8; ++nt)
#pragma unroll
            for (int j = 0; j < 4; ++j) acc[mt][nt][j] = 0.f;

    auto prefetch = [&](int it, int stage) {
        const int part = it / KCH;
        const int ko   = (it % KCH) << 6;
        const __nv_bfloat16* Ap = (PARTS == 3 && part == 2) ? Alo : Ahi;
        const __nv_bfloat16* Bp = (PARTS == 3 && part == 1) ? Blo : Bhi;
        const uint32_t as = smBase + (uint32_t)stage * 32768u;
        const uint32_t bs = as + 16384u;
#pragma unroll
        for (int i = 0; i < 8; ++i) {
            int q = i * 128 + tid;
            int r = q >> 3, c = q & 7;
            CP_ASYNC16(as + sw128(r, c),
                       Ap + aOff + (((size_t)(m0 + r)) << 10) + ko + c * 8);
            CP_ASYNC16(bs + sw128(r, c),
                       Bp + bOff + (((size_t)(n0 + r)) << 10) + ko + c * 8);
        }
        CP_COMMIT();
    };

    const int NIT = PARTS * KCH;
    prefetch(0, 0);
    if (NIT > 1) prefetch(1, 1);

    for (int it = 0; it < NIT; ++it) {
        CP_WAIT1();
        __syncthreads();
        if (it + 2 < NIT) prefetch(it + 2, (it + 2) % 3);
        else CP_COMMIT();

        const uint32_t aT = smBase + (uint32_t)(it % 3) * 32768u;
        const uint32_t bT = aT + 16384u;

#pragma unroll
        for (int ks = 0; ks < 4; ++ks) {
            uint32_t af[4][4];
            uint32_t bf[8][2];
#pragma unroll
            for (int mt = 0; mt < 4; ++mt) {
                int r = wr * 64 + mt * 16 + rA;
                ldsm4(af[mt][0], af[mt][1], af[mt][2], af[mt][3],
                      aT + sw128(r, ks * 2 + cAh));
            }
#pragma unroll
            for (int tp = 0; tp < 4; ++tp) {
                int r = wc * 64 + tp * 16 + rBl;
                uint32_t x0, x1, x2, x3;
                ldsm4(x0, x1, x2, x3, bT + sw128(r, ks * 2 + cBh));
                bf[tp * 2][0] = x0;     bf[tp * 2][1] = x1;
                bf[tp * 2 + 1][0] = x2; bf[tp * 2 + 1][1] = x3;
            }
#pragma unroll
            for (int mt = 0; mt < 4; ++mt)
#pragma unroll
                for (int nt = 0; nt < 8; ++nt)
                    mma_bf16(acc[mt][nt], af[mt], bf[nt]);
        }
    }
    __syncthreads();

#pragma unroll
    for (int mt = 0; mt < 4; ++mt) {
        const int row = m0 + wr * 64 + mt * 16 + (lane >> 2);
#pragma unroll
        for (int nt = 0; nt < 8; ++nt) {
            const int col = n0 + wc * 64 + nt * 8 + (lane & 3) * 2;
            const float b0 = bias ? bias[col]     : 0.f;
            const float b1 = bias ? bias[col + 1] : 0.f;
            const float v0 = (acc[mt][nt][0] + b0) * scale;
            const float v1 = (acc[mt][nt][1] + b1) * scale;
            const float v2 = (acc[mt][nt][2] + b0) * scale;
            const float v3 = (acc[mt][nt][3] + b1) * scale;
            const size_t i0 = cOff + ((size_t)row << 10) + col;
            const size_t i1 = i0 + (8 << 10);
            if (I16OUT) {
                *(short2*)(Cs + i0) = make_short2(squant(v0), squant(v1));
                *(short2*)(Cs + i1) = make_short2(squant(v2), squant(v3));
            } else {
                Cf[i0] = v0; Cf[i0 + 1] = v1;
                Cf[i1] = v2; Cf[i1 + 1] = v3;
            }
        }
    }
}

// ---------------------------------------------------------------------------
// Head-mean of softmax(S) using precomputed 1/rowsum from ctx_fused.
// One block (512 thr) per (b,q). Thread owns 8-wide k-slice x 4 heads
// (hgrp = tid>>7), accumulating e*inv directly in registers — no slab
// round-trip, no reductions. 16 KB static smem for the 4-way combine.
// ---------------------------------------------------------------------------
__global__ void __launch_bounds__(512) mean_heads(const short* __restrict__ S,
                                                  const float* __restrict__ rinv,
                                                  float* __restrict__ mean_out)
{
    __shared__ float part[4][1024];
    __shared__ float sinv[16];
    const int bq = blockIdx.x;
    const int b = bq >> 9, q = bq & 511;
    const int tid = threadIdx.x;
    const int hg = tid >> 7;          // 0..3 head group
    const int kb = (tid & 127) * 8;   // k base

    if (tid < 16) sinv[tid] = __ldg(&rinv[(size_t)(b * 16 + tid) * 512 + q]);
    __syncthreads();

    float macc[8];
#pragma unroll
    for (int j = 0; j < 8; ++j) macc[j] = 0.f;

#pragma unroll
    for (int i = 0; i < 4; ++i) {
        const int h = hg + i * 4;
        const float inv = sinv[h];
        int4 raw = __ldg((const int4*)(S + (((size_t)(b * 16 + h) * 512 + q) << 10) + kb));
        const uint32_t* u = (const uint32_t*)&raw;
#pragma unroll
        for (int j = 0; j < 4; ++j) {
            macc[j * 2 + 0] += __expf((float)((short)(u[j] & 0xFFFF)) * S_INVSC) * inv;
            macc[j * 2 + 1] += __expf((float)((short)(u[j] >> 16))    * S_INVSC) * inv;
        }
    }
    *(float4*)&part[hg][kb]     = make_float4(macc[0], macc[1], macc[2], macc[3]);
    *(float4*)&part[hg][kb + 4] = make_float4(macc[4], macc[5], macc[6], macc[7]);
    __syncthreads();

    const float inv16 = 1.0f / HH_;
    float* mo = mean_out + (((size_t)bq) << 10);
    float s0 = (part[0][tid] + part[1][tid]) + (part[2][tid] + part[3][tid]);
    float s1 = (part[0][tid + 512] + part[1][tid + 512]) +
               (part[2][tid + 512] + part[3][tid + 512]);
    mo[tid]       = s0 * inv16;
    mo[tid + 512] = s1 * inv16;
}

// ---------------------------------------------------------------------------
// Fused ctx (plain bf16), SELF-NORMALIZING, exports 1/rowsum to global.
// ---------------------------------------------------------------------------
__global__ void __launch_bounds__(512) ctx_fused(
    const short* __restrict__ S,
    const __nv_bfloat16* __restrict__ Vhi,
    __nv_bfloat16* __restrict__ Chi, float* __restrict__ rinv_out)
{
    extern __shared__ __align__(16) char dynsm[];
    const uint32_t smBase = smem_u32(dynsm);
    float* rs = (float*)(dynsm + 32768 + 3 * 8192);   // [128] row sums

    const int tid  = threadIdx.x;
    const int lane = tid & 31;
    const int wid  = tid >> 5;
    const int wr   = wid >> 2;
    const int wc   = wid & 3;
    const int z    = blockIdx.z, b = z >> 4, h = z & 15;
    const int m0   = blockIdx.y * 128;
    const size_t sOff  = ((size_t)z * 512 + m0) << 10;
    const size_t vOff  = ((size_t)z * 64) << 10;

    const int rA  = lane & 15;
    const int cAh = lane >> 4;
    const int rBl = (lane & 7) + ((lane & 16) >> 1);
    const int cBh = (lane >> 3) & 1;

    float acc[2][2][4];
#pragma unroll
    for (int mt = 0; mt < 2; ++mt)
#pragma unroll
        for (int nt = 0; nt < 2; ++nt)
#pragma unroll
            for (int j = 0; j < 4; ++j) acc[mt][nt][j] = 0.f;

    float rsum0 = 0.f, rsum1 = 0.f;

    int4 sreg[2];
    auto ldS = [&](int kc) {
#pragma unroll
        for (int i = 0; i < 2; ++i) {
            int idx = i * 512 + tid;
            int row = idx >> 3, c8 = idx & 7;
            sreg[i] = __ldg((const int4*)(S + sOff + ((size_t)row << 10) +
                                          (kc << 6) + c8 * 8));
        }
    };
    auto cpV = [&](int kc) {
        const uint32_t vs = smBase + 32768u + (uint32_t)(kc % 3) * 8192u;
        int r = tid >> 3, c = tid & 7;
        CP_ASYNC16(vs + sw128(r, c), Vhi + vOff + ((size_t)r << 10) + (kc << 6) + c * 8);
        CP_COMMIT();
    };

    ldS(0);
    cpV(0);
    cpV(1);

    for (int kc = 0; kc < 16; ++kc) {
        const uint32_t pB = smBase + (uint32_t)(kc & 1) * 16384u;
#pragma unroll
        for (int i = 0; i < 2; ++i) {
            int idx = i * 512 + tid;
            int row = idx >> 3, c8 = idx & 7;
            const uint32_t* u = (const uint32_t*)&sreg[i];
            uint32_t packed[4];
            float esum = 0.f;
#pragma unroll
            for (int j = 0; j < 4; ++j) {
                float a = __expf((float)((short)(u[j] & 0xFFFF)) * S_INVSC);
                float c = __expf((float)((short)(u[j] >> 16))    * S_INVSC);
                esum += a + c;
                __nv_bfloat162 pp = __halves2bfloat162(__float2bfloat16(a),
                                                       __float2bfloat16(c));
                packed[j] = *(uint32_t*)&pp;
            }
            if (i == 0) rsum0 += esum; else rsum1 += esum;
            uint32_t off = sw128(row, c8);
            asm volatile("st.shared.v4.b32 [%0], {%1, %2, %3, %4};" ::
                         "r"(pB + off), "r"(packed[0]), "r"(packed[1]),
                         "r"(packed[2]), "r"(packed[3]) : "memory");
        }
        if (kc + 1 < 16) ldS(kc + 1);

        CP_WAIT1();
        __syncthreads();
        if (kc + 2 < 16) cpV(kc + 2);
        else CP_COMMIT();

        const uint32_t phT = smBase + (uint32_t)(kc & 1) * 16384u;
        const uint32_t vhT = smBase + 32768u + (uint32_t)(kc % 3) * 8192u;

#pragma unroll
        for (int ks = 0; ks < 4; ++ks) {
            uint32_t ah[2][4];
            uint32_t bh[2][2];
#pragma unroll
            for (int mt = 0; mt < 2; ++mt) {
                int r = wr * 32 + mt * 16 + rA;
                ldsm4(ah[mt][0], ah[mt][1], ah[mt][2], ah[mt][3],
                      phT + sw128(r, ks * 2 + cAh));
            }
            {
                int r = wc * 16 + rBl;
                uint32_t x0, x1, x2, x3;
                ldsm4(x0, x1, x2, x3, vhT + sw128(r, ks * 2 + cBh));
                bh[0][0] = x0; bh[0][1] = x1; bh[1][0] = x2; bh[1][1] = x3;
            }
#pragma unroll
            for (int mt = 0; mt < 2; ++mt)
#pragma unroll
                for (int nt = 0; nt < 2; ++nt)
                    mma_bf16(acc[mt][nt], ah[mt], bh[nt]);
        }
    }

    // combine row sums: octet shuffle, then smem
#pragma unroll
    for (int o = 1; o < 8; o <<= 1) {
        rsum0 += __shfl_xor_sync(0xffffffffu, rsum0, o);
        rsum1 += __shfl_xor_sync(0xffffffffu, rsum1, o);
    }
    if ((tid & 7) == 0) {
        rs[tid >> 3]        = rsum0;
        rs[(tid >> 3) + 64] = rsum1;
    }
    __syncthreads();

    // export 1/rowsum for mean_heads
    if (tid < 128)
        rinv_out[(size_t)z * 512 + m0 + tid] = 1.0f / rs[tid];

#pragma unroll
    for (int mt = 0; mt < 2; ++mt) {
        const int rl = wr * 32 + mt * 16 + (lane >> 2);
        const float inv0 = 1.0f / rs[rl];
        const float inv1 = 1.0f / rs[rl + 8];
        const int row = m0 + rl;
#pragma unroll
        for (int nt = 0; nt < 2; ++nt) {
            const int col = h * 64 + wc * 16 + nt * 8 + (lane & 3) * 2;
            const size_t i0 = (((size_t)(b * 512 + row)) << 10) + col;
            const size_t i1 = i0 + (8 << 10);
            *(__nv_bfloat162*)(Chi + i0) =
                __halves2bfloat162(__float2bfloat16(acc[mt][nt][0] * inv0),
                                   __float2bfloat16(acc[mt][nt][1] * inv0));
            *(__nv_bfloat162*)(Chi + i1) =
                __halves2bfloat162(__float2bfloat16(acc[mt][nt][2] * inv1),
                                   __float2bfloat16(acc[mt][nt][3] * inv1));
        }
    }
}

// ---------------------------------------------------------------------------
// out = LayerNorm(query + attn_out) * gamma + beta.  One block per row.
// ---------------------------------------------------------------------------
__global__ void residual_ln(const float* __restrict__ q, const float* __restrict__ ao,
                            const float* __restrict__ gamma, const float* __restrict__ beta,
                            float* __restrict__ out)
{
    __shared__ float red[8];
    __shared__ float bcast;
    const long row = blockIdx.x;
    const int tid = threadIdx.x;

    float4 qa = *(const float4*)&q [row * DD + tid * 4];
    float4 aa = *(const float4*)&ao[row * DD + tid * 4];
    float x0 = qa.x + aa.x, x1 = qa.y + aa.y, x2 = qa.z + aa.z, x3 = qa.w + aa.w;

    float s = (x0 + x1) + (x2 + x3);
#pragma unroll
    for (int o = 16; o; o >>= 1) s += __shfl_xor_sync(0xffffffffu, s, o);
    if ((tid & 31) == 0) red[tid >> 5] = s;
    __syncthreads();
    if (tid < 8) {
        s = red[tid];
#pragma unroll
        for (int o = 4; o; o >>= 1) s += __shfl_xor_sync(0xffu, s, o);
        if (tid == 0) bcast = s;
    }
    __syncthreads();
    const float mu = bcast * (1.0f / DD);

    float d0 = x0 - mu, d1 = x1 - mu, d2 = x2 - mu, d3 = x3 - mu;
    float sq = (d0 * d0 + d1 * d1) + (d2 * d2 + d3 * d3);
#pragma unroll
    for (int o = 16; o; o >>= 1) sq += __shfl_xor_sync(0xffffffffu, sq, o);
    __syncthreads();
    if ((tid & 31) == 0) red[tid >> 5] = sq;
    __syncthreads();
    if (tid < 8) {
        sq = red[tid];
#pragma unroll
        for (int o = 4; o; o >>= 1) sq += __shfl_xor_sync(0xffu, sq, o);
        if (tid == 0) bcast = sq;
    }
    __syncthreads();
    const float rstd = rsqrtf(bcast * (1.0f / DD) + LN_EPS);

    float4 g = *(const float4*)&gamma[tid * 4];
    float4 be = *(const float4*)&beta[tid * 4];
    float4 o4;
    o4.x = d0 * rstd * g.x + be.x;
    o4.y = d1 * rstd * g.y + be.y;
    o4.z = d2 * rstd * g.z + be.z;
    o4.w = d3 * rstd * g.w + be.w;
    *(float4*)&out[row * DD + tid * 4] = o4;
}

// ---------------------------------------------------------------------------
extern "C" void kernel_launch(void* const* d_in, const int* in_sizes, int n_in,
                              void* d_out, int out_size)
{
    const float* query = (const float*)d_in[0];
    const float* key_  = (const float*)d_in[1];
    const float* value = (const float*)d_in[2];
    const float* in_w  = (const float*)d_in[3];
    const float* in_b  = (const float*)d_in[4];
    const float* out_w = (const float*)d_in[5];
    const float* out_b = (const float*)d_in[6];
    const float* gamma = (const float*)d_in[7];
    const float* beta  = (const float*)d_in[8];
    float* out = (float*)d_out;

    short* Si;
    float *AO, *RI;
    cudaGetSymbolAddress((void**)&Si, g_S);
    cudaGetSymbolAddress((void**)&AO, g_AO);
    cudaGetSymbolAddress((void**)&RI, g_rsum);

    __nv_bfloat16 *qh, *ql, *kh, *kl, *vh, *vt, *wh, *wl, *woh;
    __nv_bfloat16 *qh2, *ql2, *kh2, *kl2, *ch;
    cudaGetSymbolAddress((void**)&qh,  g_qh);  cudaGetSymbolAddress((void**)&ql,  g_ql);
    cudaGetSymbolAddress((void**)&kh,  g_kh);  cudaGetSymbolAddress((void**)&kl,  g_kl);
    cudaGetSymbolAddress((void**)&vh,  g_vh);  cudaGetSymbolAddress((void**)&vt,  g_vt);
    cudaGetSymbolAddress((void**)&wh,  g_wh);  cudaGetSymbolAddress((void**)&wl,  g_wl);
    cudaGetSymbolAddress((void**)&woh, g_woh);
    cudaGetSymbolAddress((void**)&qh2, g_qh2); cudaGetSymbolAddress((void**)&ql2, g_ql2);
    cudaGetSymbolAddress((void**)&kh2, g_kh2); cudaGetSymbolAddress((void**)&kl2, g_kl2);
    cudaGetSymbolAddress((void**)&ch,  g_ch);

    const int SM_G = 3 * 32768;
    const int SM_X = 2 * 16384 + 3 * 8192 + 512;
    cudaFuncSetAttribute((const void*)qkv_proj,
                         cudaFuncAttributeMaxDynamicSharedMemorySize, SM_G);
    cudaFuncSetAttribute((const void*)gemm64<1, 3, true>,
                         cudaFuncAttributeMaxDynamicSharedMemorySize, SM_G);
    cudaFuncSetAttribute((const void*)gemm64<16, 1, false>,
                         cudaFuncAttributeMaxDynamicSharedMemorySize, SM_G);
    cudaFuncSetAttribute((const void*)ctx_fused,
                         cudaFuncAttributeMaxDynamicSharedMemorySize, SM_X);

    const float qscale = 0.125f;

    // 1) split everything in one launch
    {
        const long total4 = (long)BB*LQ*DD/4 + 2L*BB*LKV*DD/4 + 3L*DD*DD/4 + (long)DD*DD/4;
        split_all<<<(unsigned)((total4 + 255) / 256), 256>>>(
            (const float4*)query, (const float4*)key_, (const float4*)value,
            (const float4*)in_w, (const float4*)out_w,
            (__nv_bfloat162*)qh, (__nv_bfloat162*)ql,
            (__nv_bfloat162*)kh, (__nv_bfloat162*)kl,
            (__nv_bfloat162*)vh,
            (__nv_bfloat162*)wh, (__nv_bfloat162*)wl,
            (__nv_bfloat162*)woh);
    }

    // 2) merged Q/K/V projection (+ fused V transpose -> vt)
    qkv_proj<<<dim3(8, 160), 128, SM_G>>>(
        qh, ql, kh, kl, vh, wh, wl, in_b,
        qh2, ql2, kh2, kl2, vt, qscale);

    // 3) scores (bf16x3) -> int16 S (scaled by 4096)
    gemm64<1, 3, true><<<dim3(8, 4, BB * HH_), 128, SM_G>>>(
        qh2, ql2, kh2, kl2, nullptr, nullptr, Si, S_SCALE,
        (long)LQ * DD,  (long)HD,
        (long)LKV * DD, (long)HD,
        (long)HH_ * LQ * LKV, (long)LQ * LKV);

    // 4) fused self-normalizing ctx MMA; exports 1/rowsum
    ctx_fused<<<dim3(1, 4, BB * HH_), 512, SM_X>>>(Si, vt, ch, RI);

    // 5) head-mean of softmax using exported rowsums (register accumulation)
    mean_heads<<<BB * LQ, 512>>>(Si, RI, out + (long)BB * LQ * DD);

    // 6) out projection (bf16x1) -> fp32 AO
    gemm64<16, 1, false><<<dim3(8, 32, 1), 128, SM_G>>>(
        ch, nullptr, woh, nullptr, out_b, AO, nullptr, 1.0f, 0,0, 0,0, 0,0);

    // 7) residual + LayerNorm
    residual_ln<<<BB * LQ, 256>>>(query, AO, gamma, beta, out);
}